// round 2
// baseline (speedup 1.0000x reference)
#include <cuda_runtime.h>
#include <math.h>

#define Bb 2
#define Tt 2048
#define Ee 1024
#define Hh 16
#define Dd 64
#define HD (Hh*Dd)

// Scratch (device globals: allocation-free rule)
__device__ float g_q[(size_t)Bb*Tt*HD];
__device__ float g_k[(size_t)Bb*Tt*HD];
__device__ float g_v[(size_t)Bb*Tt*HD];
__device__ float g_z[(size_t)Bb*Tt*HD];

// ---------------------------------------------------------------------------
// SGEMM: C[M,N] = A[M,K] @ W[K,N] + bias[N]
// 128x128 block tile, BK=8, 256 threads, 8x8 register micro-tile.
// ---------------------------------------------------------------------------
__global__ __launch_bounds__(256) void sgemm_bias(
    const float* __restrict__ A, const float* __restrict__ W,
    const float* __restrict__ bias, float* __restrict__ C,
    int M, int N, int K)
{
    __shared__ __align__(16) float As[8][128];   // transposed A tile: As[k][m]
    __shared__ __align__(16) float Bs[8][128];   // Bs[k][n]

    int tid = threadIdx.x;
    int tx = tid & 15;         // 0..15 -> 8 cols each
    int ty = tid >> 4;         // 0..15 -> 8 rows each
    int row0 = blockIdx.y * 128;
    int col0 = blockIdx.x * 128;

    float acc[8][8] = {};

    int ar = tid >> 1;          // 0..127 (A tile row)
    int ac = (tid & 1) * 4;     // 0 or 4 (A tile col base)
    int br = tid >> 5;          // 0..7  (W tile row)
    int bc = (tid & 31) * 4;    // 0..124 (W tile col base)

    const float* Aptr = A + (size_t)(row0 + ar) * K + ac;
    const float* Wptr = W + (size_t)br * N + col0 + bc;

    for (int k0 = 0; k0 < K; k0 += 8) {
        float4 av = *(const float4*)(Aptr + k0);
        As[ac + 0][ar] = av.x;
        As[ac + 1][ar] = av.y;
        As[ac + 2][ar] = av.z;
        As[ac + 3][ar] = av.w;
        float4 wv = *(const float4*)(Wptr + (size_t)k0 * N);
        *(float4*)&Bs[br][bc] = wv;
        __syncthreads();

        #pragma unroll
        for (int kk = 0; kk < 8; kk++) {
            float4 a0 = *(const float4*)&As[kk][ty * 8];
            float4 a1 = *(const float4*)&As[kk][ty * 8 + 4];
            float4 b0 = *(const float4*)&Bs[kk][tx * 8];
            float4 b1 = *(const float4*)&Bs[kk][tx * 8 + 4];
            float a[8] = {a0.x, a0.y, a0.z, a0.w, a1.x, a1.y, a1.z, a1.w};
            float b[8] = {b0.x, b0.y, b0.z, b0.w, b1.x, b1.y, b1.z, b1.w};
            #pragma unroll
            for (int i = 0; i < 8; i++)
                #pragma unroll
                for (int j = 0; j < 8; j++)
                    acc[i][j] += a[i] * b[j];
        }
        __syncthreads();
    }

    #pragma unroll
    for (int i = 0; i < 8; i++) {
        int row = row0 + ty * 8 + i;
        #pragma unroll
        for (int j = 0; j < 8; j += 4) {
            int col = col0 + tx * 8 + j;
            float4 o;
            o.x = acc[i][j + 0] + bias[col + 0];
            o.y = acc[i][j + 1] + bias[col + 1];
            o.z = acc[i][j + 2] + bias[col + 2];
            o.w = acc[i][j + 3] + bias[col + 3];
            *(float4*)&C[(size_t)row * N + col] = o;
        }
    }
}

// ---------------------------------------------------------------------------
// Flash attention: per (b,h) head, 64-query tiles, streaming over 64-KV tiles
// with online softmax. Mask is int32 (bool upcast by harness).
// ---------------------------------------------------------------------------
#define STRIDE 68   // 64 + 4 pad; keeps float4 alignment

__global__ __launch_bounds__(256) void flash_attn(
    const float* __restrict__ Qg, const float* __restrict__ Kg,
    const float* __restrict__ Vg, const int* __restrict__ mask,
    float* __restrict__ Zg)
{
    extern __shared__ float smx[];
    float* Qt   = smx;                 // [d][q]   Qt[d*STRIDE + q]
    float* Kt   = Qt + 64 * STRIDE;    // [d][c]   Kt[d*STRIDE + c]
    float* Vs   = Kt + 64 * STRIDE;    // [c][d]   Vs[c*STRIDE + d]
    float* SP   = Vs + 64 * STRIDE;    // [q][c]   scores then probabilities
    float* mrow = SP + 64 * STRIDE;    // [64] running max
    float* lrow = mrow + 64;           // [64] running denom
    float* arow = lrow + 64;           // [64] rescale factor this tile

    int tid = threadIdx.x;
    int tx = tid & 15;    // kv-col group (S) / d group (O)
    int ty = tid >> 4;    // q-row group
    int b = blockIdx.y / Hh;
    int h = blockIdx.y % Hh;
    int q0 = blockIdx.x * 64;
    const float scale = 0.125f;   // D^-0.5, D=64

    // Load Q tile transposed
    {
        int r = tid >> 2;
        int dbase = (tid & 3) * 16;
        const float* qp = Qg + (size_t)(b * Tt + q0 + r) * HD + h * Dd + dbase;
        #pragma unroll
        for (int i = 0; i < 4; i++) {
            float4 v = *(const float4*)(qp + i * 4);
            int d = dbase + i * 4;
            Qt[(d + 0) * STRIDE + r] = v.x;
            Qt[(d + 1) * STRIDE + r] = v.y;
            Qt[(d + 2) * STRIDE + r] = v.z;
            Qt[(d + 3) * STRIDE + r] = v.w;
        }
    }
    if (tid < 64) { mrow[tid] = -INFINITY; lrow[tid] = 0.0f; }

    float o[4][4] = {};

    for (int kv0 = 0; kv0 < Tt; kv0 += 64) {
        __syncthreads();   // previous iteration done reading Vs/SP (and Q ready)

        // Load K (transposed) and V (natural) tiles
        {
            int r = tid >> 2;
            int dbase = (tid & 3) * 16;
            const float* kp = Kg + (size_t)(b * Tt + kv0 + r) * HD + h * Dd + dbase;
            const float* vp = Vg + (size_t)(b * Tt + kv0 + r) * HD + h * Dd + dbase;
            #pragma unroll
            for (int i = 0; i < 4; i++) {
                int d = dbase + i * 4;
                float4 kvv = *(const float4*)(kp + i * 4);
                Kt[(d + 0) * STRIDE + r] = kvv.x;
                Kt[(d + 1) * STRIDE + r] = kvv.y;
                Kt[(d + 2) * STRIDE + r] = kvv.z;
                Kt[(d + 3) * STRIDE + r] = kvv.w;
                float4 vv = *(const float4*)(vp + i * 4);
                *(float4*)&Vs[r * STRIDE + d] = vv;
            }
        }
        __syncthreads();

        // S = Q @ K^T  (64x64x64), 4x4 per thread
        float s[4][4] = {};
        #pragma unroll 8
        for (int kk = 0; kk < 64; kk++) {
            float4 qa = *(const float4*)&Qt[kk * STRIDE + ty * 4];
            float4 kb = *(const float4*)&Kt[kk * STRIDE + tx * 4];
            float a[4] = {qa.x, qa.y, qa.z, qa.w};
            float c[4] = {kb.x, kb.y, kb.z, kb.w};
            #pragma unroll
            for (int i = 0; i < 4; i++)
                #pragma unroll
                for (int j = 0; j < 4; j++)
                    s[i][j] += a[i] * c[j];
        }
        // write S naturally [q][c] with float4 stores
        #pragma unroll
        for (int i = 0; i < 4; i++) {
            float4 sv = make_float4(s[i][0], s[i][1], s[i][2], s[i][3]);
            *(float4*)&SP[(ty * 4 + i) * STRIDE + tx * 4] = sv;
        }
        __syncthreads();

        // Online softmax: 4 threads per query row, 16 cols each
        {
            int r = tid >> 2;
            int part = tid & 3;
            int cb = part * 16;
            // mask is int32 (harness upcasts bool)
            const int* mp = mask + ((size_t)(b * Tt + q0 + r)) * Tt + kv0 + cb;
            int mv[16];
            #pragma unroll
            for (int i = 0; i < 4; i++)
                *(int4*)&mv[i * 4] = *(const int4*)(mp + i * 4);

            float sv[16];
            float mloc = -INFINITY;
            #pragma unroll
            for (int c = 0; c < 16; c++) {
                float x = SP[r * STRIDE + cb + c] * scale;
                if (mv[c] == 0) x = -1e30f;
                sv[c] = x;
                mloc = fmaxf(mloc, x);
            }
            #pragma unroll
            for (int off = 1; off < 4; off <<= 1)
                mloc = fmaxf(mloc, __shfl_xor_sync(0xffffffffu, mloc, off));

            float m_old = mrow[r];
            float m_new = fmaxf(m_old, mloc);
            float alpha = __expf(m_old - m_new);   // exp(-inf)=0 on first tile

            float lsum = 0.0f;
            #pragma unroll
            for (int c = 0; c < 16; c++) {
                float p = __expf(sv[c] - m_new);
                SP[r * STRIDE + cb + c] = p;
                lsum += p;
            }
            #pragma unroll
            for (int off = 1; off < 4; off <<= 1)
                lsum += __shfl_xor_sync(0xffffffffu, lsum, off);

            if (part == 0) {
                mrow[r] = m_new;
                lrow[r] = lrow[r] * alpha + lsum;
                arow[r] = alpha;
            }
        }
        __syncthreads();

        // O = O*alpha + P @ V   (64x64x64), 4x4 per thread (rows=q, cols=d)
        #pragma unroll
        for (int i = 0; i < 4; i++) {
            float al = arow[ty * 4 + i];
            o[i][0] *= al; o[i][1] *= al; o[i][2] *= al; o[i][3] *= al;
        }
        #pragma unroll 8
        for (int c = 0; c < 64; c++) {
            float4 vb = *(const float4*)&Vs[c * STRIDE + tx * 4];
            float a0 = SP[(ty * 4 + 0) * STRIDE + c];
            float a1 = SP[(ty * 4 + 1) * STRIDE + c];
            float a2 = SP[(ty * 4 + 2) * STRIDE + c];
            float a3 = SP[(ty * 4 + 3) * STRIDE + c];
            o[0][0] += a0 * vb.x; o[0][1] += a0 * vb.y; o[0][2] += a0 * vb.z; o[0][3] += a0 * vb.w;
            o[1][0] += a1 * vb.x; o[1][1] += a1 * vb.y; o[1][2] += a1 * vb.z; o[1][3] += a1 * vb.w;
            o[2][0] += a2 * vb.x; o[2][1] += a2 * vb.y; o[2][2] += a2 * vb.z; o[2][3] += a2 * vb.w;
            o[3][0] += a3 * vb.x; o[3][1] += a3 * vb.y; o[3][2] += a3 * vb.z; o[3][3] += a3 * vb.w;
        }
    }

    // Epilogue: divide by denom, write z
    #pragma unroll
    for (int i = 0; i < 4; i++) {
        int qg = q0 + ty * 4 + i;
        float inv = 1.0f / lrow[ty * 4 + i];
        float4 out = make_float4(o[i][0] * inv, o[i][1] * inv,
                                 o[i][2] * inv, o[i][3] * inv);
        *(float4*)&Zg[(size_t)(b * Tt + qg) * HD + h * Dd + tx * 4] = out;
    }
}

// ---------------------------------------------------------------------------
extern "C" void kernel_launch(void* const* d_in, const int* in_sizes, int n_in,
                              void* d_out, int out_size)
{
    const float* embed = (const float*)d_in[0];
    const int*   mask  = (const int*)d_in[1];
    const float* Wq = (const float*)d_in[2];
    const float* bq = (const float*)d_in[3];
    const float* Wk = (const float*)d_in[4];
    const float* bk = (const float*)d_in[5];
    const float* Wv = (const float*)d_in[6];
    const float* bv = (const float*)d_in[7];
    const float* Wz = (const float*)d_in[8];
    const float* bz = (const float*)d_in[9];
    float* out = (float*)d_out;

    float *q, *k, *v, *z;
    cudaGetSymbolAddress((void**)&q, g_q);
    cudaGetSymbolAddress((void**)&k, g_k);
    cudaGetSymbolAddress((void**)&v, g_v);
    cudaGetSymbolAddress((void**)&z, g_z);

    const int M = Bb * Tt;   // 4096

    dim3 gproj(HD / 128, M / 128);   // (8, 32)
    sgemm_bias<<<gproj, 256>>>(embed, Wq, bq, q, M, HD, Ee);
    sgemm_bias<<<gproj, 256>>>(embed, Wk, bk, k, M, HD, Ee);
    sgemm_bias<<<gproj, 256>>>(embed, Wv, bv, v, M, HD, Ee);

    int smem_bytes = (4 * 64 * STRIDE + 3 * 64) * (int)sizeof(float);  // 70,400
    cudaFuncSetAttribute(flash_attn,
                         cudaFuncAttributeMaxDynamicSharedMemorySize, smem_bytes);
    dim3 gattn(Tt / 64, Bb * Hh);    // (32, 32)
    flash_attn<<<gattn, 256, smem_bytes>>>(q, k, v, mask, z);

    dim3 gout(Ee / 128, M / 128);    // (8, 32)
    sgemm_bias<<<gout, 256>>>(z, Wz, bz, out, M, Ee, HD);
}

// round 4
// speedup vs baseline: 2.2640x; 2.2640x over previous
#include <cuda_runtime.h>
#include <cuda_bf16.h>
#include <cstdint>
#include <math.h>

#define Bb 2
#define Tt 2048
#define Hh 16
#define Mtot 4096
#define KDIM 1024

// ===========================================================================
// Helpers: mma.sync (bf16), ldmatrix, cp.async — all non-'a' ISA features
// ===========================================================================
__device__ __forceinline__ uint32_t smem_u32(const void* p) {
    uint32_t a;
    asm("{ .reg .u64 t; cvta.to.shared.u64 t, %1; cvt.u32.u64 %0, t; }"
        : "=r"(a) : "l"(p));
    return a;
}
__device__ __forceinline__ void cp16(uint32_t dst, const void* src) {
    asm volatile("cp.async.cg.shared.global [%0], [%1], 16;" :: "r"(dst), "l"(src));
}
#define CP_COMMIT() asm volatile("cp.async.commit_group;" ::: "memory")
#define CP_WAIT0()  asm volatile("cp.async.wait_group 0;" ::: "memory")
#define CP_WAIT1()  asm volatile("cp.async.wait_group 1;" ::: "memory")

__device__ __forceinline__ void ldm4(uint32_t* r, uint32_t a) {
    asm volatile("ldmatrix.sync.aligned.m8n8.x4.shared.b16 {%0,%1,%2,%3}, [%4];"
        : "=r"(r[0]), "=r"(r[1]), "=r"(r[2]), "=r"(r[3]) : "r"(a));
}
__device__ __forceinline__ void mma16816(float* d, const uint32_t* a,
                                         uint32_t b0, uint32_t b1) {
    asm volatile("mma.sync.aligned.m16n8k16.row.col.f32.bf16.bf16.f32 "
        "{%0,%1,%2,%3}, {%4,%5,%6,%7}, {%8,%9}, {%0,%1,%2,%3};"
        : "+f"(d[0]), "+f"(d[1]), "+f"(d[2]), "+f"(d[3])
        : "r"(a[0]), "r"(a[1]), "r"(a[2]), "r"(a[3]), "r"(b0), "r"(b1));
}

__device__ __forceinline__ void split2(float x, __nv_bfloat16& h, __nv_bfloat16& l) {
    h = __float2bfloat16(x);
    l = __float2bfloat16(x - __bfloat162float(h));
}

// ===========================================================================
// Scratch (device globals)
// ===========================================================================
__device__ __nv_bfloat16 g_eh[(size_t)Mtot * KDIM], g_el[(size_t)Mtot * KDIM];
__device__ __nv_bfloat16 g_wth[(size_t)4 * 1024 * 1024], g_wtl[(size_t)4 * 1024 * 1024];
__device__ __nv_bfloat16 g_qh[(size_t)Mtot * KDIM], g_ql[(size_t)Mtot * KDIM];
__device__ __nv_bfloat16 g_kh[(size_t)Mtot * KDIM], g_kl[(size_t)Mtot * KDIM];
__device__ __nv_bfloat16 g_vth[(size_t)Mtot * KDIM], g_vtl[(size_t)Mtot * KDIM]; // [b][n][t]
__device__ __nv_bfloat16 g_zh[(size_t)Mtot * KDIM], g_zl[(size_t)Mtot * KDIM];
__device__ uint32_t g_mbits[(size_t)Bb * Tt * (Tt / 32)];

// ===========================================================================
// Prep kernels
// ===========================================================================
__global__ void split_f32(const float* __restrict__ x, __nv_bfloat16* __restrict__ h,
                          __nv_bfloat16* __restrict__ l, int n4) {
    int i = blockIdx.x * blockDim.x + threadIdx.x;
    if (i >= n4) return;
    float4 v = ((const float4*)x)[i];
    __nv_bfloat16 h0, h1, h2, h3, l0, l1, l2, l3;
    split2(v.x, h0, l0); split2(v.y, h1, l1); split2(v.z, h2, l2); split2(v.w, h3, l3);
    __nv_bfloat162 hp0; hp0.x = h0; hp0.y = h1;
    __nv_bfloat162 hp1; hp1.x = h2; hp1.y = h3;
    __nv_bfloat162 lp0; lp0.x = l0; lp0.y = l1;
    __nv_bfloat162 lp1; lp1.x = l2; lp1.y = l3;
    ((__nv_bfloat162*)h)[2 * i] = hp0; ((__nv_bfloat162*)h)[2 * i + 1] = hp1;
    ((__nv_bfloat162*)l)[2 * i] = lp0; ((__nv_bfloat162*)l)[2 * i + 1] = lp1;
}

// W[K,N] (1024x1024) -> WT[N,K] split hi/lo
__global__ void trans_split(const float* __restrict__ W, __nv_bfloat16* __restrict__ Th,
                            __nv_bfloat16* __restrict__ Tl) {
    __shared__ float t[32][33];
    int tx = threadIdx.x, ty = threadIdx.y;
    int x0 = blockIdx.x * 32, y0 = blockIdx.y * 32;
    #pragma unroll
    for (int i = 0; i < 32; i += 8)
        t[ty + i][tx] = W[(size_t)(y0 + ty + i) * 1024 + x0 + tx];
    __syncthreads();
    #pragma unroll
    for (int i = 0; i < 32; i += 8) {
        float v = t[tx][ty + i];
        size_t o = (size_t)(x0 + ty + i) * 1024 + y0 + tx;
        __nv_bfloat16 h, l; split2(v, h, l);
        Th[o] = h; Tl[o] = l;
    }
}

__global__ void pack_mask(const int* __restrict__ m, uint32_t* __restrict__ bits) {
    int i = blockIdx.x * blockDim.x + threadIdx.x;
    uint32_t bal = __ballot_sync(0xffffffffu, m[i] != 0);
    if ((threadIdx.x & 31) == 0) bits[i >> 5] = bal;
}

// ===========================================================================
// GEMM (mma.sync split-bf16): C[M,1024] = A[M,1024] @ Wt^T + bias
// 128x128 tile, 8 warps (4m x 2n), warp tile 32x64, KC=32, cp.async 2-stage.
// mode 0: fp32 out; 1: hi/lo bf16 natural; 2: hi/lo bf16 transposed [b][n][t]
// ===========================================================================
#define GSTR 40                  // smem row stride in bf16 (32 + 8 pad)
#define GTILE (128 * GSTR)       // elements per tile
#define GBUF  (4 * GTILE)        // 4 tiles per buffer
#define GEMM_SMEM_BYTES (2 * GBUF * 2)   // 81920

__global__ __launch_bounds__(256) void gemm_mma(
    const __nv_bfloat16* __restrict__ Ah, const __nv_bfloat16* __restrict__ Al,
    const __nv_bfloat16* __restrict__ Bh, const __nv_bfloat16* __restrict__ Bl,
    const float* __restrict__ bias, int mode, float* __restrict__ outF,
    __nv_bfloat16* __restrict__ Oh, __nv_bfloat16* __restrict__ Ol)
{
    extern __shared__ __nv_bfloat16 sm[];
    uint32_t sb = smem_u32(sm);
    int tid = threadIdx.x, lane = tid & 31, w = tid >> 5;
    int wm = w & 3, wn = w >> 2;
    int m0 = blockIdx.y * 128, n0 = blockIdx.x * 128;

    const __nv_bfloat16* srcs[4] = {Ah + (size_t)m0 * KDIM, Al + (size_t)m0 * KDIM,
                                    Bh + (size_t)n0 * KDIM, Bl + (size_t)n0 * KDIM};

    auto issue = [&](int ch, int buf) {
        uint32_t dbase = sb + (uint32_t)buf * (GBUF * 2);
        #pragma unroll
        for (int t = 0; t < 4; t++) {
            #pragma unroll
            for (int i = 0; i < 2; i++) {
                int idx = tid + i * 256;
                int row = idx >> 2, c = idx & 3;
                cp16(dbase + t * (GTILE * 2) + row * (GSTR * 2) + c * 16,
                     srcs[t] + (size_t)row * KDIM + ch * 32 + c * 8);
            }
        }
        CP_COMMIT();
    };

    float acc[2][8][4];
    #pragma unroll
    for (int ma = 0; ma < 2; ma++)
        #pragma unroll
        for (int na = 0; na < 8; na++)
            #pragma unroll
            for (int j = 0; j < 4; j++) acc[ma][na][j] = 0.0f;

    issue(0, 0);
    const int NC = KDIM / 32;   // 32
    for (int ch = 0; ch < NC; ch++) {
        __syncthreads();                       // prior mma done with buf being refilled
        if (ch + 1 < NC) { issue(ch + 1, (ch + 1) & 1); CP_WAIT1(); }
        else             { CP_WAIT0(); }
        __syncthreads();
        uint32_t bb = sb + (uint32_t)(ch & 1) * (GBUF * 2);
        uint32_t tAh = bb, tAl = bb + GTILE * 2;
        uint32_t tBh = bb + 2 * GTILE * 2, tBl = bb + 3 * GTILE * 2;
        #pragma unroll
        for (int ks = 0; ks < 2; ks++) {
            uint32_t ao = (uint32_t)(wm * 32 + (lane & 15)) * (GSTR * 2)
                        + ks * 32 + (lane >> 4) * 16;
            uint32_t ah[2][4], al[2][4];
            ldm4(ah[0], tAh + ao); ldm4(ah[1], tAh + ao + 16 * (GSTR * 2));
            ldm4(al[0], tAl + ao); ldm4(al[1], tAl + ao + 16 * (GSTR * 2));
            #pragma unroll
            for (int p = 0; p < 4; p++) {
                uint32_t bo = (uint32_t)(wn * 64 + p * 16 + (lane & 15)) * (GSTR * 2)
                            + ks * 32 + (lane >> 4) * 16;
                uint32_t bh[4], bl[4];
                ldm4(bh, tBh + bo); ldm4(bl, tBl + bo);
                #pragma unroll
                for (int ma = 0; ma < 2; ma++) {
                    mma16816(acc[ma][2 * p],     ah[ma], bh[0], bh[2]);
                    mma16816(acc[ma][2 * p],     ah[ma], bl[0], bl[2]);
                    mma16816(acc[ma][2 * p],     al[ma], bh[0], bh[2]);
                    mma16816(acc[ma][2 * p + 1], ah[ma], bh[1], bh[3]);
                    mma16816(acc[ma][2 * p + 1], ah[ma], bl[1], bl[3]);
                    mma16816(acc[ma][2 * p + 1], al[ma], bh[1], bh[3]);
                }
            }
        }
    }

    // Epilogue
    #pragma unroll
    for (int ma = 0; ma < 2; ma++)
    #pragma unroll
    for (int na = 0; na < 8; na++)
    #pragma unroll
    for (int half = 0; half < 2; half++) {
        int row = m0 + wm * 32 + ma * 16 + half * 8 + (lane >> 2);
        int col = n0 + wn * 64 + na * 8 + (lane & 3) * 2;
        float v0 = acc[ma][na][half * 2 + 0] + bias[col];
        float v1 = acc[ma][na][half * 2 + 1] + bias[col + 1];
        if (mode == 0) {
            *(float2*)(outF + (size_t)row * 1024 + col) = make_float2(v0, v1);
        } else if (mode == 1) {
            __nv_bfloat16 h0, l0, h1, l1;
            split2(v0, h0, l0); split2(v1, h1, l1);
            __nv_bfloat162 hp; hp.x = h0; hp.y = h1;
            __nv_bfloat162 lp; lp.x = l0; lp.y = l1;
            *(__nv_bfloat162*)(Oh + (size_t)row * 1024 + col) = hp;
            *(__nv_bfloat162*)(Ol + (size_t)row * 1024 + col) = lp;
        } else {
            int bi = row >> 11, t = row & 2047;
            __nv_bfloat16 h0, l0, h1, l1;
            split2(v0, h0, l0); split2(v1, h1, l1);
            Oh[((size_t)bi * 1024 + col) * 2048 + t] = h0;
            Ol[((size_t)bi * 1024 + col) * 2048 + t] = l0;
            Oh[((size_t)bi * 1024 + col + 1) * 2048 + t] = h1;
            Ol[((size_t)bi * 1024 + col + 1) * 2048 + t] = l1;
        }
    }
}

// ===========================================================================
// Attention (mma.sync split-bf16, no-max softmax, O in registers)
// CTA = 128 queries x 1 head; 8 warps (4m x 2n); 32 KV tiles of 64.
// ===========================================================================
#define ASTR 72                   // smem row stride bf16 (64 + 8)
#define AQ   (128 * ASTR)         // 9216 el
#define AKV  (64 * ASTR)          // 4608 el
#define ATTN_EL (2 * AQ + 2 * 4 * AKV + 2 * AQ)
#define ATTN_SMEM_BYTES (ATTN_EL * 2 + 1024)

__global__ __launch_bounds__(256) void attn_mma() {
    extern __shared__ __nv_bfloat16 sm[];
    uint32_t sb = smem_u32(sm);
    __nv_bfloat16* Qh = sm;
    __nv_bfloat16* Ql = sm + AQ;
    __nv_bfloat16* Ph = sm + 2 * AQ + 8 * AKV;
    __nv_bfloat16* Pl = Ph + AQ;
    float* lsum = (float*)(sm + ATTN_EL);

    int tid = threadIdx.x, lane = tid & 31, w = tid >> 5;
    int wm = w & 3, wn = w >> 2;
    int q0 = blockIdx.x * 128;
    int b = blockIdx.y >> 4, hd = blockIdx.y & 15;

    // Load Q tile (hi/lo) once
    #pragma unroll
    for (int i = 0; i < 4; i++) {
        int idx = tid + i * 256;
        int row = idx >> 3, c = idx & 7;
        size_t src = (size_t)(b * Tt + q0 + row) * 1024 + hd * 64 + c * 8;
        uint4 vh = *(const uint4*)(g_qh + src);
        uint4 vl = *(const uint4*)(g_ql + src);
        *(uint4*)(Qh + row * ASTR + c * 8) = vh;
        *(uint4*)(Ql + row * ASTR + c * 8) = vl;
    }

    auto issueKV = [&](int kt, int buf) {
        uint32_t dbase = sb + (uint32_t)(2 * AQ + buf * 4 * AKV) * 2;
        int kv0 = kt * 64;
        #pragma unroll
        for (int i = 0; i < 8; i++) {
            int idx = tid + i * 256;        // 0..2047
            int t = idx >> 9;               // 0:Kh 1:Kl 2:Vh 3:Vl
            int r = (idx >> 3) & 63, c = idx & 7;
            const __nv_bfloat16* src;
            if (t == 0)      src = g_kh  + (size_t)(b * Tt + kv0 + r) * 1024 + hd * 64 + c * 8;
            else if (t == 1) src = g_kl  + (size_t)(b * Tt + kv0 + r) * 1024 + hd * 64 + c * 8;
            else if (t == 2) src = g_vth + (size_t)(b * 1024 + hd * 64 + r) * Tt + kv0 + c * 8;
            else             src = g_vtl + (size_t)(b * 1024 + hd * 64 + r) * Tt + kv0 + c * 8;
            cp16(dbase + t * (AKV * 2) + r * (ASTR * 2) + c * 16, src);
        }
        CP_COMMIT();
    };

    float oacc[2][4][4];
    #pragma unroll
    for (int ma = 0; ma < 2; ma++)
        #pragma unroll
        for (int na = 0; na < 4; na++)
            #pragma unroll
            for (int j = 0; j < 4; j++) oacc[ma][na][j] = 0.0f;
    float lacc[4] = {0.0f, 0.0f, 0.0f, 0.0f};

    uint32_t tQh = sb, tQl = sb + AQ * 2;
    uint32_t tPh = sb + (uint32_t)(2 * AQ + 8 * AKV) * 2, tPl = tPh + AQ * 2;

    issueKV(0, 0);
    for (int kt = 0; kt < 32; kt++) {
        __syncthreads();                     // all warps done PV(kt-1)
        if (kt + 1 < 32) { issueKV(kt + 1, (kt + 1) & 1); CP_WAIT1(); }
        else             { CP_WAIT0(); }
        __syncthreads();
        uint32_t kb = sb + (uint32_t)(2 * AQ + (kt & 1) * 4 * AKV) * 2;
        uint32_t tKh = kb, tKl = kb + AKV * 2;
        uint32_t tVh = kb + 2 * AKV * 2, tVl = kb + 3 * AKV * 2;

        // ---- S = Q @ K^T (3-MMA split), d = 64 -> 4 k-steps ----
        float s[2][4][4];
        #pragma unroll
        for (int ma = 0; ma < 2; ma++)
            #pragma unroll
            for (int na = 0; na < 4; na++)
                #pragma unroll
                for (int j = 0; j < 4; j++) s[ma][na][j] = 0.0f;
        #pragma unroll
        for (int ks = 0; ks < 4; ks++) {
            uint32_t ao = (uint32_t)(wm * 32 + (lane & 15)) * (ASTR * 2)
                        + ks * 32 + (lane >> 4) * 16;
            uint32_t qh2[2][4], ql2[2][4];
            ldm4(qh2[0], tQh + ao); ldm4(qh2[1], tQh + ao + 16 * (ASTR * 2));
            ldm4(ql2[0], tQl + ao); ldm4(ql2[1], tQl + ao + 16 * (ASTR * 2));
            #pragma unroll
            for (int p = 0; p < 2; p++) {
                uint32_t bo = (uint32_t)(wn * 32 + p * 16 + (lane & 15)) * (ASTR * 2)
                            + ks * 32 + (lane >> 4) * 16;
                uint32_t bh[4], bl[4];
                ldm4(bh, tKh + bo); ldm4(bl, tKl + bo);
                #pragma unroll
                for (int ma = 0; ma < 2; ma++) {
                    mma16816(s[ma][2 * p],     qh2[ma], bh[0], bh[2]);
                    mma16816(s[ma][2 * p],     qh2[ma], bl[0], bl[2]);
                    mma16816(s[ma][2 * p],     ql2[ma], bh[0], bh[2]);
                    mma16816(s[ma][2 * p + 1], qh2[ma], bh[1], bh[3]);
                    mma16816(s[ma][2 * p + 1], qh2[ma], bl[1], bl[3]);
                    mma16816(s[ma][2 * p + 1], ql2[ma], bh[1], bh[3]);
                }
            }
        }

        // ---- softmax (no max-subtraction) + P -> smem hi/lo ----
        #pragma unroll
        for (int ma = 0; ma < 2; ma++)
        #pragma unroll
        for (int half = 0; half < 2; half++) {
            int row = wm * 32 + ma * 16 + half * 8 + (lane >> 2);
            uint32_t mw = g_mbits[(size_t)(b * Tt + q0 + row) * 64 + kt * 2 + wn];
            #pragma unroll
            for (int na = 0; na < 4; na++) {
                int colb = na * 8 + (lane & 3) * 2;
                float v0 = s[ma][na][half * 2 + 0] * 0.125f;
                float v1 = s[ma][na][half * 2 + 1] * 0.125f;
                float p0 = ((mw >> colb) & 1u) ? __expf(v0) : 0.0f;
                float p1 = ((mw >> (colb + 1)) & 1u) ? __expf(v1) : 0.0f;
                lacc[ma * 2 + half] += p0 + p1;
                __nv_bfloat16 h0, l0, h1, l1;
                split2(p0, h0, l0); split2(p1, h1, l1);
                __nv_bfloat162 hp; hp.x = h0; hp.y = h1;
                __nv_bfloat162 lp; lp.x = l0; lp.y = l1;
                int col = wn * 32 + colb;
                *(__nv_bfloat162*)(Ph + row * ASTR + col) = hp;
                *(__nv_bfloat162*)(Pl + row * ASTR + col) = lp;
            }
        }
        __syncthreads();   // P complete

        // ---- O += P @ V (3-MMA split), kv = 64 -> 4 k-steps ----
        #pragma unroll
        for (int ks = 0; ks < 4; ks++) {
            uint32_t ao = (uint32_t)(wm * 32 + (lane & 15)) * (ASTR * 2)
                        + ks * 32 + (lane >> 4) * 16;
            uint32_t ph2[2][4], pl2[2][4];
            ldm4(ph2[0], tPh + ao); ldm4(ph2[1], tPh + ao + 16 * (ASTR * 2));
            ldm4(pl2[0], tPl + ao); ldm4(pl2[1], tPl + ao + 16 * (ASTR * 2));
            #pragma unroll
            for (int p = 0; p < 2; p++) {
                uint32_t bo = (uint32_t)(wn * 32 + p * 16 + (lane & 15)) * (ASTR * 2)
                            + ks * 32 + (lane >> 4) * 16;
                uint32_t bh[4], bl[4];
                ldm4(bh, tVh + bo); ldm4(bl, tVl + bo);
                #pragma unroll
                for (int ma = 0; ma < 2; ma++) {
                    mma16816(oacc[ma][2 * p],     ph2[ma], bh[0], bh[2]);
                    mma16816(oacc[ma][2 * p],     ph2[ma], bl[0], bl[2]);
                    mma16816(oacc[ma][2 * p],     pl2[ma], bh[0], bh[2]);
                    mma16816(oacc[ma][2 * p + 1], ph2[ma], bh[1], bh[3]);
                    mma16816(oacc[ma][2 * p + 1], ph2[ma], bl[1], bl[3]);
                    mma16816(oacc[ma][2 * p + 1], pl2[ma], bh[1], bh[3]);
                }
            }
        }
    }

    // ---- row-sum reduce and output ----
    #pragma unroll
    for (int i = 0; i < 4; i++) {
        lacc[i] += __shfl_xor_sync(0xffffffffu, lacc[i], 1);
        lacc[i] += __shfl_xor_sync(0xffffffffu, lacc[i], 2);
    }
    if ((lane & 3) == 0) {
        #pragma unroll
        for (int ma = 0; ma < 2; ma++)
        #pragma unroll
        for (int half = 0; half < 2; half++) {
            int row = wm * 32 + ma * 16 + half * 8 + (lane >> 2);
            lsum[wn * 128 + row] = lacc[ma * 2 + half];
        }
    }
    __syncthreads();

    #pragma unroll
    for (int ma = 0; ma < 2; ma++)
    #pragma unroll
    for (int half = 0; half < 2; half++) {
        int row = wm * 32 + ma * 16 + half * 8 + (lane >> 2);
        float inv = 1.0f / (lsum[row] + lsum[128 + row]);
        #pragma unroll
        for (int na = 0; na < 4; na++) {
            int col = wn * 32 + na * 8 + (lane & 3) * 2;
            float v0 = oacc[ma][na][half * 2 + 0] * inv;
            float v1 = oacc[ma][na][half * 2 + 1] * inv;
            __nv_bfloat16 h0, l0, h1, l1;
            split2(v0, h0, l0); split2(v1, h1, l1);
            __nv_bfloat162 hp; hp.x = h0; hp.y = h1;
            __nv_bfloat162 lp; lp.x = l0; lp.y = l1;
            size_t off = (size_t)(b * Tt + q0 + row) * 1024 + hd * 64 + col;
            *(__nv_bfloat162*)(g_zh + off) = hp;
            *(__nv_bfloat162*)(g_zl + off) = lp;
        }
    }
}

// ===========================================================================
extern "C" void kernel_launch(void* const* d_in, const int* in_sizes, int n_in,
                              void* d_out, int out_size)
{
    const float* embed = (const float*)d_in[0];
    const int*   mask  = (const int*)d_in[1];
    const float* Wq = (const float*)d_in[2];
    const float* bq = (const float*)d_in[3];
    const float* Wk = (const float*)d_in[4];
    const float* bk = (const float*)d_in[5];
    const float* Wv = (const float*)d_in[6];
    const float* bv = (const float*)d_in[7];
    const float* Wz = (const float*)d_in[8];
    const float* bz = (const float*)d_in[9];
    float* out = (float*)d_out;

    __nv_bfloat16 *eh, *el, *wth, *wtl, *qh, *ql, *kh, *kl, *vth, *vtl, *zh, *zl;
    uint32_t* mbits;
    cudaGetSymbolAddress((void**)&eh, g_eh);   cudaGetSymbolAddress((void**)&el, g_el);
    cudaGetSymbolAddress((void**)&wth, g_wth); cudaGetSymbolAddress((void**)&wtl, g_wtl);
    cudaGetSymbolAddress((void**)&qh, g_qh);   cudaGetSymbolAddress((void**)&ql, g_ql);
    cudaGetSymbolAddress((void**)&kh, g_kh);   cudaGetSymbolAddress((void**)&kl, g_kl);
    cudaGetSymbolAddress((void**)&vth, g_vth); cudaGetSymbolAddress((void**)&vtl, g_vtl);
    cudaGetSymbolAddress((void**)&zh, g_zh);   cudaGetSymbolAddress((void**)&zl, g_zl);
    cudaGetSymbolAddress((void**)&mbits, g_mbits);

    cudaFuncSetAttribute(gemm_mma, cudaFuncAttributeMaxDynamicSharedMemorySize,
                         GEMM_SMEM_BYTES);
    cudaFuncSetAttribute(attn_mma, cudaFuncAttributeMaxDynamicSharedMemorySize,
                         ATTN_SMEM_BYTES);

    const size_t WSZ = (size_t)1024 * 1024;

    // Preps
    split_f32<<<(Mtot * KDIM / 4 + 255) / 256, 256>>>(embed, eh, el, Mtot * KDIM / 4);
    dim3 tb(32, 8), tg(32, 32);
    trans_split<<<tg, tb>>>(Wq, wth + 0 * WSZ, wtl + 0 * WSZ);
    trans_split<<<tg, tb>>>(Wk, wth + 1 * WSZ, wtl + 1 * WSZ);
    trans_split<<<tg, tb>>>(Wv, wth + 2 * WSZ, wtl + 2 * WSZ);
    trans_split<<<tg, tb>>>(Wz, wth + 3 * WSZ, wtl + 3 * WSZ);
    pack_mask<<<(Bb * Tt * Tt) / 256, 256>>>(mask, mbits);

    // Projections
    dim3 gg(8, 32);
    gemm_mma<<<gg, 256, GEMM_SMEM_BYTES>>>(eh, el, wth + 0 * WSZ, wtl + 0 * WSZ, bq, 1, nullptr, qh, ql);
    gemm_mma<<<gg, 256, GEMM_SMEM_BYTES>>>(eh, el, wth + 1 * WSZ, wtl + 1 * WSZ, bk, 1, nullptr, kh, kl);
    gemm_mma<<<gg, 256, GEMM_SMEM_BYTES>>>(eh, el, wth + 2 * WSZ, wtl + 2 * WSZ, bv, 2, nullptr, vth, vtl);

    // Attention
    attn_mma<<<dim3(16, 32), 256, ATTN_SMEM_BYTES>>>();

    // Output projection -> d_out (fp32)
    gemm_mma<<<gg, 256, GEMM_SMEM_BYTES>>>(zh, zl, wth + 3 * WSZ, wtl + 3 * WSZ, bz, 0, out, nullptr, nullptr);
}

// round 5
// speedup vs baseline: 2.4354x; 1.0757x over previous
#include <cuda_runtime.h>
#include <cuda_bf16.h>
#include <cstdint>
#include <math.h>

#define Bb 2
#define Tt 2048
#define Hh 16
#define Mtot 4096
#define KDIM 1024

// ===========================================================================
// Helpers: mma.sync (bf16), ldmatrix, cp.async — all non-'a' ISA features
// ===========================================================================
__device__ __forceinline__ uint32_t smem_u32(const void* p) {
    uint32_t a;
    asm("{ .reg .u64 t; cvta.to.shared.u64 t, %1; cvt.u32.u64 %0, t; }"
        : "=r"(a) : "l"(p));
    return a;
}
__device__ __forceinline__ void cp16(uint32_t dst, const void* src) {
    asm volatile("cp.async.cg.shared.global [%0], [%1], 16;" :: "r"(dst), "l"(src));
}
#define CP_COMMIT() asm volatile("cp.async.commit_group;" ::: "memory")
#define CP_WAIT0()  asm volatile("cp.async.wait_group 0;" ::: "memory")
#define CP_WAIT1()  asm volatile("cp.async.wait_group 1;" ::: "memory")

__device__ __forceinline__ void ldm4(uint32_t* r, uint32_t a) {
    asm volatile("ldmatrix.sync.aligned.m8n8.x4.shared.b16 {%0,%1,%2,%3}, [%4];"
        : "=r"(r[0]), "=r"(r[1]), "=r"(r[2]), "=r"(r[3]) : "r"(a));
}
__device__ __forceinline__ void mma16816(float* d, const uint32_t* a,
                                         uint32_t b0, uint32_t b1) {
    asm volatile("mma.sync.aligned.m16n8k16.row.col.f32.bf16.bf16.f32 "
        "{%0,%1,%2,%3}, {%4,%5,%6,%7}, {%8,%9}, {%0,%1,%2,%3};"
        : "+f"(d[0]), "+f"(d[1]), "+f"(d[2]), "+f"(d[3])
        : "r"(a[0]), "r"(a[1]), "r"(a[2]), "r"(a[3]), "r"(b0), "r"(b1));
}

__device__ __forceinline__ void split2(float x, __nv_bfloat16& h, __nv_bfloat16& l) {
    h = __float2bfloat16(x);
    l = __float2bfloat16(x - __bfloat162float(h));
}
__device__ __forceinline__ uint32_t packbf(__nv_bfloat16 a, __nv_bfloat16 b) {
    __nv_bfloat162 t; t.x = a; t.y = b;
    return *(uint32_t*)&t;
}

// ===========================================================================
// Scratch (device globals)
// ===========================================================================
__device__ __nv_bfloat16 g_eh[(size_t)Mtot * KDIM], g_el[(size_t)Mtot * KDIM];
__device__ __nv_bfloat16 g_wth[(size_t)4 * 1024 * 1024], g_wtl[(size_t)4 * 1024 * 1024];
__device__ __nv_bfloat16 g_qh[(size_t)Mtot * KDIM], g_ql[(size_t)Mtot * KDIM];
__device__ __nv_bfloat16 g_kh[(size_t)Mtot * KDIM], g_kl[(size_t)Mtot * KDIM];
__device__ __nv_bfloat16 g_vth[(size_t)Mtot * KDIM], g_vtl[(size_t)Mtot * KDIM]; // [b][n][t]
__device__ __nv_bfloat16 g_zh[(size_t)Mtot * KDIM], g_zl[(size_t)Mtot * KDIM];
__device__ uint32_t g_mbits[(size_t)Bb * Tt * (Tt / 32)];

// ===========================================================================
// Prep kernels
// ===========================================================================
__global__ void split_f32(const float* __restrict__ x, __nv_bfloat16* __restrict__ h,
                          __nv_bfloat16* __restrict__ l, int n4) {
    int i = blockIdx.x * blockDim.x + threadIdx.x;
    if (i >= n4) return;
    float4 v = ((const float4*)x)[i];
    __nv_bfloat16 h0, h1, h2, h3, l0, l1, l2, l3;
    split2(v.x, h0, l0); split2(v.y, h1, l1); split2(v.z, h2, l2); split2(v.w, h3, l3);
    ((uint32_t*)h)[2 * i] = packbf(h0, h1); ((uint32_t*)h)[2 * i + 1] = packbf(h2, h3);
    ((uint32_t*)l)[2 * i] = packbf(l0, l1); ((uint32_t*)l)[2 * i + 1] = packbf(l2, l3);
}

// Fused: 4 weight matrices W[K,N] (1024x1024) -> WT[N,K] split hi/lo
__global__ void trans_split4(const float* __restrict__ W0, const float* __restrict__ W1,
                             const float* __restrict__ W2, const float* __restrict__ W3,
                             __nv_bfloat16* __restrict__ Th, __nv_bfloat16* __restrict__ Tl) {
    __shared__ float t[32][33];
    const float* W = (blockIdx.z == 0) ? W0 : (blockIdx.z == 1) ? W1
                   : (blockIdx.z == 2) ? W2 : W3;
    size_t dbase = (size_t)blockIdx.z * 1024 * 1024;
    int tx = threadIdx.x, ty = threadIdx.y;
    int x0 = blockIdx.x * 32, y0 = blockIdx.y * 32;
    #pragma unroll
    for (int i = 0; i < 32; i += 8)
        t[ty + i][tx] = W[(size_t)(y0 + ty + i) * 1024 + x0 + tx];
    __syncthreads();
    #pragma unroll
    for (int i = 0; i < 32; i += 8) {
        float v = t[tx][ty + i];
        size_t o = dbase + (size_t)(x0 + ty + i) * 1024 + y0 + tx;
        __nv_bfloat16 h, l; split2(v, h, l);
        Th[o] = h; Tl[o] = l;
    }
}

__global__ void pack_mask(const int* __restrict__ m, uint32_t* __restrict__ bits) {
    int i = blockIdx.x * blockDim.x + threadIdx.x;
    uint32_t bal = __ballot_sync(0xffffffffu, m[i] != 0);
    if ((threadIdx.x & 31) == 0) bits[i >> 5] = bal;
}

// ===========================================================================
// GEMM (mma.sync split-bf16): C[M,1024] = A[M,1024] @ Wt^T + bias
// (unchanged from R4 — passing)
// ===========================================================================
#define GSTR 40
#define GTILE (128 * GSTR)
#define GBUF  (4 * GTILE)
#define GEMM_SMEM_BYTES (2 * GBUF * 2)

__global__ __launch_bounds__(256) void gemm_mma(
    const __nv_bfloat16* __restrict__ Ah, const __nv_bfloat16* __restrict__ Al,
    const __nv_bfloat16* __restrict__ Bh, const __nv_bfloat16* __restrict__ Bl,
    const float* __restrict__ bias, int mode, float* __restrict__ outF,
    __nv_bfloat16* __restrict__ Oh, __nv_bfloat16* __restrict__ Ol)
{
    extern __shared__ __nv_bfloat16 sm[];
    uint32_t sb = smem_u32(sm);
    int tid = threadIdx.x, lane = tid & 31, w = tid >> 5;
    int wm = w & 3, wn = w >> 2;
    int m0 = blockIdx.y * 128, n0 = blockIdx.x * 128;

    const __nv_bfloat16* srcs[4] = {Ah + (size_t)m0 * KDIM, Al + (size_t)m0 * KDIM,
                                    Bh + (size_t)n0 * KDIM, Bl + (size_t)n0 * KDIM};

    auto issue = [&](int ch, int buf) {
        uint32_t dbase = sb + (uint32_t)buf * (GBUF * 2);
        #pragma unroll
        for (int t = 0; t < 4; t++) {
            #pragma unroll
            for (int i = 0; i < 2; i++) {
                int idx = tid + i * 256;
                int row = idx >> 2, c = idx & 3;
                cp16(dbase + t * (GTILE * 2) + row * (GSTR * 2) + c * 16,
                     srcs[t] + (size_t)row * KDIM + ch * 32 + c * 8);
            }
        }
        CP_COMMIT();
    };

    float acc[2][8][4];
    #pragma unroll
    for (int ma = 0; ma < 2; ma++)
        #pragma unroll
        for (int na = 0; na < 8; na++)
            #pragma unroll
            for (int j = 0; j < 4; j++) acc[ma][na][j] = 0.0f;

    issue(0, 0);
    const int NC = KDIM / 32;
    for (int ch = 0; ch < NC; ch++) {
        __syncthreads();
        if (ch + 1 < NC) { issue(ch + 1, (ch + 1) & 1); CP_WAIT1(); }
        else             { CP_WAIT0(); }
        __syncthreads();
        uint32_t bb = sb + (uint32_t)(ch & 1) * (GBUF * 2);
        uint32_t tAh = bb, tAl = bb + GTILE * 2;
        uint32_t tBh = bb + 2 * GTILE * 2, tBl = bb + 3 * GTILE * 2;
        #pragma unroll
        for (int ks = 0; ks < 2; ks++) {
            uint32_t ao = (uint32_t)(wm * 32 + (lane & 15)) * (GSTR * 2)
                        + ks * 32 + (lane >> 4) * 16;
            uint32_t ah[2][4], al[2][4];
            ldm4(ah[0], tAh + ao); ldm4(ah[1], tAh + ao + 16 * (GSTR * 2));
            ldm4(al[0], tAl + ao); ldm4(al[1], tAl + ao + 16 * (GSTR * 2));
            #pragma unroll
            for (int p = 0; p < 4; p++) {
                uint32_t bo = (uint32_t)(wn * 64 + p * 16 + (lane & 15)) * (GSTR * 2)
                            + ks * 32 + (lane >> 4) * 16;
                uint32_t bh[4], bl[4];
                ldm4(bh, tBh + bo); ldm4(bl, tBl + bo);
                #pragma unroll
                for (int ma = 0; ma < 2; ma++) {
                    mma16816(acc[ma][2 * p],     ah[ma], bh[0], bh[2]);
                    mma16816(acc[ma][2 * p],     ah[ma], bl[0], bl[2]);
                    mma16816(acc[ma][2 * p],     al[ma], bh[0], bh[2]);
                    mma16816(acc[ma][2 * p + 1], ah[ma], bh[1], bh[3]);
                    mma16816(acc[ma][2 * p + 1], ah[ma], bl[1], bl[3]);
                    mma16816(acc[ma][2 * p + 1], al[ma], bh[1], bh[3]);
                }
            }
        }
    }

    #pragma unroll
    for (int ma = 0; ma < 2; ma++)
    #pragma unroll
    for (int na = 0; na < 8; na++)
    #pragma unroll
    for (int half = 0; half < 2; half++) {
        int row = m0 + wm * 32 + ma * 16 + half * 8 + (lane >> 2);
        int col = n0 + wn * 64 + na * 8 + (lane & 3) * 2;
        float v0 = acc[ma][na][half * 2 + 0] + bias[col];
        float v1 = acc[ma][na][half * 2 + 1] + bias[col + 1];
        if (mode == 0) {
            *(float2*)(outF + (size_t)row * 1024 + col) = make_float2(v0, v1);
        } else if (mode == 1) {
            __nv_bfloat16 h0, l0, h1, l1;
            split2(v0, h0, l0); split2(v1, h1, l1);
            *(uint32_t*)(Oh + (size_t)row * 1024 + col) = packbf(h0, h1);
            *(uint32_t*)(Ol + (size_t)row * 1024 + col) = packbf(l0, l1);
        } else {
            int bi = row >> 11, t = row & 2047;
            __nv_bfloat16 h0, l0, h1, l1;
            split2(v0, h0, l0); split2(v1, h1, l1);
            Oh[((size_t)bi * 1024 + col) * 2048 + t] = h0;
            Ol[((size_t)bi * 1024 + col) * 2048 + t] = l0;
            Oh[((size_t)bi * 1024 + col + 1) * 2048 + t] = h1;
            Ol[((size_t)bi * 1024 + col + 1) * 2048 + t] = l1;
        }
    }
}

// ===========================================================================
// Attention — FA-2 style: P stays in registers (S C-fragment == PV A-fragment).
// 8 warps x 16 q-rows each; every warp spans the full 64-wide KV tile,
// so no cross-warp reductions. 32 KV tiles, cp.async double-buffered.
// ===========================================================================
#define ASTR 72                       // smem row stride (bf16 elements)
#define AQ   (128 * ASTR)
#define AKV  (64 * ASTR)
#define ATTN_SMEM_BYTES ((2 * AQ + 8 * AKV) * 2)   // 110,592

__global__ __launch_bounds__(256) void attn_mma() {
    extern __shared__ __nv_bfloat16 sm[];
    uint32_t sb = smem_u32(sm);
    int tid = threadIdx.x, lane = tid & 31, w = tid >> 5;
    int q0 = blockIdx.x * 128;
    int b = blockIdx.y >> 4, hd = blockIdx.y & 15;

    uint32_t tQh = sb, tQl = sb + AQ * 2;
    const uint32_t kvb0 = sb + 4 * AQ;   // bytes

    // Q tile hi/lo via cp.async (goes into group 0 together with KV0)
    #pragma unroll
    for (int i = 0; i < 4; i++) {
        int idx = tid + i * 256;          // 0..1023
        int row = idx >> 3, c = idx & 7;
        size_t src = (size_t)(b * Tt + q0 + row) * 1024 + hd * 64 + c * 8;
        cp16(tQh + row * (ASTR * 2) + c * 16, g_qh + src);
        cp16(tQl + row * (ASTR * 2) + c * 16, g_ql + src);
    }

    auto issueKV = [&](int kt, int buf) {
        uint32_t dbase = kvb0 + (uint32_t)buf * (4 * AKV * 2);
        int kv0 = kt * 64;
        #pragma unroll
        for (int i = 0; i < 8; i++) {
            int idx = tid + i * 256;      // 0..2047
            int t = idx >> 9;             // 0:Kh 1:Kl 2:Vh 3:Vl
            int r = (idx >> 3) & 63, c = idx & 7;
            const __nv_bfloat16* src;
            if (t == 0)      src = g_kh  + (size_t)(b * Tt + kv0 + r) * 1024 + hd * 64 + c * 8;
            else if (t == 1) src = g_kl  + (size_t)(b * Tt + kv0 + r) * 1024 + hd * 64 + c * 8;
            else if (t == 2) src = g_vth + (size_t)(b * 1024 + hd * 64 + r) * Tt + kv0 + c * 8;
            else             src = g_vtl + (size_t)(b * 1024 + hd * 64 + r) * Tt + kv0 + c * 8;
            cp16(dbase + t * (AKV * 2) + r * (ASTR * 2) + c * 16, src);
        }
        CP_COMMIT();
    };

    float o[8][4];
    #pragma unroll
    for (int t = 0; t < 8; t++)
        #pragma unroll
        for (int j = 0; j < 4; j++) o[t][j] = 0.0f;
    float lacc0 = 0.0f, lacc1 = 0.0f;

    int rowg = b * Tt + q0 + w * 16 + (lane >> 2);   // global mask row (lane's r)

    issueKV(0, 0);   // commits {Q, KV0}

    for (int kt = 0; kt < 32; kt++) {
        __syncthreads();                       // everyone done reading buffer being refilled
        if (kt + 1 < 32) { issueKV(kt + 1, (kt + 1) & 1); CP_WAIT1(); }
        else             { CP_WAIT0(); }
        __syncthreads();

        uint32_t kb = kvb0 + (uint32_t)(kt & 1) * (4 * AKV * 2);
        uint32_t tKh = kb, tKl = kb + AKV * 2;
        uint32_t tVh = kb + 2 * AKV * 2, tVl = kb + 3 * AKV * 2;

        // ---- S = Q @ K^T  (16 q-rows x 64 kv, 3-term split) ----
        float s[8][4];
        #pragma unroll
        for (int t = 0; t < 8; t++)
            #pragma unroll
            for (int j = 0; j < 4; j++) s[t][j] = 0.0f;
        #pragma unroll
        for (int ks = 0; ks < 4; ks++) {
            uint32_t ao = (uint32_t)(w * 16 + (lane & 15)) * (ASTR * 2)
                        + ks * 32 + (lane >> 4) * 16;
            uint32_t qh[4], ql[4];
            ldm4(qh, tQh + ao); ldm4(ql, tQl + ao);
            #pragma unroll
            for (int p = 0; p < 4; p++) {
                uint32_t bo = (uint32_t)(p * 16 + (lane & 15)) * (ASTR * 2)
                            + ks * 32 + (lane >> 4) * 16;
                uint32_t bh[4], bl[4];
                ldm4(bh, tKh + bo); ldm4(bl, tKl + bo);
                mma16816(s[2 * p],     qh, bh[0], bh[2]);
                mma16816(s[2 * p],     qh, bl[0], bl[2]);
                mma16816(s[2 * p],     ql, bh[0], bh[2]);
                mma16816(s[2 * p + 1], qh, bh[1], bh[3]);
                mma16816(s[2 * p + 1], qh, bl[1], bl[3]);
                mma16816(s[2 * p + 1], ql, bh[1], bh[3]);
            }
        }

        // ---- softmax in registers (no max-subtraction) + pack P fragments ----
        uint32_t mw0 = g_mbits[(size_t)rowg * 64 + kt * 2];
        uint32_t mw1 = g_mbits[(size_t)rowg * 64 + kt * 2 + 1];
        uint32_t mw2 = g_mbits[(size_t)(rowg + 8) * 64 + kt * 2];
        uint32_t mw3 = g_mbits[(size_t)(rowg + 8) * 64 + kt * 2 + 1];

        uint32_t afh[4][4], afl[4][4];
        #pragma unroll
        for (int t = 0; t < 8; t++) {
            int cb = 8 * t + 2 * (lane & 3);
            uint32_t wa = (t < 4) ? mw0 : mw1;
            uint32_t wb = (t < 4) ? mw2 : mw3;
            int bit = cb & 31;
            float p0 = ((wa >> bit) & 1u)       ? __expf(s[t][0] * 0.125f) : 0.0f;
            float p1 = ((wa >> (bit + 1)) & 1u) ? __expf(s[t][1] * 0.125f) : 0.0f;
            float p2 = ((wb >> bit) & 1u)       ? __expf(s[t][2] * 0.125f) : 0.0f;
            float p3 = ((wb >> (bit + 1)) & 1u) ? __expf(s[t][3] * 0.125f) : 0.0f;
            lacc0 += p0 + p1;
            lacc1 += p2 + p3;
            __nv_bfloat16 h0, l0, h1, l1, h2, l2, h3, l3;
            split2(p0, h0, l0); split2(p1, h1, l1);
            split2(p2, h2, l2); split2(p3, h3, l3);
            int u = t >> 1, k = (t & 1) * 2;
            afh[u][k]     = packbf(h0, h1);
            afh[u][k + 1] = packbf(h2, h3);
            afl[u][k]     = packbf(l0, l1);
            afl[u][k + 1] = packbf(l2, l3);
        }

        // ---- O += P @ V  (P in registers; V^T is the B operand) ----
        #pragma unroll
        for (int u = 0; u < 4; u++) {
            #pragma unroll
            for (int p = 0; p < 4; p++) {
                uint32_t bo = (uint32_t)(p * 16 + (lane & 15)) * (ASTR * 2)
                            + u * 32 + (lane >> 4) * 16;
                uint32_t vh[4], vl[4];
                ldm4(vh, tVh + bo); ldm4(vl, tVl + bo);
                mma16816(o[2 * p],     afh[u], vh[0], vh[2]);
                mma16816(o[2 * p],     afh[u], vl[0], vl[2]);
                mma16816(o[2 * p],     afl[u], vh[0], vh[2]);
                mma16816(o[2 * p + 1], afh[u], vh[1], vh[3]);
                mma16816(o[2 * p + 1], afh[u], vl[1], vl[3]);
                mma16816(o[2 * p + 1], afl[u], vh[1], vh[3]);
            }
        }
    }

    // ---- epilogue: normalize, split, store z ----
    lacc0 += __shfl_xor_sync(0xffffffffu, lacc0, 1);
    lacc0 += __shfl_xor_sync(0xffffffffu, lacc0, 2);
    lacc1 += __shfl_xor_sync(0xffffffffu, lacc1, 1);
    lacc1 += __shfl_xor_sync(0xffffffffu, lacc1, 2);
    float inv0 = 1.0f / lacc0, inv1 = 1.0f / lacc1;

    int row = q0 + w * 16 + (lane >> 2);
    #pragma unroll
    for (int t = 0; t < 8; t++) {
        int col = hd * 64 + 8 * t + 2 * (lane & 3);
        float v0 = o[t][0] * inv0, v1 = o[t][1] * inv0;
        float v2 = o[t][2] * inv1, v3 = o[t][3] * inv1;
        __nv_bfloat16 h0, l0, h1, l1, h2, l2, h3, l3;
        split2(v0, h0, l0); split2(v1, h1, l1);
        split2(v2, h2, l2); split2(v3, h3, l3);
        size_t o0 = (size_t)(b * Tt + row) * 1024 + col;
        size_t o1 = (size_t)(b * Tt + row + 8) * 1024 + col;
        *(uint32_t*)(g_zh + o0) = packbf(h0, h1);
        *(uint32_t*)(g_zl + o0) = packbf(l0, l1);
        *(uint32_t*)(g_zh + o1) = packbf(h2, h3);
        *(uint32_t*)(g_zl + o1) = packbf(l2, l3);
    }
}

// ===========================================================================
extern "C" void kernel_launch(void* const* d_in, const int* in_sizes, int n_in,
                              void* d_out, int out_size)
{
    const float* embed = (const float*)d_in[0];
    const int*   mask  = (const int*)d_in[1];
    const float* Wq = (const float*)d_in[2];
    const float* bq = (const float*)d_in[3];
    const float* Wk = (const float*)d_in[4];
    const float* bk = (const float*)d_in[5];
    const float* Wv = (const float*)d_in[6];
    const float* bv = (const float*)d_in[7];
    const float* Wz = (const float*)d_in[8];
    const float* bz = (const float*)d_in[9];
    float* out = (float*)d_out;

    __nv_bfloat16 *eh, *el, *wth, *wtl, *qh, *ql, *kh, *kl, *vth, *vtl, *zh, *zl;
    uint32_t* mbits;
    cudaGetSymbolAddress((void**)&eh, g_eh);   cudaGetSymbolAddress((void**)&el, g_el);
    cudaGetSymbolAddress((void**)&wth, g_wth); cudaGetSymbolAddress((void**)&wtl, g_wtl);
    cudaGetSymbolAddress((void**)&qh, g_qh);   cudaGetSymbolAddress((void**)&ql, g_ql);
    cudaGetSymbolAddress((void**)&kh, g_kh);   cudaGetSymbolAddress((void**)&kl, g_kl);
    cudaGetSymbolAddress((void**)&vth, g_vth); cudaGetSymbolAddress((void**)&vtl, g_vtl);
    cudaGetSymbolAddress((void**)&zh, g_zh);   cudaGetSymbolAddress((void**)&zl, g_zl);
    cudaGetSymbolAddress((void**)&mbits, g_mbits);

    cudaFuncSetAttribute(gemm_mma, cudaFuncAttributeMaxDynamicSharedMemorySize,
                         GEMM_SMEM_BYTES);
    cudaFuncSetAttribute(attn_mma, cudaFuncAttributeMaxDynamicSharedMemorySize,
                         ATTN_SMEM_BYTES);

    const size_t WSZ = (size_t)1024 * 1024;

    // Preps
    split_f32<<<(Mtot * KDIM / 4 + 255) / 256, 256>>>(embed, eh, el, Mtot * KDIM / 4);
    dim3 tb(32, 8), tg4(32, 32, 4);
    trans_split4<<<tg4, tb>>>(Wq, Wk, Wv, Wz, wth, wtl);
    pack_mask<<<(Bb * Tt * Tt) / 256, 256>>>(mask, mbits);

    // Projections
    dim3 gg(8, 32);
    gemm_mma<<<gg, 256, GEMM_SMEM_BYTES>>>(eh, el, wth + 0 * WSZ, wtl + 0 * WSZ, bq, 1, nullptr, qh, ql);
    gemm_mma<<<gg, 256, GEMM_SMEM_BYTES>>>(eh, el, wth + 1 * WSZ, wtl + 1 * WSZ, bk, 1, nullptr, kh, kl);
    gemm_mma<<<gg, 256, GEMM_SMEM_BYTES>>>(eh, el, wth + 2 * WSZ, wtl + 2 * WSZ, bv, 2, nullptr, vth, vtl);

    // Attention
    attn_mma<<<dim3(16, 32), 256, ATTN_SMEM_BYTES>>>();

    // Output projection -> d_out (fp32)
    gemm_mma<<<gg, 256, GEMM_SMEM_BYTES>>>(zh, zl, wth + 3 * WSZ, wtl + 3 * WSZ, bz, 0, out, nullptr, nullptr);
}

// round 6
// speedup vs baseline: 2.4630x; 1.0113x over previous
#include <cuda_runtime.h>
#include <cuda_bf16.h>
#include <cstdint>
#include <math.h>

#define Bb 2
#define Tt 2048
#define Hh 16
#define Mtot 4096
#define KDIM 1024

// ===========================================================================
// Helpers: mma.sync (bf16), ldmatrix, cp.async
// ===========================================================================
__device__ __forceinline__ uint32_t smem_u32(const void* p) {
    uint32_t a;
    asm("{ .reg .u64 t; cvta.to.shared.u64 t, %1; cvt.u32.u64 %0, t; }"
        : "=r"(a) : "l"(p));
    return a;
}
__device__ __forceinline__ void cp16(uint32_t dst, const void* src) {
    asm volatile("cp.async.cg.shared.global [%0], [%1], 16;" :: "r"(dst), "l"(src));
}
#define CP_COMMIT() asm volatile("cp.async.commit_group;" ::: "memory")
#define CP_WAIT0()  asm volatile("cp.async.wait_group 0;" ::: "memory")
#define CP_WAIT1()  asm volatile("cp.async.wait_group 1;" ::: "memory")

__device__ __forceinline__ void ldm4(uint32_t* r, uint32_t a) {
    asm volatile("ldmatrix.sync.aligned.m8n8.x4.shared.b16 {%0,%1,%2,%3}, [%4];"
        : "=r"(r[0]), "=r"(r[1]), "=r"(r[2]), "=r"(r[3]) : "r"(a));
}
__device__ __forceinline__ void mma16816(float* d, const uint32_t* a,
                                         uint32_t b0, uint32_t b1) {
    asm volatile("mma.sync.aligned.m16n8k16.row.col.f32.bf16.bf16.f32 "
        "{%0,%1,%2,%3}, {%4,%5,%6,%7}, {%8,%9}, {%0,%1,%2,%3};"
        : "+f"(d[0]), "+f"(d[1]), "+f"(d[2]), "+f"(d[3])
        : "r"(a[0]), "r"(a[1]), "r"(a[2]), "r"(a[3]), "r"(b0), "r"(b1));
}

__device__ __forceinline__ void split2(float x, __nv_bfloat16& h, __nv_bfloat16& l) {
    h = __float2bfloat16(x);
    l = __float2bfloat16(x - __bfloat162float(h));
}
__device__ __forceinline__ uint32_t packbf(__nv_bfloat16 a, __nv_bfloat16 b) {
    __nv_bfloat162 t; t.x = a; t.y = b;
    return *(uint32_t*)&t;
}

// ===========================================================================
// Scratch (device globals)
// ===========================================================================
__device__ __nv_bfloat16 g_eh[(size_t)Mtot * KDIM], g_el[(size_t)Mtot * KDIM];
__device__ __nv_bfloat16 g_wth[(size_t)4 * 1024 * 1024], g_wtl[(size_t)4 * 1024 * 1024];
__device__ __nv_bfloat16 g_qh[(size_t)Mtot * KDIM], g_ql[(size_t)Mtot * KDIM];
__device__ __nv_bfloat16 g_kh[(size_t)Mtot * KDIM], g_kl[(size_t)Mtot * KDIM];
__device__ __nv_bfloat16 g_vth[(size_t)Mtot * KDIM], g_vtl[(size_t)Mtot * KDIM]; // [b][n][t]
__device__ __nv_bfloat16 g_zh[(size_t)Mtot * KDIM], g_zl[(size_t)Mtot * KDIM];
__device__ uint32_t g_mbits[(size_t)Bb * Tt * (Tt / 32)];

// ===========================================================================
// Prep kernels
// ===========================================================================
__global__ void split_f32(const float* __restrict__ x, __nv_bfloat16* __restrict__ h,
                          __nv_bfloat16* __restrict__ l, int n4) {
    int i = blockIdx.x * blockDim.x + threadIdx.x;
    if (i >= n4) return;
    float4 v = ((const float4*)x)[i];
    __nv_bfloat16 h0, h1, h2, h3, l0, l1, l2, l3;
    split2(v.x, h0, l0); split2(v.y, h1, l1); split2(v.z, h2, l2); split2(v.w, h3, l3);
    ((uint32_t*)h)[2 * i] = packbf(h0, h1); ((uint32_t*)h)[2 * i + 1] = packbf(h2, h3);
    ((uint32_t*)l)[2 * i] = packbf(l0, l1); ((uint32_t*)l)[2 * i + 1] = packbf(l2, l3);
}

// Fused: 4 weight matrices W[K,N] (1024x1024) -> WT[N,K] split hi/lo
__global__ void trans_split4(const float* __restrict__ W0, const float* __restrict__ W1,
                             const float* __restrict__ W2, const float* __restrict__ W3,
                             __nv_bfloat16* __restrict__ Th, __nv_bfloat16* __restrict__ Tl) {
    __shared__ float t[32][33];
    const float* W = (blockIdx.z == 0) ? W0 : (blockIdx.z == 1) ? W1
                   : (blockIdx.z == 2) ? W2 : W3;
    size_t dbase = (size_t)blockIdx.z * 1024 * 1024;
    int tx = threadIdx.x, ty = threadIdx.y;
    int x0 = blockIdx.x * 32, y0 = blockIdx.y * 32;
    #pragma unroll
    for (int i = 0; i < 32; i += 8)
        t[ty + i][tx] = W[(size_t)(y0 + ty + i) * 1024 + x0 + tx];
    __syncthreads();
    #pragma unroll
    for (int i = 0; i < 32; i += 8) {
        float v = t[tx][ty + i];
        size_t o = dbase + (size_t)(x0 + ty + i) * 1024 + y0 + tx;
        __nv_bfloat16 h, l; split2(v, h, l);
        Th[o] = h; Tl[o] = l;
    }
}

__global__ void pack_mask(const int* __restrict__ m, uint32_t* __restrict__ bits) {
    int i = blockIdx.x * blockDim.x + threadIdx.x;
    uint32_t bal = __ballot_sync(0xffffffffu, m[i] != 0);
    if ((threadIdx.x & 31) == 0) bits[i >> 5] = bal;
}

// ===========================================================================
// GEMM core: 128x64 CTA tile, 8 warps x (16 rows x 64 cols), KC=32, 2-stage.
// Smem/stage: Ah[128][40] Al[128][40] Bh[64][40] Bl[64][40] (bf16)
// ===========================================================================
#define GSTR 40
#define GA (128 * GSTR)                 // 5120 el per A split
#define GB (64 * GSTR)                  // 2560 el per B split
#define GBUFEL (2 * GA + 2 * GB)        // 15360 el per stage
#define GEMM_SMEM_BYTES (2 * GBUFEL * 2)   // 61440 B

__device__ __forceinline__ void gemm_core(
    uint32_t sb, int tid, int lane, int w,
    const __nv_bfloat16* __restrict__ Ah, const __nv_bfloat16* __restrict__ Al,
    const __nv_bfloat16* __restrict__ Bh, const __nv_bfloat16* __restrict__ Bl,
    int m0, int n0, float acc[8][4])
{
    const __nv_bfloat16* srcA[2] = {Ah + (size_t)m0 * KDIM, Al + (size_t)m0 * KDIM};
    const __nv_bfloat16* srcB[2] = {Bh + (size_t)n0 * KDIM, Bl + (size_t)n0 * KDIM};

    auto issue = [&](int ch, int buf) {
        uint32_t dbase = sb + (uint32_t)buf * (GBUFEL * 2);
        #pragma unroll
        for (int i = 0; i < 6; i++) {
            int idx = tid + i * 256;            // 0..1535
            if (idx < 1024) {
                int sp = idx >> 9, r = (idx >> 2) & 127, c = idx & 3;
                cp16(dbase + sp * (GA * 2) + r * (GSTR * 2) + c * 16,
                     srcA[sp] + (size_t)r * KDIM + ch * 32 + c * 8);
            } else {
                int j = idx - 1024;             // 0..511
                int sp = j >> 8, r = (j >> 2) & 63, c = j & 3;
                cp16(dbase + (2 * GA + sp * GB) * 2 + r * (GSTR * 2) + c * 16,
                     srcB[sp] + (size_t)r * KDIM + ch * 32 + c * 8);
            }
        }
        CP_COMMIT();
    };

    issue(0, 0);
    const int NC = KDIM / 32;
    for (int ch = 0; ch < NC; ch++) {
        __syncthreads();
        if (ch + 1 < NC) { issue(ch + 1, (ch + 1) & 1); CP_WAIT1(); }
        else             { CP_WAIT0(); }
        __syncthreads();
        uint32_t bb = sb + (uint32_t)(ch & 1) * (GBUFEL * 2);
        uint32_t tAh = bb, tAl = bb + GA * 2;
        uint32_t tBh = bb + 2 * GA * 2, tBl = tBh + GB * 2;
        #pragma unroll
        for (int ks = 0; ks < 2; ks++) {
            uint32_t ao = (uint32_t)(w * 16 + (lane & 15)) * (GSTR * 2)
                        + ks * 32 + (lane >> 4) * 16;
            uint32_t ah[4], al[4];
            ldm4(ah, tAh + ao); ldm4(al, tAl + ao);
            #pragma unroll
            for (int p = 0; p < 4; p++) {
                uint32_t bo = (uint32_t)(p * 16 + (lane & 15)) * (GSTR * 2)
                            + ks * 32 + (lane >> 4) * 16;
                uint32_t bh[4], bl[4];
                ldm4(bh, tBh + bo); ldm4(bl, tBl + bo);
                mma16816(acc[2 * p],     ah, bh[0], bh[2]);
                mma16816(acc[2 * p],     ah, bl[0], bl[2]);
                mma16816(acc[2 * p],     al, bh[0], bh[2]);
                mma16816(acc[2 * p + 1], ah, bh[1], bh[3]);
                mma16816(acc[2 * p + 1], ah, bl[1], bl[3]);
                mma16816(acc[2 * p + 1], al, bh[1], bh[3]);
            }
        }
    }
}

// Fused Q/K/V projections: blockIdx.z selects weight/bias/output.
__global__ __launch_bounds__(256, 3) void gemm_qkv(
    const __nv_bfloat16* __restrict__ Ah, const __nv_bfloat16* __restrict__ Al,
    const __nv_bfloat16* __restrict__ Wth, const __nv_bfloat16* __restrict__ Wtl,
    const float* __restrict__ bq, const float* __restrict__ bk,
    const float* __restrict__ bv,
    __nv_bfloat16* __restrict__ qh, __nv_bfloat16* __restrict__ ql,
    __nv_bfloat16* __restrict__ kh, __nv_bfloat16* __restrict__ kl,
    __nv_bfloat16* __restrict__ vth, __nv_bfloat16* __restrict__ vtl)
{
    extern __shared__ __nv_bfloat16 sm[];
    uint32_t sb = smem_u32(sm);
    int tid = threadIdx.x, lane = tid & 31, w = tid >> 5;
    int m0 = blockIdx.y * 128, n0 = blockIdx.x * 64;
    int z = blockIdx.z;
    const size_t WSZ = (size_t)1024 * 1024;
    const __nv_bfloat16* Bh = Wth + (size_t)z * WSZ;
    const __nv_bfloat16* Bl = Wtl + (size_t)z * WSZ;
    const float* bias = (z == 0) ? bq : (z == 1) ? bk : bv;

    float acc[8][4];
    #pragma unroll
    for (int na = 0; na < 8; na++)
        #pragma unroll
        for (int j = 0; j < 4; j++) acc[na][j] = 0.0f;

    gemm_core(sb, tid, lane, w, Ah, Al, Bh, Bl, m0, n0, acc);

    int r0 = m0 + w * 16 + (lane >> 2);
    #pragma unroll
    for (int na = 0; na < 8; na++) {
        int col = n0 + na * 8 + (lane & 3) * 2;
        float v0 = acc[na][0] + bias[col], v1 = acc[na][1] + bias[col + 1];
        float v2 = acc[na][2] + bias[col], v3 = acc[na][3] + bias[col + 1];
        __nv_bfloat16 h0, l0, h1, l1, h2, l2, h3, l3;
        split2(v0, h0, l0); split2(v1, h1, l1);
        split2(v2, h2, l2); split2(v3, h3, l3);
        if (z == 0 || z == 1) {
            __nv_bfloat16* Oh = (z == 0) ? qh : kh;
            __nv_bfloat16* Ol = (z == 0) ? ql : kl;
            *(uint32_t*)(Oh + (size_t)r0 * 1024 + col)       = packbf(h0, h1);
            *(uint32_t*)(Ol + (size_t)r0 * 1024 + col)       = packbf(l0, l1);
            *(uint32_t*)(Oh + (size_t)(r0 + 8) * 1024 + col) = packbf(h2, h3);
            *(uint32_t*)(Ol + (size_t)(r0 + 8) * 1024 + col) = packbf(l2, l3);
        } else {
            int bi = r0 >> 11, t = r0 & 2047;
            vth[((size_t)bi * 1024 + col) * 2048 + t] = h0;
            vtl[((size_t)bi * 1024 + col) * 2048 + t] = l0;
            vth[((size_t)bi * 1024 + col + 1) * 2048 + t] = h1;
            vtl[((size_t)bi * 1024 + col + 1) * 2048 + t] = l1;
            int r1 = r0 + 8, t1 = r1 & 2047; bi = r1 >> 11;
            vth[((size_t)bi * 1024 + col) * 2048 + t1] = h2;
            vtl[((size_t)bi * 1024 + col) * 2048 + t1] = l2;
            vth[((size_t)bi * 1024 + col + 1) * 2048 + t1] = h3;
            vtl[((size_t)bi * 1024 + col + 1) * 2048 + t1] = l3;
        }
    }
}

// Output projection: fp32 result straight to d_out.
__global__ __launch_bounds__(256, 3) void gemm_out(
    const __nv_bfloat16* __restrict__ Ah, const __nv_bfloat16* __restrict__ Al,
    const __nv_bfloat16* __restrict__ Bh, const __nv_bfloat16* __restrict__ Bl,
    const float* __restrict__ bias, float* __restrict__ outF)
{
    extern __shared__ __nv_bfloat16 sm[];
    uint32_t sb = smem_u32(sm);
    int tid = threadIdx.x, lane = tid & 31, w = tid >> 5;
    int m0 = blockIdx.y * 128, n0 = blockIdx.x * 64;

    float acc[8][4];
    #pragma unroll
    for (int na = 0; na < 8; na++)
        #pragma unroll
        for (int j = 0; j < 4; j++) acc[na][j] = 0.0f;

    gemm_core(sb, tid, lane, w, Ah, Al, Bh, Bl, m0, n0, acc);

    int r0 = m0 + w * 16 + (lane >> 2);
    #pragma unroll
    for (int na = 0; na < 8; na++) {
        int col = n0 + na * 8 + (lane & 3) * 2;
        float b0 = bias[col], b1 = bias[col + 1];
        *(float2*)(outF + (size_t)r0 * 1024 + col) =
            make_float2(acc[na][0] + b0, acc[na][1] + b1);
        *(float2*)(outF + (size_t)(r0 + 8) * 1024 + col) =
            make_float2(acc[na][2] + b0, acc[na][3] + b1);
    }
}

// ===========================================================================
// Attention — FA-2 style (unchanged from R5 except launch_bounds cap)
// ===========================================================================
#define ASTR 72
#define AQ   (128 * ASTR)
#define AKV  (64 * ASTR)
#define ATTN_SMEM_BYTES ((2 * AQ + 8 * AKV) * 2)   // 110,592

__global__ __launch_bounds__(256, 2) void attn_mma() {
    extern __shared__ __nv_bfloat16 sm[];
    uint32_t sb = smem_u32(sm);
    int tid = threadIdx.x, lane = tid & 31, w = tid >> 5;
    int q0 = blockIdx.x * 128;
    int b = blockIdx.y >> 4, hd = blockIdx.y & 15;

    uint32_t tQh = sb, tQl = sb + AQ * 2;
    const uint32_t kvb0 = sb + 4 * AQ;

    #pragma unroll
    for (int i = 0; i < 4; i++) {
        int idx = tid + i * 256;
        int row = idx >> 3, c = idx & 7;
        size_t src = (size_t)(b * Tt + q0 + row) * 1024 + hd * 64 + c * 8;
        cp16(tQh + row * (ASTR * 2) + c * 16, g_qh + src);
        cp16(tQl + row * (ASTR * 2) + c * 16, g_ql + src);
    }

    auto issueKV = [&](int kt, int buf) {
        uint32_t dbase = kvb0 + (uint32_t)buf * (4 * AKV * 2);
        int kv0 = kt * 64;
        #pragma unroll
        for (int i = 0; i < 8; i++) {
            int idx = tid + i * 256;
            int t = idx >> 9;
            int r = (idx >> 3) & 63, c = idx & 7;
            const __nv_bfloat16* src;
            if (t == 0)      src = g_kh  + (size_t)(b * Tt + kv0 + r) * 1024 + hd * 64 + c * 8;
            else if (t == 1) src = g_kl  + (size_t)(b * Tt + kv0 + r) * 1024 + hd * 64 + c * 8;
            else if (t == 2) src = g_vth + (size_t)(b * 1024 + hd * 64 + r) * Tt + kv0 + c * 8;
            else             src = g_vtl + (size_t)(b * 1024 + hd * 64 + r) * Tt + kv0 + c * 8;
            cp16(dbase + t * (AKV * 2) + r * (ASTR * 2) + c * 16, src);
        }
        CP_COMMIT();
    };

    float o[8][4];
    #pragma unroll
    for (int t = 0; t < 8; t++)
        #pragma unroll
        for (int j = 0; j < 4; j++) o[t][j] = 0.0f;
    float lacc0 = 0.0f, lacc1 = 0.0f;

    int rowg = b * Tt + q0 + w * 16 + (lane >> 2);

    issueKV(0, 0);

    for (int kt = 0; kt < 32; kt++) {
        __syncthreads();
        if (kt + 1 < 32) { issueKV(kt + 1, (kt + 1) & 1); CP_WAIT1(); }
        else             { CP_WAIT0(); }
        __syncthreads();

        uint32_t kb = kvb0 + (uint32_t)(kt & 1) * (4 * AKV * 2);
        uint32_t tKh = kb, tKl = kb + AKV * 2;
        uint32_t tVh = kb + 2 * AKV * 2, tVl = kb + 3 * AKV * 2;

        float s[8][4];
        #pragma unroll
        for (int t = 0; t < 8; t++)
            #pragma unroll
            for (int j = 0; j < 4; j++) s[t][j] = 0.0f;
        #pragma unroll
        for (int ks = 0; ks < 4; ks++) {
            uint32_t ao = (uint32_t)(w * 16 + (lane & 15)) * (ASTR * 2)
                        + ks * 32 + (lane >> 4) * 16;
            uint32_t qh[4], ql[4];
            ldm4(qh, tQh + ao); ldm4(ql, tQl + ao);
            #pragma unroll
            for (int p = 0; p < 4; p++) {
                uint32_t bo = (uint32_t)(p * 16 + (lane & 15)) * (ASTR * 2)
                            + ks * 32 + (lane >> 4) * 16;
                uint32_t bh[4], bl[4];
                ldm4(bh, tKh + bo); ldm4(bl, tKl + bo);
                mma16816(s[2 * p],     qh, bh[0], bh[2]);
                mma16816(s[2 * p],     qh, bl[0], bl[2]);
                mma16816(s[2 * p],     ql, bh[0], bh[2]);
                mma16816(s[2 * p + 1], qh, bh[1], bh[3]);
                mma16816(s[2 * p + 1], qh, bl[1], bl[3]);
                mma16816(s[2 * p + 1], ql, bh[1], bh[3]);
            }
        }

        uint32_t mw0 = g_mbits[(size_t)rowg * 64 + kt * 2];
        uint32_t mw1 = g_mbits[(size_t)rowg * 64 + kt * 2 + 1];
        uint32_t mw2 = g_mbits[(size_t)(rowg + 8) * 64 + kt * 2];
        uint32_t mw3 = g_mbits[(size_t)(rowg + 8) * 64 + kt * 2 + 1];

        uint32_t afh[4][4], afl[4][4];
        #pragma unroll
        for (int t = 0; t < 8; t++) {
            int cb = 8 * t + 2 * (lane & 3);
            uint32_t wa = (t < 4) ? mw0 : mw1;
            uint32_t wb = (t < 4) ? mw2 : mw3;
            int bit = cb & 31;
            float p0 = ((wa >> bit) & 1u)       ? __expf(s[t][0] * 0.125f) : 0.0f;
            float p1 = ((wa >> (bit + 1)) & 1u) ? __expf(s[t][1] * 0.125f) : 0.0f;
            float p2 = ((wb >> bit) & 1u)       ? __expf(s[t][2] * 0.125f) : 0.0f;
            float p3 = ((wb >> (bit + 1)) & 1u) ? __expf(s[t][3] * 0.125f) : 0.0f;
            lacc0 += p0 + p1;
            lacc1 += p2 + p3;
            __nv_bfloat16 h0, l0, h1, l1, h2, l2, h3, l3;
            split2(p0, h0, l0); split2(p1, h1, l1);
            split2(p2, h2, l2); split2(p3, h3, l3);
            int u = t >> 1, k = (t & 1) * 2;
            afh[u][k]     = packbf(h0, h1);
            afh[u][k + 1] = packbf(h2, h3);
            afl[u][k]     = packbf(l0, l1);
            afl[u][k + 1] = packbf(l2, l3);
        }

        #pragma unroll
        for (int u = 0; u < 4; u++) {
            #pragma unroll
            for (int p = 0; p < 4; p++) {
                uint32_t bo = (uint32_t)(p * 16 + (lane & 15)) * (ASTR * 2)
                            + u * 32 + (lane >> 4) * 16;
                uint32_t vh[4], vl[4];
                ldm4(vh, tVh + bo); ldm4(vl, tVl + bo);
                mma16816(o[2 * p],     afh[u], vh[0], vh[2]);
                mma16816(o[2 * p],     afh[u], vl[0], vl[2]);
                mma16816(o[2 * p],     afl[u], vh[0], vh[2]);
                mma16816(o[2 * p + 1], afh[u], vh[1], vh[3]);
                mma16816(o[2 * p + 1], afh[u], vl[1], vl[3]);
                mma16816(o[2 * p + 1], afl[u], vh[1], vh[3]);
            }
        }
    }

    lacc0 += __shfl_xor_sync(0xffffffffu, lacc0, 1);
    lacc0 += __shfl_xor_sync(0xffffffffu, lacc0, 2);
    lacc1 += __shfl_xor_sync(0xffffffffu, lacc1, 1);
    lacc1 += __shfl_xor_sync(0xffffffffu, lacc1, 2);
    float inv0 = 1.0f / lacc0, inv1 = 1.0f / lacc1;

    int row = q0 + w * 16 + (lane >> 2);
    #pragma unroll
    for (int t = 0; t < 8; t++) {
        int col = hd * 64 + 8 * t + 2 * (lane & 3);
        float v0 = o[t][0] * inv0, v1 = o[t][1] * inv0;
        float v2 = o[t][2] * inv1, v3 = o[t][3] * inv1;
        __nv_bfloat16 h0, l0, h1, l1, h2, l2, h3, l3;
        split2(v0, h0, l0); split2(v1, h1, l1);
        split2(v2, h2, l2); split2(v3, h3, l3);
        size_t o0 = (size_t)(b * Tt + row) * 1024 + col;
        size_t o1 = (size_t)(b * Tt + row + 8) * 1024 + col;
        *(uint32_t*)(g_zh + o0) = packbf(h0, h1);
        *(uint32_t*)(g_zl + o0) = packbf(l0, l1);
        *(uint32_t*)(g_zh + o1) = packbf(h2, h3);
        *(uint32_t*)(g_zl + o1) = packbf(l2, l3);
    }
}

// ===========================================================================
extern "C" void kernel_launch(void* const* d_in, const int* in_sizes, int n_in,
                              void* d_out, int out_size)
{
    const float* embed = (const float*)d_in[0];
    const int*   mask  = (const int*)d_in[1];
    const float* Wq = (const float*)d_in[2];
    const float* bq = (const float*)d_in[3];
    const float* Wk = (const float*)d_in[4];
    const float* bk = (const float*)d_in[5];
    const float* Wv = (const float*)d_in[6];
    const float* bv = (const float*)d_in[7];
    const float* Wz = (const float*)d_in[8];
    const float* bz = (const float*)d_in[9];
    float* out = (float*)d_out;

    __nv_bfloat16 *eh, *el, *wth, *wtl, *qh, *ql, *kh, *kl, *vth, *vtl, *zh, *zl;
    uint32_t* mbits;
    cudaGetSymbolAddress((void**)&eh, g_eh);   cudaGetSymbolAddress((void**)&el, g_el);
    cudaGetSymbolAddress((void**)&wth, g_wth); cudaGetSymbolAddress((void**)&wtl, g_wtl);
    cudaGetSymbolAddress((void**)&qh, g_qh);   cudaGetSymbolAddress((void**)&ql, g_ql);
    cudaGetSymbolAddress((void**)&kh, g_kh);   cudaGetSymbolAddress((void**)&kl, g_kl);
    cudaGetSymbolAddress((void**)&vth, g_vth); cudaGetSymbolAddress((void**)&vtl, g_vtl);
    cudaGetSymbolAddress((void**)&zh, g_zh);   cudaGetSymbolAddress((void**)&zl, g_zl);
    cudaGetSymbolAddress((void**)&mbits, g_mbits);

    cudaFuncSetAttribute(gemm_qkv, cudaFuncAttributeMaxDynamicSharedMemorySize,
                         GEMM_SMEM_BYTES);
    cudaFuncSetAttribute(gemm_out, cudaFuncAttributeMaxDynamicSharedMemorySize,
                         GEMM_SMEM_BYTES);
    cudaFuncSetAttribute(attn_mma, cudaFuncAttributeMaxDynamicSharedMemorySize,
                         ATTN_SMEM_BYTES);

    const size_t WSZ = (size_t)1024 * 1024;

    // Preps
    split_f32<<<(Mtot * KDIM / 4 + 255) / 256, 256>>>(embed, eh, el, Mtot * KDIM / 4);
    dim3 tb(32, 8), tg4(32, 32, 4);
    trans_split4<<<tg4, tb>>>(Wq, Wk, Wv, Wz, wth, wtl);
    pack_mask<<<(Bb * Tt * Tt) / 256, 256>>>(mask, mbits);

    // Fused Q/K/V projections (z = 0/1/2)
    gemm_qkv<<<dim3(16, 32, 3), 256, GEMM_SMEM_BYTES>>>(
        eh, el, wth, wtl, bq, bk, bv, qh, ql, kh, kl, vth, vtl);

    // Attention
    attn_mma<<<dim3(16, 32), 256, ATTN_SMEM_BYTES>>>();

    // Output projection -> d_out (fp32)
    gemm_out<<<dim3(16, 32), 256, GEMM_SMEM_BYTES>>>(
        zh, zl, wth + 3 * WSZ, wtl + 3 * WSZ, bz, out);
}

// round 7
// speedup vs baseline: 2.5309x; 1.0275x over previous
#include <cuda_runtime.h>
#include <cuda_bf16.h>
#include <cstdint>
#include <math.h>

#define Bb 2
#define Tt 2048
#define Hh 16
#define Mtot 4096
#define KDIM 1024

// ===========================================================================
// Helpers
// ===========================================================================
__device__ __forceinline__ uint32_t smem_u32(const void* p) {
    uint32_t a;
    asm("{ .reg .u64 t; cvta.to.shared.u64 t, %1; cvt.u32.u64 %0, t; }"
        : "=r"(a) : "l"(p));
    return a;
}
__device__ __forceinline__ void cp16(uint32_t dst, const void* src) {
    asm volatile("cp.async.cg.shared.global [%0], [%1], 16;" :: "r"(dst), "l"(src));
}
#define CP_COMMIT() asm volatile("cp.async.commit_group;" ::: "memory")
#define CP_WAIT0()  asm volatile("cp.async.wait_group 0;" ::: "memory")

__device__ __forceinline__ void ldm4(uint32_t* r, uint32_t a) {
    asm volatile("ldmatrix.sync.aligned.m8n8.x4.shared.b16 {%0,%1,%2,%3}, [%4];"
        : "=r"(r[0]), "=r"(r[1]), "=r"(r[2]), "=r"(r[3]) : "r"(a));
}
__device__ __forceinline__ void mma16816(float* d, const uint32_t* a,
                                         uint32_t b0, uint32_t b1) {
    asm volatile("mma.sync.aligned.m16n8k16.row.col.f32.bf16.bf16.f32 "
        "{%0,%1,%2,%3}, {%4,%5,%6,%7}, {%8,%9}, {%0,%1,%2,%3};"
        : "+f"(d[0]), "+f"(d[1]), "+f"(d[2]), "+f"(d[3])
        : "r"(a[0]), "r"(a[1]), "r"(a[2]), "r"(a[3]), "r"(b0), "r"(b1));
}

__device__ __forceinline__ void split2(float x, __nv_bfloat16& h, __nv_bfloat16& l) {
    h = __float2bfloat16(x);
    l = __float2bfloat16(x - __bfloat162float(h));
}
__device__ __forceinline__ uint32_t packbf(__nv_bfloat16 a, __nv_bfloat16 b) {
    __nv_bfloat162 t; t.x = a; t.y = b;
    return *(uint32_t*)&t;
}

// ===========================================================================
// Scratch (device globals)
// ===========================================================================
__device__ __nv_bfloat16 g_eh[(size_t)Mtot * KDIM], g_el[(size_t)Mtot * KDIM];
__device__ __nv_bfloat16 g_wth[(size_t)4 * 1024 * 1024], g_wtl[(size_t)4 * 1024 * 1024];
__device__ __nv_bfloat16 g_qh[(size_t)Mtot * KDIM], g_ql[(size_t)Mtot * KDIM];
__device__ __nv_bfloat16 g_kh[(size_t)Mtot * KDIM], g_kl[(size_t)Mtot * KDIM];
__device__ __nv_bfloat16 g_vth[(size_t)Mtot * KDIM], g_vtl[(size_t)Mtot * KDIM]; // [b][n][t]
__device__ __nv_bfloat16 g_zh[(size_t)Mtot * KDIM], g_zl[(size_t)Mtot * KDIM];
__device__ uint32_t g_mbits[(size_t)Bb * Tt * (Tt / 32)];

// ===========================================================================
// Prep kernels
// ===========================================================================
__global__ void split_f32(const float* __restrict__ x, __nv_bfloat16* __restrict__ h,
                          __nv_bfloat16* __restrict__ l, int n4) {
    int i = blockIdx.x * blockDim.x + threadIdx.x;
    if (i >= n4) return;
    float4 v = ((const float4*)x)[i];
    __nv_bfloat16 h0, h1, h2, h3, l0, l1, l2, l3;
    split2(v.x, h0, l0); split2(v.y, h1, l1); split2(v.z, h2, l2); split2(v.w, h3, l3);
    ((uint32_t*)h)[2 * i] = packbf(h0, h1); ((uint32_t*)h)[2 * i + 1] = packbf(h2, h3);
    ((uint32_t*)l)[2 * i] = packbf(l0, l1); ((uint32_t*)l)[2 * i + 1] = packbf(l2, l3);
}

__global__ void trans_split4(const float* __restrict__ W0, const float* __restrict__ W1,
                             const float* __restrict__ W2, const float* __restrict__ W3,
                             __nv_bfloat16* __restrict__ Th, __nv_bfloat16* __restrict__ Tl) {
    __shared__ float t[32][33];
    const float* W = (blockIdx.z == 0) ? W0 : (blockIdx.z == 1) ? W1
                   : (blockIdx.z == 2) ? W2 : W3;
    size_t dbase = (size_t)blockIdx.z * 1024 * 1024;
    int tx = threadIdx.x, ty = threadIdx.y;
    int x0 = blockIdx.x * 32, y0 = blockIdx.y * 32;
    #pragma unroll
    for (int i = 0; i < 32; i += 8)
        t[ty + i][tx] = W[(size_t)(y0 + ty + i) * 1024 + x0 + tx];
    __syncthreads();
    #pragma unroll
    for (int i = 0; i < 32; i += 8) {
        float v = t[tx][ty + i];
        size_t o = dbase + (size_t)(x0 + ty + i) * 1024 + y0 + tx;
        __nv_bfloat16 h, l; split2(v, h, l);
        Th[o] = h; Tl[o] = l;
    }
}

__global__ void pack_mask(const int* __restrict__ m, uint32_t* __restrict__ bits) {
    int i = blockIdx.x * blockDim.x + threadIdx.x;
    uint32_t bal = __ballot_sync(0xffffffffu, m[i] != 0);
    if ((threadIdx.x & 31) == 0) bits[i >> 5] = bal;
}

// ===========================================================================
// GEMM core: 128x64 CTA tile, 8 warps x (16 x 64), KC=32, 2-stage, 1 barrier,
// p-pair mma ordering (4 independent accumulator chains).
// ===========================================================================
#define GSTR 40
#define GA (128 * GSTR)
#define GB (64 * GSTR)
#define GBUFEL (2 * GA + 2 * GB)
#define GEMM_SMEM_BYTES (2 * GBUFEL * 2)   // 61440 B

__device__ __forceinline__ void gemm_core(
    uint32_t sb, int tid, int lane, int w,
    const __nv_bfloat16* __restrict__ Ah, const __nv_bfloat16* __restrict__ Al,
    const __nv_bfloat16* __restrict__ Bh, const __nv_bfloat16* __restrict__ Bl,
    int m0, int n0, float acc[8][4])
{
    const __nv_bfloat16* srcA[2] = {Ah + (size_t)m0 * KDIM, Al + (size_t)m0 * KDIM};
    const __nv_bfloat16* srcB[2] = {Bh + (size_t)n0 * KDIM, Bl + (size_t)n0 * KDIM};

    auto issue = [&](int ch, int buf) {
        uint32_t dbase = sb + (uint32_t)buf * (GBUFEL * 2);
        #pragma unroll
        for (int i = 0; i < 6; i++) {
            int idx = tid + i * 256;
            if (idx < 1024) {
                int sp = idx >> 9, r = (idx >> 2) & 127, c = idx & 3;
                cp16(dbase + sp * (GA * 2) + r * (GSTR * 2) + c * 16,
                     srcA[sp] + (size_t)r * KDIM + ch * 32 + c * 8);
            } else {
                int j = idx - 1024;
                int sp = j >> 8, r = (j >> 2) & 63, c = j & 3;
                cp16(dbase + (2 * GA + sp * GB) * 2 + r * (GSTR * 2) + c * 16,
                     srcB[sp] + (size_t)r * KDIM + ch * 32 + c * 8);
            }
        }
        CP_COMMIT();
    };

    issue(0, 0);
    const int NC = KDIM / 32;
    for (int ch = 0; ch < NC; ch++) {
        CP_WAIT0();
        __syncthreads();   // (a) all warps' cp groups drained; (b) prev compute done
        if (ch + 1 < NC) issue(ch + 1, (ch + 1) & 1);

        uint32_t bb = sb + (uint32_t)(ch & 1) * (GBUFEL * 2);
        uint32_t tAh = bb, tAl = bb + GA * 2;
        uint32_t tBh = bb + 2 * GA * 2, tBl = tBh + GB * 2;
        #pragma unroll
        for (int ks = 0; ks < 2; ks++) {
            uint32_t ao = (uint32_t)(w * 16 + (lane & 15)) * (GSTR * 2)
                        + ks * 32 + (lane >> 4) * 16;
            uint32_t ah[4], al[4];
            ldm4(ah, tAh + ao); ldm4(al, tAl + ao);
            #pragma unroll
            for (int pp = 0; pp < 2; pp++) {
                uint32_t bo0 = (uint32_t)((2 * pp) * 16 + (lane & 15)) * (GSTR * 2)
                             + ks * 32 + (lane >> 4) * 16;
                uint32_t bo1 = (uint32_t)((2 * pp + 1) * 16 + (lane & 15)) * (GSTR * 2)
                             + ks * 32 + (lane >> 4) * 16;
                uint32_t bh0[4], bl0[4], bh1[4], bl1[4];
                ldm4(bh0, tBh + bo0); ldm4(bh1, tBh + bo1);
                ldm4(bl0, tBl + bo0); ldm4(bl1, tBl + bo1);
                float* a0 = acc[4 * pp + 0];
                float* a1 = acc[4 * pp + 1];
                float* a2 = acc[4 * pp + 2];
                float* a3 = acc[4 * pp + 3];
                // term 1: ah * bh  (4 independent chains)
                mma16816(a0, ah, bh0[0], bh0[2]);
                mma16816(a1, ah, bh0[1], bh0[3]);
                mma16816(a2, ah, bh1[0], bh1[2]);
                mma16816(a3, ah, bh1[1], bh1[3]);
                // term 2: ah * bl
                mma16816(a0, ah, bl0[0], bl0[2]);
                mma16816(a1, ah, bl0[1], bl0[3]);
                mma16816(a2, ah, bl1[0], bl1[2]);
                mma16816(a3, ah, bl1[1], bl1[3]);
                // term 3: al * bh
                mma16816(a0, al, bh0[0], bh0[2]);
                mma16816(a1, al, bh0[1], bh0[3]);
                mma16816(a2, al, bh1[0], bh1[2]);
                mma16816(a3, al, bh1[1], bh1[3]);
            }
        }
    }
}

// Fused Q/K/V projections
__global__ __launch_bounds__(256, 3) void gemm_qkv(
    const __nv_bfloat16* __restrict__ Ah, const __nv_bfloat16* __restrict__ Al,
    const __nv_bfloat16* __restrict__ Wth, const __nv_bfloat16* __restrict__ Wtl,
    const float* __restrict__ bq, const float* __restrict__ bk,
    const float* __restrict__ bv,
    __nv_bfloat16* __restrict__ qh, __nv_bfloat16* __restrict__ ql,
    __nv_bfloat16* __restrict__ kh, __nv_bfloat16* __restrict__ kl,
    __nv_bfloat16* __restrict__ vth, __nv_bfloat16* __restrict__ vtl)
{
    extern __shared__ __nv_bfloat16 sm[];
    uint32_t sb = smem_u32(sm);
    int tid = threadIdx.x, lane = tid & 31, w = tid >> 5;
    int m0 = blockIdx.y * 128, n0 = blockIdx.x * 64;
    int z = blockIdx.z;
    const size_t WSZ = (size_t)1024 * 1024;
    const __nv_bfloat16* Bh = Wth + (size_t)z * WSZ;
    const __nv_bfloat16* Bl = Wtl + (size_t)z * WSZ;
    const float* bias = (z == 0) ? bq : (z == 1) ? bk : bv;

    float acc[8][4];
    #pragma unroll
    for (int na = 0; na < 8; na++)
        #pragma unroll
        for (int j = 0; j < 4; j++) acc[na][j] = 0.0f;

    gemm_core(sb, tid, lane, w, Ah, Al, Bh, Bl, m0, n0, acc);

    int r0 = m0 + w * 16 + (lane >> 2);
    #pragma unroll
    for (int na = 0; na < 8; na++) {
        int col = n0 + na * 8 + (lane & 3) * 2;
        float v0 = acc[na][0] + bias[col], v1 = acc[na][1] + bias[col + 1];
        float v2 = acc[na][2] + bias[col], v3 = acc[na][3] + bias[col + 1];
        __nv_bfloat16 h0, l0, h1, l1, h2, l2, h3, l3;
        split2(v0, h0, l0); split2(v1, h1, l1);
        split2(v2, h2, l2); split2(v3, h3, l3);
        if (z == 0 || z == 1) {
            __nv_bfloat16* Oh = (z == 0) ? qh : kh;
            __nv_bfloat16* Ol = (z == 0) ? ql : kl;
            *(uint32_t*)(Oh + (size_t)r0 * 1024 + col)       = packbf(h0, h1);
            *(uint32_t*)(Ol + (size_t)r0 * 1024 + col)       = packbf(l0, l1);
            *(uint32_t*)(Oh + (size_t)(r0 + 8) * 1024 + col) = packbf(h2, h3);
            *(uint32_t*)(Ol + (size_t)(r0 + 8) * 1024 + col) = packbf(l2, l3);
        } else {
            int bi = r0 >> 11, t = r0 & 2047;
            vth[((size_t)bi * 1024 + col) * 2048 + t] = h0;
            vtl[((size_t)bi * 1024 + col) * 2048 + t] = l0;
            vth[((size_t)bi * 1024 + col + 1) * 2048 + t] = h1;
            vtl[((size_t)bi * 1024 + col + 1) * 2048 + t] = l1;
            int r1 = r0 + 8, t1 = r1 & 2047; bi = r1 >> 11;
            vth[((size_t)bi * 1024 + col) * 2048 + t1] = h2;
            vtl[((size_t)bi * 1024 + col) * 2048 + t1] = l2;
            vth[((size_t)bi * 1024 + col + 1) * 2048 + t1] = h3;
            vtl[((size_t)bi * 1024 + col + 1) * 2048 + t1] = l3;
        }
    }
}

// Output projection
__global__ __launch_bounds__(256, 3) void gemm_out(
    const __nv_bfloat16* __restrict__ Ah, const __nv_bfloat16* __restrict__ Al,
    const __nv_bfloat16* __restrict__ Bh, const __nv_bfloat16* __restrict__ Bl,
    const float* __restrict__ bias, float* __restrict__ outF)
{
    extern __shared__ __nv_bfloat16 sm[];
    uint32_t sb = smem_u32(sm);
    int tid = threadIdx.x, lane = tid & 31, w = tid >> 5;
    int m0 = blockIdx.y * 128, n0 = blockIdx.x * 64;

    float acc[8][4];
    #pragma unroll
    for (int na = 0; na < 8; na++)
        #pragma unroll
        for (int j = 0; j < 4; j++) acc[na][j] = 0.0f;

    gemm_core(sb, tid, lane, w, Ah, Al, Bh, Bl, m0, n0, acc);

    int r0 = m0 + w * 16 + (lane >> 2);
    #pragma unroll
    for (int na = 0; na < 8; na++) {
        int col = n0 + na * 8 + (lane & 3) * 2;
        float b0 = bias[col], b1 = bias[col + 1];
        *(float2*)(outF + (size_t)r0 * 1024 + col) =
            make_float2(acc[na][0] + b0, acc[na][1] + b1);
        *(float2*)(outF + (size_t)(r0 + 8) * 1024 + col) =
            make_float2(acc[na][2] + b0, acc[na][3] + b1);
    }
}

// ===========================================================================
// Attention — FA-2, 1 barrier per KV tile, p-pair mma ordering
// ===========================================================================
#define ASTR 72
#define AQ   (128 * ASTR)
#define AKV  (64 * ASTR)
#define ATTN_SMEM_BYTES ((2 * AQ + 8 * AKV) * 2)   // 110,592

__global__ __launch_bounds__(256, 2) void attn_mma() {
    extern __shared__ __nv_bfloat16 sm[];
    uint32_t sb = smem_u32(sm);
    int tid = threadIdx.x, lane = tid & 31, w = tid >> 5;
    int q0 = blockIdx.x * 128;
    int b = blockIdx.y >> 4, hd = blockIdx.y & 15;

    uint32_t tQh = sb, tQl = sb + AQ * 2;
    const uint32_t kvb0 = sb + 4 * AQ;

    // Q cps join cp group 0 (committed inside issueKV(0,0))
    #pragma unroll
    for (int i = 0; i < 4; i++) {
        int idx = tid + i * 256;
        int row = idx >> 3, c = idx & 7;
        size_t src = (size_t)(b * Tt + q0 + row) * 1024 + hd * 64 + c * 8;
        cp16(tQh + row * (ASTR * 2) + c * 16, g_qh + src);
        cp16(tQl + row * (ASTR * 2) + c * 16, g_ql + src);
    }

    auto issueKV = [&](int kt, int buf) {
        uint32_t dbase = kvb0 + (uint32_t)buf * (4 * AKV * 2);
        int kv0 = kt * 64;
        #pragma unroll
        for (int i = 0; i < 8; i++) {
            int idx = tid + i * 256;
            int t = idx >> 9;
            int r = (idx >> 3) & 63, c = idx & 7;
            const __nv_bfloat16* src;
            if (t == 0)      src = g_kh  + (size_t)(b * Tt + kv0 + r) * 1024 + hd * 64 + c * 8;
            else if (t == 1) src = g_kl  + (size_t)(b * Tt + kv0 + r) * 1024 + hd * 64 + c * 8;
            else if (t == 2) src = g_vth + (size_t)(b * 1024 + hd * 64 + r) * Tt + kv0 + c * 8;
            else             src = g_vtl + (size_t)(b * 1024 + hd * 64 + r) * Tt + kv0 + c * 8;
            cp16(dbase + t * (AKV * 2) + r * (ASTR * 2) + c * 16, src);
        }
        CP_COMMIT();
    };

    float o[8][4];
    #pragma unroll
    for (int t = 0; t < 8; t++)
        #pragma unroll
        for (int j = 0; j < 4; j++) o[t][j] = 0.0f;
    float lacc0 = 0.0f, lacc1 = 0.0f;

    int rowg = b * Tt + q0 + w * 16 + (lane >> 2);

    issueKV(0, 0);

    for (int kt = 0; kt < 32; kt++) {
        CP_WAIT0();
        __syncthreads();   // cp groups drained everywhere + prev tile compute done
        if (kt + 1 < 32) issueKV(kt + 1, (kt + 1) & 1);

        uint32_t kb = kvb0 + (uint32_t)(kt & 1) * (4 * AKV * 2);
        uint32_t tKh = kb, tKl = kb + AKV * 2;
        uint32_t tVh = kb + 2 * AKV * 2, tVl = kb + 3 * AKV * 2;

        // ---- S = Q @ K^T (p-pair ordering, 4 chains) ----
        float s[8][4];
        #pragma unroll
        for (int t = 0; t < 8; t++)
            #pragma unroll
            for (int j = 0; j < 4; j++) s[t][j] = 0.0f;
        #pragma unroll
        for (int ks = 0; ks < 4; ks++) {
            uint32_t ao = (uint32_t)(w * 16 + (lane & 15)) * (ASTR * 2)
                        + ks * 32 + (lane >> 4) * 16;
            uint32_t qh[4], ql[4];
            ldm4(qh, tQh + ao); ldm4(ql, tQl + ao);
            #pragma unroll
            for (int pp = 0; pp < 2; pp++) {
                uint32_t bo0 = (uint32_t)((2 * pp) * 16 + (lane & 15)) * (ASTR * 2)
                             + ks * 32 + (lane >> 4) * 16;
                uint32_t bo1 = (uint32_t)((2 * pp + 1) * 16 + (lane & 15)) * (ASTR * 2)
                             + ks * 32 + (lane >> 4) * 16;
                uint32_t bh0[4], bl0[4], bh1[4], bl1[4];
                ldm4(bh0, tKh + bo0); ldm4(bh1, tKh + bo1);
                ldm4(bl0, tKl + bo0); ldm4(bl1, tKl + bo1);
                float* s0 = s[4 * pp + 0];
                float* s1 = s[4 * pp + 1];
                float* s2 = s[4 * pp + 2];
                float* s3 = s[4 * pp + 3];
                mma16816(s0, qh, bh0[0], bh0[2]);
                mma16816(s1, qh, bh0[1], bh0[3]);
                mma16816(s2, qh, bh1[0], bh1[2]);
                mma16816(s3, qh, bh1[1], bh1[3]);
                mma16816(s0, qh, bl0[0], bl0[2]);
                mma16816(s1, qh, bl0[1], bl0[3]);
                mma16816(s2, qh, bl1[0], bl1[2]);
                mma16816(s3, qh, bl1[1], bl1[3]);
                mma16816(s0, ql, bh0[0], bh0[2]);
                mma16816(s1, ql, bh0[1], bh0[3]);
                mma16816(s2, ql, bh1[0], bh1[2]);
                mma16816(s3, ql, bh1[1], bh1[3]);
            }
        }

        // ---- softmax in registers + pack P fragments ----
        uint32_t mw0 = g_mbits[(size_t)rowg * 64 + kt * 2];
        uint32_t mw1 = g_mbits[(size_t)rowg * 64 + kt * 2 + 1];
        uint32_t mw2 = g_mbits[(size_t)(rowg + 8) * 64 + kt * 2];
        uint32_t mw3 = g_mbits[(size_t)(rowg + 8) * 64 + kt * 2 + 1];

        uint32_t afh[4][4], afl[4][4];
        #pragma unroll
        for (int t = 0; t < 8; t++) {
            int cb = 8 * t + 2 * (lane & 3);
            uint32_t wa = (t < 4) ? mw0 : mw1;
            uint32_t wb = (t < 4) ? mw2 : mw3;
            int bit = cb & 31;
            float p0 = ((wa >> bit) & 1u)       ? __expf(s[t][0] * 0.125f) : 0.0f;
            float p1 = ((wa >> (bit + 1)) & 1u) ? __expf(s[t][1] * 0.125f) : 0.0f;
            float p2 = ((wb >> bit) & 1u)       ? __expf(s[t][2] * 0.125f) : 0.0f;
            float p3 = ((wb >> (bit + 1)) & 1u) ? __expf(s[t][3] * 0.125f) : 0.0f;
            lacc0 += p0 + p1;
            lacc1 += p2 + p3;
            __nv_bfloat16 h0, l0, h1, l1, h2, l2, h3, l3;
            split2(p0, h0, l0); split2(p1, h1, l1);
            split2(p2, h2, l2); split2(p3, h3, l3);
            int u = t >> 1, k = (t & 1) * 2;
            afh[u][k]     = packbf(h0, h1);
            afh[u][k + 1] = packbf(h2, h3);
            afl[u][k]     = packbf(l0, l1);
            afl[u][k + 1] = packbf(l2, l3);
        }

        // ---- O += P @ V (p-pair ordering) ----
        #pragma unroll
        for (int u = 0; u < 4; u++) {
            #pragma unroll
            for (int pp = 0; pp < 2; pp++) {
                uint32_t bo0 = (uint32_t)((2 * pp) * 16 + (lane & 15)) * (ASTR * 2)
                             + u * 32 + (lane >> 4) * 16;
                uint32_t bo1 = (uint32_t)((2 * pp + 1) * 16 + (lane & 15)) * (ASTR * 2)
                             + u * 32 + (lane >> 4) * 16;
                uint32_t vh0[4], vl0[4], vh1[4], vl1[4];
                ldm4(vh0, tVh + bo0); ldm4(vh1, tVh + bo1);
                ldm4(vl0, tVl + bo0); ldm4(vl1, tVl + bo1);
                float* o0 = o[4 * pp + 0];
                float* o1 = o[4 * pp + 1];
                float* o2 = o[4 * pp + 2];
                float* o3 = o[4 * pp + 3];
                mma16816(o0, afh[u], vh0[0], vh0[2]);
                mma16816(o1, afh[u], vh0[1], vh0[3]);
                mma16816(o2, afh[u], vh1[0], vh1[2]);
                mma16816(o3, afh[u], vh1[1], vh1[3]);
                mma16816(o0, afh[u], vl0[0], vl0[2]);
                mma16816(o1, afh[u], vl0[1], vl0[3]);
                mma16816(o2, afh[u], vl1[0], vl1[2]);
                mma16816(o3, afh[u], vl1[1], vl1[3]);
                mma16816(o0, afl[u], vh0[0], vh0[2]);
                mma16816(o1, afl[u], vh0[1], vh0[3]);
                mma16816(o2, afl[u], vh1[0], vh1[2]);
                mma16816(o3, afl[u], vh1[1], vh1[3]);
            }
        }
    }

    lacc0 += __shfl_xor_sync(0xffffffffu, lacc0, 1);
    lacc0 += __shfl_xor_sync(0xffffffffu, lacc0, 2);
    lacc1 += __shfl_xor_sync(0xffffffffu, lacc1, 1);
    lacc1 += __shfl_xor_sync(0xffffffffu, lacc1, 2);
    float inv0 = 1.0f / lacc0, inv1 = 1.0f / lacc1;

    int row = q0 + w * 16 + (lane >> 2);
    #pragma unroll
    for (int t = 0; t < 8; t++) {
        int col = hd * 64 + 8 * t + 2 * (lane & 3);
        float v0 = o[t][0] * inv0, v1 = o[t][1] * inv0;
        float v2 = o[t][2] * inv1, v3 = o[t][3] * inv1;
        __nv_bfloat16 h0, l0, h1, l1, h2, l2, h3, l3;
        split2(v0, h0, l0); split2(v1, h1, l1);
        split2(v2, h2, l2); split2(v3, h3, l3);
        size_t o0 = (size_t)(b * Tt + row) * 1024 + col;
        size_t o1 = (size_t)(b * Tt + row + 8) * 1024 + col;
        *(uint32_t*)(g_zh + o0) = packbf(h0, h1);
        *(uint32_t*)(g_zl + o0) = packbf(l0, l1);
        *(uint32_t*)(g_zh + o1) = packbf(h2, h3);
        *(uint32_t*)(g_zl + o1) = packbf(l2, l3);
    }
}

// ===========================================================================
extern "C" void kernel_launch(void* const* d_in, const int* in_sizes, int n_in,
                              void* d_out, int out_size)
{
    const float* embed = (const float*)d_in[0];
    const int*   mask  = (const int*)d_in[1];
    const float* Wq = (const float*)d_in[2];
    const float* bq = (const float*)d_in[3];
    const float* Wk = (const float*)d_in[4];
    const float* bk = (const float*)d_in[5];
    const float* Wv = (const float*)d_in[6];
    const float* bv = (const float*)d_in[7];
    const float* Wz = (const float*)d_in[8];
    const float* bz = (const float*)d_in[9];
    float* out = (float*)d_out;

    __nv_bfloat16 *eh, *el, *wth, *wtl, *qh, *ql, *kh, *kl, *vth, *vtl, *zh, *zl;
    uint32_t* mbits;
    cudaGetSymbolAddress((void**)&eh, g_eh);   cudaGetSymbolAddress((void**)&el, g_el);
    cudaGetSymbolAddress((void**)&wth, g_wth); cudaGetSymbolAddress((void**)&wtl, g_wtl);
    cudaGetSymbolAddress((void**)&qh, g_qh);   cudaGetSymbolAddress((void**)&ql, g_ql);
    cudaGetSymbolAddress((void**)&kh, g_kh);   cudaGetSymbolAddress((void**)&kl, g_kl);
    cudaGetSymbolAddress((void**)&vth, g_vth); cudaGetSymbolAddress((void**)&vtl, g_vtl);
    cudaGetSymbolAddress((void**)&zh, g_zh);   cudaGetSymbolAddress((void**)&zl, g_zl);
    cudaGetSymbolAddress((void**)&mbits, g_mbits);

    cudaFuncSetAttribute(gemm_qkv, cudaFuncAttributeMaxDynamicSharedMemorySize,
                         GEMM_SMEM_BYTES);
    cudaFuncSetAttribute(gemm_out, cudaFuncAttributeMaxDynamicSharedMemorySize,
                         GEMM_SMEM_BYTES);
    cudaFuncSetAttribute(attn_mma, cudaFuncAttributeMaxDynamicSharedMemorySize,
                         ATTN_SMEM_BYTES);

    const size_t WSZ = (size_t)1024 * 1024;

    // Preps
    split_f32<<<(Mtot * KDIM / 4 + 255) / 256, 256>>>(embed, eh, el, Mtot * KDIM / 4);
    dim3 tb(32, 8), tg4(32, 32, 4);
    trans_split4<<<tg4, tb>>>(Wq, Wk, Wv, Wz, wth, wtl);
    pack_mask<<<(Bb * Tt * Tt) / 256, 256>>>(mask, mbits);

    // Fused Q/K/V projections
    gemm_qkv<<<dim3(16, 32, 3), 256, GEMM_SMEM_BYTES>>>(
        eh, el, wth, wtl, bq, bk, bv, qh, ql, kh, kl, vth, vtl);

    // Attention
    attn_mma<<<dim3(16, 32), 256, ATTN_SMEM_BYTES>>>();

    // Output projection -> d_out (fp32)
    gemm_out<<<dim3(16, 32), 256, GEMM_SMEM_BYTES>>>(
        zh, zl, wth + 3 * WSZ, wtl + 3 * WSZ, bz, out);
}

// round 8
// speedup vs baseline: 3.4070x; 1.3462x over previous
#include <cuda_runtime.h>
#include <cuda_fp16.h>
#include <cstdint>
#include <math.h>

#define Bb 2
#define Tt 2048
#define Hh 16
#define Mtot 4096
#define KDIM 1024

// ===========================================================================
// Helpers
// ===========================================================================
__device__ __forceinline__ uint32_t smem_u32(const void* p) {
    uint32_t a;
    asm("{ .reg .u64 t; cvta.to.shared.u64 t, %1; cvt.u32.u64 %0, t; }"
        : "=r"(a) : "l"(p));
    return a;
}
__device__ __forceinline__ void cp16(uint32_t dst, const void* src) {
    asm volatile("cp.async.cg.shared.global [%0], [%1], 16;" :: "r"(dst), "l"(src));
}
#define CP_COMMIT() asm volatile("cp.async.commit_group;" ::: "memory")
#define CP_WAIT0()  asm volatile("cp.async.wait_group 0;" ::: "memory")

__device__ __forceinline__ void ldm4(uint32_t* r, uint32_t a) {
    asm volatile("ldmatrix.sync.aligned.m8n8.x4.shared.b16 {%0,%1,%2,%3}, [%4];"
        : "=r"(r[0]), "=r"(r[1]), "=r"(r[2]), "=r"(r[3]) : "r"(a));
}
__device__ __forceinline__ void mma16816(float* d, const uint32_t* a,
                                         uint32_t b0, uint32_t b1) {
    asm volatile("mma.sync.aligned.m16n8k16.row.col.f32.f16.f16.f32 "
        "{%0,%1,%2,%3}, {%4,%5,%6,%7}, {%8,%9}, {%0,%1,%2,%3};"
        : "+f"(d[0]), "+f"(d[1]), "+f"(d[2]), "+f"(d[3])
        : "r"(a[0]), "r"(a[1]), "r"(a[2]), "r"(a[3]), "r"(b0), "r"(b1));
}

__device__ __forceinline__ void split2h(float x, __half& h, __half& l) {
    h = __float2half(x);
    l = __float2half(x - __half2float(h));
}
__device__ __forceinline__ uint32_t packh(__half a, __half b) {
    __half2 t; t.x = a; t.y = b;
    return *(uint32_t*)&t;
}
__device__ __forceinline__ uint32_t packhf(float a, float b) {
    __half2 t; t.x = __float2half(a); t.y = __float2half(b);
    return *(uint32_t*)&t;
}

// ===========================================================================
// Scratch (device globals) — fp16 scheme: A-operands single, B-operands hi/lo
// ===========================================================================
__device__ __half g_e[(size_t)Mtot * KDIM];                                   // embed (A)
__device__ __half g_wh[(size_t)4 * 1024 * 1024], g_wl[(size_t)4 * 1024 * 1024]; // W^T hi/lo (B)
__device__ __half g_q[(size_t)Mtot * KDIM];                                   // Q (A in S)
__device__ __half g_kh[(size_t)Mtot * KDIM], g_kl[(size_t)Mtot * KDIM];       // K hi/lo (B)
__device__ __half g_vth[(size_t)Mtot * KDIM], g_vtl[(size_t)Mtot * KDIM];     // V^T hi/lo (B), [b][n][t]
__device__ __half g_z[(size_t)Mtot * KDIM];                                   // Z (A in out-proj)
__device__ uint32_t g_mbits[(size_t)Bb * Tt * (Tt / 32)];

// ===========================================================================
// Prep kernels
// ===========================================================================
__global__ void conv_f16(const float* __restrict__ x, __half* __restrict__ o, int n4) {
    int i = blockIdx.x * blockDim.x + threadIdx.x;
    if (i >= n4) return;
    float4 v = ((const float4*)x)[i];
    ((uint32_t*)o)[2 * i]     = packhf(v.x, v.y);
    ((uint32_t*)o)[2 * i + 1] = packhf(v.z, v.w);
}

// 4 weight matrices W[K,N] -> WT[N,K] fp16 hi/lo
__global__ void trans_split4(const float* __restrict__ W0, const float* __restrict__ W1,
                             const float* __restrict__ W2, const float* __restrict__ W3,
                             __half* __restrict__ Th, __half* __restrict__ Tl) {
    __shared__ float t[32][33];
    const float* W = (blockIdx.z == 0) ? W0 : (blockIdx.z == 1) ? W1
                   : (blockIdx.z == 2) ? W2 : W3;
    size_t dbase = (size_t)blockIdx.z * 1024 * 1024;
    int tx = threadIdx.x, ty = threadIdx.y;
    int x0 = blockIdx.x * 32, y0 = blockIdx.y * 32;
    #pragma unroll
    for (int i = 0; i < 32; i += 8)
        t[ty + i][tx] = W[(size_t)(y0 + ty + i) * 1024 + x0 + tx];
    __syncthreads();
    #pragma unroll
    for (int i = 0; i < 32; i += 8) {
        float v = t[tx][ty + i];
        size_t o = dbase + (size_t)(x0 + ty + i) * 1024 + y0 + tx;
        __half h, l; split2h(v, h, l);
        Th[o] = h; Tl[o] = l;
    }
}

__global__ void pack_mask(const int* __restrict__ m, uint32_t* __restrict__ bits) {
    int i = blockIdx.x * blockDim.x + threadIdx.x;
    uint32_t bal = __ballot_sync(0xffffffffu, m[i] != 0);
    if ((threadIdx.x & 31) == 0) bits[i >> 5] = bal;
}

// ===========================================================================
// GEMM core: 128x64 tile, A single fp16, B hi/lo fp16 (2 mmas per k-step).
// KC=32, 2-stage, 1 barrier/chunk.
// ===========================================================================
#define GSTR 40
#define GA (128 * GSTR)                 // 5120 el
#define GB (64 * GSTR)                  // 2560 el
#define GBUFEL (GA + 2 * GB)            // 10240 el / stage
#define GEMM_SMEM_BYTES (2 * GBUFEL * 2)   // 40960 B

__device__ __forceinline__ void gemm_core(
    uint32_t sb, int tid, int lane, int w,
    const __half* __restrict__ A,
    const __half* __restrict__ Bh, const __half* __restrict__ Bl,
    int m0, int n0, float acc[8][4])
{
    const __half* srcA = A + (size_t)m0 * KDIM;
    const __half* srcB[2] = {Bh + (size_t)n0 * KDIM, Bl + (size_t)n0 * KDIM};

    auto issue = [&](int ch, int buf) {
        uint32_t dbase = sb + (uint32_t)buf * (GBUFEL * 2);
        #pragma unroll
        for (int i = 0; i < 4; i++) {
            int idx = tid + i * 256;            // 0..1023
            if (idx < 512) {
                int r = idx >> 2, c = idx & 3;
                cp16(dbase + r * (GSTR * 2) + c * 16,
                     srcA + (size_t)r * KDIM + ch * 32 + c * 8);
            } else {
                int j = idx - 512;              // 0..511
                int sp = j >> 8, r = (j >> 2) & 63, c = j & 3;
                cp16(dbase + (GA + sp * GB) * 2 + r * (GSTR * 2) + c * 16,
                     srcB[sp] + (size_t)r * KDIM + ch * 32 + c * 8);
            }
        }
        CP_COMMIT();
    };

    issue(0, 0);
    const int NC = KDIM / 32;
    for (int ch = 0; ch < NC; ch++) {
        CP_WAIT0();
        __syncthreads();
        if (ch + 1 < NC) issue(ch + 1, (ch + 1) & 1);

        uint32_t bb = sb + (uint32_t)(ch & 1) * (GBUFEL * 2);
        uint32_t tA = bb, tBh = bb + GA * 2, tBl = bb + (GA + GB) * 2;
        #pragma unroll
        for (int ks = 0; ks < 2; ks++) {
            uint32_t ao = (uint32_t)(w * 16 + (lane & 15)) * (GSTR * 2)
                        + ks * 32 + (lane >> 4) * 16;
            uint32_t a[4];
            ldm4(a, tA + ao);
            #pragma unroll
            for (int pp = 0; pp < 2; pp++) {
                uint32_t bo0 = (uint32_t)((2 * pp) * 16 + (lane & 15)) * (GSTR * 2)
                             + ks * 32 + (lane >> 4) * 16;
                uint32_t bo1 = bo0 + 16 * (GSTR * 2);
                uint32_t bh0[4], bh1[4], bl0[4], bl1[4];
                ldm4(bh0, tBh + bo0); ldm4(bh1, tBh + bo1);
                ldm4(bl0, tBl + bo0); ldm4(bl1, tBl + bo1);
                float* a0 = acc[4 * pp + 0];
                float* a1 = acc[4 * pp + 1];
                float* a2 = acc[4 * pp + 2];
                float* a3 = acc[4 * pp + 3];
                mma16816(a0, a, bh0[0], bh0[2]);
                mma16816(a1, a, bh0[1], bh0[3]);
                mma16816(a2, a, bh1[0], bh1[2]);
                mma16816(a3, a, bh1[1], bh1[3]);
                mma16816(a0, a, bl0[0], bl0[2]);
                mma16816(a1, a, bl0[1], bl0[3]);
                mma16816(a2, a, bl1[0], bl1[2]);
                mma16816(a3, a, bl1[1], bl1[3]);
            }
        }
    }
}

// Fused Q/K/V projections. z=0: Q single; z=1: K hi/lo; z=2: V^T hi/lo.
__global__ __launch_bounds__(256, 3) void gemm_qkv(
    const __half* __restrict__ A,
    const __half* __restrict__ Wth, const __half* __restrict__ Wtl,
    const float* __restrict__ bq, const float* __restrict__ bk,
    const float* __restrict__ bv,
    __half* __restrict__ q,
    __half* __restrict__ kh, __half* __restrict__ kl,
    __half* __restrict__ vth, __half* __restrict__ vtl)
{
    extern __shared__ __half sm[];
    uint32_t sb = smem_u32(sm);
    int tid = threadIdx.x, lane = tid & 31, w = tid >> 5;
    int m0 = blockIdx.y * 128, n0 = blockIdx.x * 64;
    int z = blockIdx.z;
    const size_t WSZ = (size_t)1024 * 1024;
    const __half* Bh = Wth + (size_t)z * WSZ;
    const __half* Bl = Wtl + (size_t)z * WSZ;
    const float* bias = (z == 0) ? bq : (z == 1) ? bk : bv;

    float acc[8][4];
    #pragma unroll
    for (int na = 0; na < 8; na++)
        #pragma unroll
        for (int j = 0; j < 4; j++) acc[na][j] = 0.0f;

    gemm_core(sb, tid, lane, w, A, Bh, Bl, m0, n0, acc);

    int r0 = m0 + w * 16 + (lane >> 2);
    #pragma unroll
    for (int na = 0; na < 8; na++) {
        int col = n0 + na * 8 + (lane & 3) * 2;
        float v0 = acc[na][0] + bias[col], v1 = acc[na][1] + bias[col + 1];
        float v2 = acc[na][2] + bias[col], v3 = acc[na][3] + bias[col + 1];
        if (z == 0) {
            *(uint32_t*)(q + (size_t)r0 * 1024 + col)       = packhf(v0, v1);
            *(uint32_t*)(q + (size_t)(r0 + 8) * 1024 + col) = packhf(v2, v3);
        } else if (z == 1) {
            __half h0, l0, h1, l1, h2, l2, h3, l3;
            split2h(v0, h0, l0); split2h(v1, h1, l1);
            split2h(v2, h2, l2); split2h(v3, h3, l3);
            *(uint32_t*)(kh + (size_t)r0 * 1024 + col)       = packh(h0, h1);
            *(uint32_t*)(kl + (size_t)r0 * 1024 + col)       = packh(l0, l1);
            *(uint32_t*)(kh + (size_t)(r0 + 8) * 1024 + col) = packh(h2, h3);
            *(uint32_t*)(kl + (size_t)(r0 + 8) * 1024 + col) = packh(l2, l3);
        } else {
            __half h0, l0, h1, l1, h2, l2, h3, l3;
            split2h(v0, h0, l0); split2h(v1, h1, l1);
            split2h(v2, h2, l2); split2h(v3, h3, l3);
            int bi = r0 >> 11, t = r0 & 2047;
            vth[((size_t)bi * 1024 + col) * 2048 + t] = h0;
            vtl[((size_t)bi * 1024 + col) * 2048 + t] = l0;
            vth[((size_t)bi * 1024 + col + 1) * 2048 + t] = h1;
            vtl[((size_t)bi * 1024 + col + 1) * 2048 + t] = l1;
            int r1 = r0 + 8, t1 = r1 & 2047; bi = r1 >> 11;
            vth[((size_t)bi * 1024 + col) * 2048 + t1] = h2;
            vtl[((size_t)bi * 1024 + col) * 2048 + t1] = l2;
            vth[((size_t)bi * 1024 + col + 1) * 2048 + t1] = h3;
            vtl[((size_t)bi * 1024 + col + 1) * 2048 + t1] = l3;
        }
    }
}

// Output projection: fp32 straight to d_out.
__global__ __launch_bounds__(256, 3) void gemm_out(
    const __half* __restrict__ A,
    const __half* __restrict__ Bh, const __half* __restrict__ Bl,
    const float* __restrict__ bias, float* __restrict__ outF)
{
    extern __shared__ __half sm[];
    uint32_t sb = smem_u32(sm);
    int tid = threadIdx.x, lane = tid & 31, w = tid >> 5;
    int m0 = blockIdx.y * 128, n0 = blockIdx.x * 64;

    float acc[8][4];
    #pragma unroll
    for (int na = 0; na < 8; na++)
        #pragma unroll
        for (int j = 0; j < 4; j++) acc[na][j] = 0.0f;

    gemm_core(sb, tid, lane, w, A, Bh, Bl, m0, n0, acc);

    int r0 = m0 + w * 16 + (lane >> 2);
    #pragma unroll
    for (int na = 0; na < 8; na++) {
        int col = n0 + na * 8 + (lane & 3) * 2;
        float b0 = bias[col], b1 = bias[col + 1];
        *(float2*)(outF + (size_t)r0 * 1024 + col) =
            make_float2(acc[na][0] + b0, acc[na][1] + b1);
        *(float2*)(outF + (size_t)(r0 + 8) * 1024 + col) =
            make_float2(acc[na][2] + b0, acc[na][3] + b1);
    }
}

// ===========================================================================
// Attention — FA-2, Q and P single fp16, K/V hi/lo (2 mmas per k-step)
// ===========================================================================
#define ASTR 72
#define AQ   (128 * ASTR)               // single Q
#define AKV  (64 * ASTR)
#define ATTN_SMEM_BYTES ((AQ + 8 * AKV) * 2)   // 92160 B

__global__ __launch_bounds__(256, 2) void attn_mma() {
    extern __shared__ __half sm[];
    uint32_t sb = smem_u32(sm);
    int tid = threadIdx.x, lane = tid & 31, w = tid >> 5;
    int q0 = blockIdx.x * 128;
    int b = blockIdx.y >> 4, hd = blockIdx.y & 15;

    uint32_t tQ = sb;
    const uint32_t kvb0 = sb + 2 * AQ;   // bytes

    // Q (single) joins cp group 0
    #pragma unroll
    for (int i = 0; i < 4; i++) {
        int idx = tid + i * 256;
        int row = idx >> 3, c = idx & 7;
        cp16(tQ + row * (ASTR * 2) + c * 16,
             g_q + (size_t)(b * Tt + q0 + row) * 1024 + hd * 64 + c * 8);
    }

    auto issueKV = [&](int kt, int buf) {
        uint32_t dbase = kvb0 + (uint32_t)buf * (4 * AKV * 2);
        int kv0 = kt * 64;
        #pragma unroll
        for (int i = 0; i < 8; i++) {
            int idx = tid + i * 256;
            int t = idx >> 9;
            int r = (idx >> 3) & 63, c = idx & 7;
            const __half* src;
            if (t == 0)      src = g_kh  + (size_t)(b * Tt + kv0 + r) * 1024 + hd * 64 + c * 8;
            else if (t == 1) src = g_kl  + (size_t)(b * Tt + kv0 + r) * 1024 + hd * 64 + c * 8;
            else if (t == 2) src = g_vth + (size_t)(b * 1024 + hd * 64 + r) * Tt + kv0 + c * 8;
            else             src = g_vtl + (size_t)(b * 1024 + hd * 64 + r) * Tt + kv0 + c * 8;
            cp16(dbase + t * (AKV * 2) + r * (ASTR * 2) + c * 16, src);
        }
        CP_COMMIT();
    };

    float o[8][4];
    #pragma unroll
    for (int t = 0; t < 8; t++)
        #pragma unroll
        for (int j = 0; j < 4; j++) o[t][j] = 0.0f;
    float lacc0 = 0.0f, lacc1 = 0.0f;

    int rowg = b * Tt + q0 + w * 16 + (lane >> 2);

    issueKV(0, 0);

    for (int kt = 0; kt < 32; kt++) {
        CP_WAIT0();
        __syncthreads();
        if (kt + 1 < 32) issueKV(kt + 1, (kt + 1) & 1);

        uint32_t kb = kvb0 + (uint32_t)(kt & 1) * (4 * AKV * 2);
        uint32_t tKh = kb, tKl = kb + AKV * 2;
        uint32_t tVh = kb + 2 * AKV * 2, tVl = kb + 3 * AKV * 2;

        // ---- S = Q @ (Kh + Kl)^T ----
        float s[8][4];
        #pragma unroll
        for (int t = 0; t < 8; t++)
            #pragma unroll
            for (int j = 0; j < 4; j++) s[t][j] = 0.0f;
        #pragma unroll
        for (int ks = 0; ks < 4; ks++) {
            uint32_t ao = (uint32_t)(w * 16 + (lane & 15)) * (ASTR * 2)
                        + ks * 32 + (lane >> 4) * 16;
            uint32_t q[4];
            ldm4(q, tQ + ao);
            #pragma unroll
            for (int pp = 0; pp < 2; pp++) {
                uint32_t bo0 = (uint32_t)((2 * pp) * 16 + (lane & 15)) * (ASTR * 2)
                             + ks * 32 + (lane >> 4) * 16;
                uint32_t bo1 = bo0 + 16 * (ASTR * 2);
                uint32_t kh0[4], kh1[4], kl0[4], kl1[4];
                ldm4(kh0, tKh + bo0); ldm4(kh1, tKh + bo1);
                ldm4(kl0, tKl + bo0); ldm4(kl1, tKl + bo1);
                float* s0 = s[4 * pp + 0];
                float* s1 = s[4 * pp + 1];
                float* s2 = s[4 * pp + 2];
                float* s3 = s[4 * pp + 3];
                mma16816(s0, q, kh0[0], kh0[2]);
                mma16816(s1, q, kh0[1], kh0[3]);
                mma16816(s2, q, kh1[0], kh1[2]);
                mma16816(s3, q, kh1[1], kh1[3]);
                mma16816(s0, q, kl0[0], kl0[2]);
                mma16816(s1, q, kl0[1], kl0[3]);
                mma16816(s2, q, kl1[0], kl1[2]);
                mma16816(s3, q, kl1[1], kl1[3]);
            }
        }

        // ---- softmax in registers, P single fp16 fragments ----
        uint32_t mw0 = g_mbits[(size_t)rowg * 64 + kt * 2];
        uint32_t mw1 = g_mbits[(size_t)rowg * 64 + kt * 2 + 1];
        uint32_t mw2 = g_mbits[(size_t)(rowg + 8) * 64 + kt * 2];
        uint32_t mw3 = g_mbits[(size_t)(rowg + 8) * 64 + kt * 2 + 1];

        uint32_t af[4][4];
        #pragma unroll
        for (int t = 0; t < 8; t++) {
            int cb = 8 * t + 2 * (lane & 3);
            uint32_t wa = (t < 4) ? mw0 : mw1;
            uint32_t wb = (t < 4) ? mw2 : mw3;
            int bit = cb & 31;
            float p0 = ((wa >> bit) & 1u)       ? __expf(s[t][0] * 0.125f) : 0.0f;
            float p1 = ((wa >> (bit + 1)) & 1u) ? __expf(s[t][1] * 0.125f) : 0.0f;
            float p2 = ((wb >> bit) & 1u)       ? __expf(s[t][2] * 0.125f) : 0.0f;
            float p3 = ((wb >> (bit + 1)) & 1u) ? __expf(s[t][3] * 0.125f) : 0.0f;
            lacc0 += p0 + p1;
            lacc1 += p2 + p3;
            int u = t >> 1, k = (t & 1) * 2;
            af[u][k]     = packhf(p0, p1);
            af[u][k + 1] = packhf(p2, p3);
        }

        // ---- O += P @ (Vh + Vl) ----
        #pragma unroll
        for (int u = 0; u < 4; u++) {
            #pragma unroll
            for (int pp = 0; pp < 2; pp++) {
                uint32_t bo0 = (uint32_t)((2 * pp) * 16 + (lane & 15)) * (ASTR * 2)
                             + u * 32 + (lane >> 4) * 16;
                uint32_t bo1 = bo0 + 16 * (ASTR * 2);
                uint32_t vh0[4], vh1[4], vl0[4], vl1[4];
                ldm4(vh0, tVh + bo0); ldm4(vh1, tVh + bo1);
                ldm4(vl0, tVl + bo0); ldm4(vl1, tVl + bo1);
                float* o0 = o[4 * pp + 0];
                float* o1 = o[4 * pp + 1];
                float* o2 = o[4 * pp + 2];
                float* o3 = o[4 * pp + 3];
                mma16816(o0, af[u], vh0[0], vh0[2]);
                mma16816(o1, af[u], vh0[1], vh0[3]);
                mma16816(o2, af[u], vh1[0], vh1[2]);
                mma16816(o3, af[u], vh1[1], vh1[3]);
                mma16816(o0, af[u], vl0[0], vl0[2]);
                mma16816(o1, af[u], vl0[1], vl0[3]);
                mma16816(o2, af[u], vl1[0], vl1[2]);
                mma16816(o3, af[u], vl1[1], vl1[3]);
            }
        }
    }

    lacc0 += __shfl_xor_sync(0xffffffffu, lacc0, 1);
    lacc0 += __shfl_xor_sync(0xffffffffu, lacc0, 2);
    lacc1 += __shfl_xor_sync(0xffffffffu, lacc1, 1);
    lacc1 += __shfl_xor_sync(0xffffffffu, lacc1, 2);
    float inv0 = 1.0f / lacc0, inv1 = 1.0f / lacc1;

    int row = q0 + w * 16 + (lane >> 2);
    #pragma unroll
    for (int t = 0; t < 8; t++) {
        int col = hd * 64 + 8 * t + 2 * (lane & 3);
        size_t o0 = (size_t)(b * Tt + row) * 1024 + col;
        size_t o1 = (size_t)(b * Tt + row + 8) * 1024 + col;
        *(uint32_t*)(g_z + o0) = packhf(o[t][0] * inv0, o[t][1] * inv0);
        *(uint32_t*)(g_z + o1) = packhf(o[t][2] * inv1, o[t][3] * inv1);
    }
}

// ===========================================================================
extern "C" void kernel_launch(void* const* d_in, const int* in_sizes, int n_in,
                              void* d_out, int out_size)
{
    const float* embed = (const float*)d_in[0];
    const int*   mask  = (const int*)d_in[1];
    const float* Wq = (const float*)d_in[2];
    const float* bq = (const float*)d_in[3];
    const float* Wk = (const float*)d_in[4];
    const float* bk = (const float*)d_in[5];
    const float* Wv = (const float*)d_in[6];
    const float* bv = (const float*)d_in[7];
    const float* Wz = (const float*)d_in[8];
    const float* bz = (const float*)d_in[9];
    float* out = (float*)d_out;

    __half *e, *wh, *wl, *q, *kh, *kl, *vth, *vtl, *z;
    uint32_t* mbits;
    cudaGetSymbolAddress((void**)&e, g_e);
    cudaGetSymbolAddress((void**)&wh, g_wh);   cudaGetSymbolAddress((void**)&wl, g_wl);
    cudaGetSymbolAddress((void**)&q, g_q);
    cudaGetSymbolAddress((void**)&kh, g_kh);   cudaGetSymbolAddress((void**)&kl, g_kl);
    cudaGetSymbolAddress((void**)&vth, g_vth); cudaGetSymbolAddress((void**)&vtl, g_vtl);
    cudaGetSymbolAddress((void**)&z, g_z);
    cudaGetSymbolAddress((void**)&mbits, g_mbits);

    cudaFuncSetAttribute(gemm_qkv, cudaFuncAttributeMaxDynamicSharedMemorySize,
                         GEMM_SMEM_BYTES);
    cudaFuncSetAttribute(gemm_out, cudaFuncAttributeMaxDynamicSharedMemorySize,
                         GEMM_SMEM_BYTES);
    cudaFuncSetAttribute(attn_mma, cudaFuncAttributeMaxDynamicSharedMemorySize,
                         ATTN_SMEM_BYTES);

    const size_t WSZ = (size_t)1024 * 1024;

    // Preps
    conv_f16<<<(Mtot * KDIM / 4 + 255) / 256, 256>>>(embed, e, Mtot * KDIM / 4);
    dim3 tb(32, 8), tg4(32, 32, 4);
    trans_split4<<<tg4, tb>>>(Wq, Wk, Wv, Wz, wh, wl);
    pack_mask<<<(Bb * Tt * Tt) / 256, 256>>>(mask, mbits);

    // Fused Q/K/V projections
    gemm_qkv<<<dim3(16, 32, 3), 256, GEMM_SMEM_BYTES>>>(
        e, wh, wl, bq, bk, bv, q, kh, kl, vth, vtl);

    // Attention
    attn_mma<<<dim3(16, 32), 256, ATTN_SMEM_BYTES>>>();

    // Output projection -> d_out (fp32)
    gemm_out<<<dim3(16, 32), 256, GEMM_SMEM_BYTES>>>(
        z, wh + 3 * WSZ, wl + 3 * WSZ, bz, out);
}

// round 10
// speedup vs baseline: 5.4930x; 1.6122x over previous
#include <cuda_runtime.h>
#include <cuda_fp16.h>
#include <cstdint>
#include <math.h>

#define Bb 2
#define Tt 2048
#define Hh 16
#define Mtot 4096
#define KDIM 1024

// ===========================================================================
// Helpers
// ===========================================================================
__device__ __forceinline__ uint32_t smem_u32(const void* p) {
    uint32_t a;
    asm("{ .reg .u64 t; cvta.to.shared.u64 t, %1; cvt.u32.u64 %0, t; }"
        : "=r"(a) : "l"(p));
    return a;
}
__device__ __forceinline__ void cp16(uint32_t dst, const void* src) {
    asm volatile("cp.async.cg.shared.global [%0], [%1], 16;" :: "r"(dst), "l"(src));
}
#define CP_COMMIT() asm volatile("cp.async.commit_group;" ::: "memory")
#define CP_WAIT0()  asm volatile("cp.async.wait_group 0;" ::: "memory")

__device__ __forceinline__ void ldm4(uint32_t* r, uint32_t a) {
    asm volatile("ldmatrix.sync.aligned.m8n8.x4.shared.b16 {%0,%1,%2,%3}, [%4];"
        : "=r"(r[0]), "=r"(r[1]), "=r"(r[2]), "=r"(r[3]) : "r"(a));
}
__device__ __forceinline__ void mma16816(float* d, const uint32_t* a,
                                         uint32_t b0, uint32_t b1) {
    asm volatile("mma.sync.aligned.m16n8k16.row.col.f32.f16.f16.f32 "
        "{%0,%1,%2,%3}, {%4,%5,%6,%7}, {%8,%9}, {%0,%1,%2,%3};"
        : "+f"(d[0]), "+f"(d[1]), "+f"(d[2]), "+f"(d[3])
        : "r"(a[0]), "r"(a[1]), "r"(a[2]), "r"(a[3]), "r"(b0), "r"(b1));
}

__device__ __forceinline__ uint32_t packhf(float a, float b) {
    __half2 t; t.x = __float2half(a); t.y = __float2half(b);
    return *(uint32_t*)&t;
}

// ===========================================================================
// Scratch (device globals) — everything single fp16
// ===========================================================================
__device__ __half g_e[(size_t)Mtot * KDIM];                 // embed
__device__ __half g_w[(size_t)4 * 1024 * 1024];             // W^T x4
__device__ __half g_q[(size_t)Mtot * KDIM];                 // Q
__device__ __half g_k[(size_t)Mtot * KDIM];                 // K
__device__ __half g_vt[(size_t)Mtot * KDIM];                // V^T [b][n][t]
__device__ __half g_z[(size_t)Mtot * KDIM];                 // Z
__device__ uint32_t g_mbits[(size_t)Bb * Tt * (Tt / 32)];

// ===========================================================================
// Prep kernels
// ===========================================================================
__global__ void conv_f16(const float* __restrict__ x, __half* __restrict__ o, int n4) {
    int i = blockIdx.x * blockDim.x + threadIdx.x;
    if (i >= n4) return;
    float4 v = ((const float4*)x)[i];
    ((uint32_t*)o)[2 * i]     = packhf(v.x, v.y);
    ((uint32_t*)o)[2 * i + 1] = packhf(v.z, v.w);
}

// 4 weight matrices W[K,N] -> WT[N,K] fp16
__global__ void trans4(const float* __restrict__ W0, const float* __restrict__ W1,
                       const float* __restrict__ W2, const float* __restrict__ W3,
                       __half* __restrict__ T) {
    __shared__ float t[32][33];
    const float* W = (blockIdx.z == 0) ? W0 : (blockIdx.z == 1) ? W1
                   : (blockIdx.z == 2) ? W2 : W3;
    size_t dbase = (size_t)blockIdx.z * 1024 * 1024;
    int tx = threadIdx.x, ty = threadIdx.y;
    int x0 = blockIdx.x * 32, y0 = blockIdx.y * 32;
    #pragma unroll
    for (int i = 0; i < 32; i += 8)
        t[ty + i][tx] = W[(size_t)(y0 + ty + i) * 1024 + x0 + tx];
    __syncthreads();
    #pragma unroll
    for (int i = 0; i < 32; i += 8) {
        float v = t[tx][ty + i];
        T[dbase + (size_t)(x0 + ty + i) * 1024 + y0 + tx] = __float2half(v);
    }
}

__global__ void pack_mask(const int* __restrict__ m, uint32_t* __restrict__ bits) {
    int i = blockIdx.x * blockDim.x + threadIdx.x;
    uint32_t bal = __ballot_sync(0xffffffffu, m[i] != 0);
    if ((threadIdx.x & 31) == 0) bits[i >> 5] = bal;
}

// ===========================================================================
// GEMM core: 128x64 tile, single fp16 A and B. KC=32, 2-stage, 1 barrier.
// ===========================================================================
#define GSTR 40
#define GA (128 * GSTR)                 // 5120 el
#define GB (64 * GSTR)                  // 2560 el
#define GBUFEL (GA + GB)                // 7680 el / stage
#define GEMM_SMEM_BYTES (2 * GBUFEL * 2)   // 30720 B

__device__ __forceinline__ void gemm_core(
    uint32_t sb, int tid, int lane, int w,
    const __half* __restrict__ A, const __half* __restrict__ B,
    int m0, int n0, float acc[8][4])
{
    const __half* srcA = A + (size_t)m0 * KDIM;
    const __half* srcB = B + (size_t)n0 * KDIM;

    auto issue = [&](int ch, int buf) {
        uint32_t dbase = sb + (uint32_t)buf * (GBUFEL * 2);
        #pragma unroll
        for (int i = 0; i < 3; i++) {
            int idx = tid + i * 256;            // 0..767
            if (idx < 512) {
                int r = idx >> 2, c = idx & 3;
                cp16(dbase + r * (GSTR * 2) + c * 16,
                     srcA + (size_t)r * KDIM + ch * 32 + c * 8);
            } else {
                int j = idx - 512;              // 0..255
                int r = j >> 2, c = j & 3;
                cp16(dbase + GA * 2 + r * (GSTR * 2) + c * 16,
                     srcB + (size_t)r * KDIM + ch * 32 + c * 8);
            }
        }
        CP_COMMIT();
    };

    issue(0, 0);
    const int NC = KDIM / 32;
    for (int ch = 0; ch < NC; ch++) {
        CP_WAIT0();
        __syncthreads();
        if (ch + 1 < NC) issue(ch + 1, (ch + 1) & 1);

        uint32_t bb = sb + (uint32_t)(ch & 1) * (GBUFEL * 2);
        uint32_t tA = bb, tB = bb + GA * 2;
        #pragma unroll
        for (int ks = 0; ks < 2; ks++) {
            uint32_t ao = (uint32_t)(w * 16 + (lane & 15)) * (GSTR * 2)
                        + ks * 32 + (lane >> 4) * 16;
            uint32_t a[4];
            ldm4(a, tA + ao);
            #pragma unroll
            for (int pp = 0; pp < 2; pp++) {
                uint32_t bo0 = (uint32_t)((2 * pp) * 16 + (lane & 15)) * (GSTR * 2)
                             + ks * 32 + (lane >> 4) * 16;
                uint32_t bo1 = bo0 + 16 * (GSTR * 2);
                uint32_t b0[4], b1[4];
                ldm4(b0, tB + bo0); ldm4(b1, tB + bo1);
                mma16816(acc[4 * pp + 0], a, b0[0], b0[2]);
                mma16816(acc[4 * pp + 1], a, b0[1], b0[3]);
                mma16816(acc[4 * pp + 2], a, b1[0], b1[2]);
                mma16816(acc[4 * pp + 3], a, b1[1], b1[3]);
            }
        }
    }
}

// Fused Q/K/V projections. z=0: Q; z=1: K; z=2: V^T.
__global__ __launch_bounds__(256, 3) void gemm_qkv(
    const __half* __restrict__ A, const __half* __restrict__ Wt,
    const float* __restrict__ bq, const float* __restrict__ bk,
    const float* __restrict__ bv,
    __half* __restrict__ q, __half* __restrict__ k, __half* __restrict__ vt)
{
    extern __shared__ __half sm[];
    uint32_t sb = smem_u32(sm);
    int tid = threadIdx.x, lane = tid & 31, w = tid >> 5;
    int m0 = blockIdx.y * 128, n0 = blockIdx.x * 64;
    int z = blockIdx.z;
    const size_t WSZ = (size_t)1024 * 1024;
    const __half* B = Wt + (size_t)z * WSZ;
    const float* bias = (z == 0) ? bq : (z == 1) ? bk : bv;

    float acc[8][4];
    #pragma unroll
    for (int na = 0; na < 8; na++)
        #pragma unroll
        for (int j = 0; j < 4; j++) acc[na][j] = 0.0f;

    gemm_core(sb, tid, lane, w, A, B, m0, n0, acc);

    int r0 = m0 + w * 16 + (lane >> 2);
    #pragma unroll
    for (int na = 0; na < 8; na++) {
        int col = n0 + na * 8 + (lane & 3) * 2;
        float v0 = acc[na][0] + bias[col], v1 = acc[na][1] + bias[col + 1];
        float v2 = acc[na][2] + bias[col], v3 = acc[na][3] + bias[col + 1];
        if (z == 0 || z == 1) {
            __half* O = (z == 0) ? q : k;
            *(uint32_t*)(O + (size_t)r0 * 1024 + col)       = packhf(v0, v1);
            *(uint32_t*)(O + (size_t)(r0 + 8) * 1024 + col) = packhf(v2, v3);
        } else {
            int bi = r0 >> 11, t = r0 & 2047;
            vt[((size_t)bi * 1024 + col) * 2048 + t]     = __float2half(v0);
            vt[((size_t)bi * 1024 + col + 1) * 2048 + t] = __float2half(v1);
            int r1 = r0 + 8, t1 = r1 & 2047; bi = r1 >> 11;
            vt[((size_t)bi * 1024 + col) * 2048 + t1]     = __float2half(v2);
            vt[((size_t)bi * 1024 + col + 1) * 2048 + t1] = __float2half(v3);
        }
    }
}

// Output projection: fp32 straight to d_out.
__global__ __launch_bounds__(256, 3) void gemm_out(
    const __half* __restrict__ A, const __half* __restrict__ B,
    const float* __restrict__ bias, float* __restrict__ outF)
{
    extern __shared__ __half sm[];
    uint32_t sb = smem_u32(sm);
    int tid = threadIdx.x, lane = tid & 31, w = tid >> 5;
    int m0 = blockIdx.y * 128, n0 = blockIdx.x * 64;

    float acc[8][4];
    #pragma unroll
    for (int na = 0; na < 8; na++)
        #pragma unroll
        for (int j = 0; j < 4; j++) acc[na][j] = 0.0f;

    gemm_core(sb, tid, lane, w, A, B, m0, n0, acc);

    int r0 = m0 + w * 16 + (lane >> 2);
    #pragma unroll
    for (int na = 0; na < 8; na++) {
        int col = n0 + na * 8 + (lane & 3) * 2;
        float b0 = bias[col], b1 = bias[col + 1];
        *(float2*)(outF + (size_t)r0 * 1024 + col) =
            make_float2(acc[na][0] + b0, acc[na][1] + b1);
        *(float2*)(outF + (size_t)(r0 + 8) * 1024 + col) =
            make_float2(acc[na][2] + b0, acc[na][3] + b1);
    }
}

// ===========================================================================
// Attention — FA-2, all operands single fp16
// ===========================================================================
#define ASTR 72
#define AQ   (128 * ASTR)               // 9216 el
#define AKV  (64 * ASTR)                // 4608 el
#define ATTN_SMEM_BYTES ((AQ + 4 * AKV) * 2)   // 55296 B

__global__ __launch_bounds__(256, 2) void attn_mma() {
    extern __shared__ __half sm[];
    uint32_t sb = smem_u32(sm);
    int tid = threadIdx.x, lane = tid & 31, w = tid >> 5;
    int q0 = blockIdx.x * 128;
    int b = blockIdx.y >> 4, hd = blockIdx.y & 15;

    uint32_t tQ = sb;
    const uint32_t kvb0 = sb + 2 * AQ;   // bytes

    // Q joins cp group 0 — FULL rows: 128 rows x 8 cp16 = 1024 cps
    #pragma unroll
    for (int i = 0; i < 4; i++) {
        int idx = tid + i * 256;            // 0..1023
        int row = idx >> 3, c = idx & 7;
        cp16(tQ + row * (ASTR * 2) + c * 16,
             g_q + (size_t)(b * Tt + q0 + row) * 1024 + hd * 64 + c * 8);
    }

    auto issueKV = [&](int kt, int buf) {
        uint32_t dbase = kvb0 + (uint32_t)buf * (2 * AKV * 2);
        int kv0 = kt * 64;
        // K tile + V tile: 2 x 64 rows x 8 cp16 = 1024 cps
        #pragma unroll
        for (int i = 0; i < 4; i++) {
            int idx = tid + i * 256;        // 0..1023
            int t = idx >> 9;               // 0:K 1:V
            int r = (idx >> 3) & 63, c = idx & 7;
            const __half* src = (t == 0)
                ? g_k  + (size_t)(b * Tt + kv0 + r) * 1024 + hd * 64 + c * 8
                : g_vt + (size_t)(b * 1024 + hd * 64 + r) * Tt + kv0 + c * 8;
            cp16(dbase + t * (AKV * 2) + r * (ASTR * 2) + c * 16, src);
        }
        CP_COMMIT();
    };

    float o[8][4];
    #pragma unroll
    for (int t = 0; t < 8; t++)
        #pragma unroll
        for (int j = 0; j < 4; j++) o[t][j] = 0.0f;
    float lacc0 = 0.0f, lacc1 = 0.0f;

    int rowg = b * Tt + q0 + w * 16 + (lane >> 2);

    issueKV(0, 0);

    for (int kt = 0; kt < 32; kt++) {
        CP_WAIT0();
        __syncthreads();
        if (kt + 1 < 32) issueKV(kt + 1, (kt + 1) & 1);

        uint32_t kb = kvb0 + (uint32_t)(kt & 1) * (2 * AKV * 2);
        uint32_t tK = kb, tV = kb + AKV * 2;

        // ---- S = Q @ K^T ----
        float s[8][4];
        #pragma unroll
        for (int t = 0; t < 8; t++)
            #pragma unroll
            for (int j = 0; j < 4; j++) s[t][j] = 0.0f;
        #pragma unroll
        for (int ks = 0; ks < 4; ks++) {
            uint32_t ao = (uint32_t)(w * 16 + (lane & 15)) * (ASTR * 2)
                        + ks * 32 + (lane >> 4) * 16;
            uint32_t q[4];
            ldm4(q, tQ + ao);
            #pragma unroll
            for (int pp = 0; pp < 2; pp++) {
                uint32_t bo0 = (uint32_t)((2 * pp) * 16 + (lane & 15)) * (ASTR * 2)
                             + ks * 32 + (lane >> 4) * 16;
                uint32_t bo1 = bo0 + 16 * (ASTR * 2);
                uint32_t k0[4], k1[4];
                ldm4(k0, tK + bo0); ldm4(k1, tK + bo1);
                mma16816(s[4 * pp + 0], q, k0[0], k0[2]);
                mma16816(s[4 * pp + 1], q, k0[1], k0[3]);
                mma16816(s[4 * pp + 2], q, k1[0], k1[2]);
                mma16816(s[4 * pp + 3], q, k1[1], k1[3]);
            }
        }

        // ---- softmax in registers, P fp16 fragments ----
        uint32_t mw0 = g_mbits[(size_t)rowg * 64 + kt * 2];
        uint32_t mw1 = g_mbits[(size_t)rowg * 64 + kt * 2 + 1];
        uint32_t mw2 = g_mbits[(size_t)(rowg + 8) * 64 + kt * 2];
        uint32_t mw3 = g_mbits[(size_t)(rowg + 8) * 64 + kt * 2 + 1];

        uint32_t af[4][4];
        #pragma unroll
        for (int t = 0; t < 8; t++) {
            int cb = 8 * t + 2 * (lane & 3);
            uint32_t wa = (t < 4) ? mw0 : mw1;
            uint32_t wb = (t < 4) ? mw2 : mw3;
            int bit = cb & 31;
            float p0 = ((wa >> bit) & 1u)       ? __expf(s[t][0] * 0.125f) : 0.0f;
            float p1 = ((wa >> (bit + 1)) & 1u) ? __expf(s[t][1] * 0.125f) : 0.0f;
            float p2 = ((wb >> bit) & 1u)       ? __expf(s[t][2] * 0.125f) : 0.0f;
            float p3 = ((wb >> (bit + 1)) & 1u) ? __expf(s[t][3] * 0.125f) : 0.0f;
            lacc0 += p0 + p1;
            lacc1 += p2 + p3;
            int u = t >> 1, k = (t & 1) * 2;
            af[u][k]     = packhf(p0, p1);
            af[u][k + 1] = packhf(p2, p3);
        }

        // ---- O += P @ V ----
        #pragma unroll
        for (int u = 0; u < 4; u++) {
            #pragma unroll
            for (int pp = 0; pp < 2; pp++) {
                uint32_t bo0 = (uint32_t)((2 * pp) * 16 + (lane & 15)) * (ASTR * 2)
                             + u * 32 + (lane >> 4) * 16;
                uint32_t bo1 = bo0 + 16 * (ASTR * 2);
                uint32_t v0[4], v1[4];
                ldm4(v0, tV + bo0); ldm4(v1, tV + bo1);
                mma16816(o[4 * pp + 0], af[u], v0[0], v0[2]);
                mma16816(o[4 * pp + 1], af[u], v0[1], v0[3]);
                mma16816(o[4 * pp + 2], af[u], v1[0], v1[2]);
                mma16816(o[4 * pp + 3], af[u], v1[1], v1[3]);
            }
        }
    }

    lacc0 += __shfl_xor_sync(0xffffffffu, lacc0, 1);
    lacc0 += __shfl_xor_sync(0xffffffffu, lacc0, 2);
    lacc1 += __shfl_xor_sync(0xffffffffu, lacc1, 1);
    lacc1 += __shfl_xor_sync(0xffffffffu, lacc1, 2);
    float inv0 = 1.0f / lacc0, inv1 = 1.0f / lacc1;

    int row = q0 + w * 16 + (lane >> 2);
    #pragma unroll
    for (int t = 0; t < 8; t++) {
        int col = hd * 64 + 8 * t + 2 * (lane & 3);
        size_t o0 = (size_t)(b * Tt + row) * 1024 + col;
        size_t o1 = (size_t)(b * Tt + row + 8) * 1024 + col;
        *(uint32_t*)(g_z + o0) = packhf(o[t][0] * inv0, o[t][1] * inv0);
        *(uint32_t*)(g_z + o1) = packhf(o[t][2] * inv1, o[t][3] * inv1);
    }
}

// ===========================================================================
extern "C" void kernel_launch(void* const* d_in, const int* in_sizes, int n_in,
                              void* d_out, int out_size)
{
    const float* embed = (const float*)d_in[0];
    const int*   mask  = (const int*)d_in[1];
    const float* Wq = (const float*)d_in[2];
    const float* bq = (const float*)d_in[3];
    const float* Wk = (const float*)d_in[4];
    const float* bk = (const float*)d_in[5];
    const float* Wv = (const float*)d_in[6];
    const float* bv = (const float*)d_in[7];
    const float* Wz = (const float*)d_in[8];
    const float* bz = (const float*)d_in[9];
    float* out = (float*)d_out;

    __half *e, *wt, *q, *k, *vt, *z;
    uint32_t* mbits;
    cudaGetSymbolAddress((void**)&e, g_e);
    cudaGetSymbolAddress((void**)&wt, g_w);
    cudaGetSymbolAddress((void**)&q, g_q);
    cudaGetSymbolAddress((void**)&k, g_k);
    cudaGetSymbolAddress((void**)&vt, g_vt);
    cudaGetSymbolAddress((void**)&z, g_z);
    cudaGetSymbolAddress((void**)&mbits, g_mbits);

    cudaFuncSetAttribute(gemm_qkv, cudaFuncAttributeMaxDynamicSharedMemorySize,
                         GEMM_SMEM_BYTES);
    cudaFuncSetAttribute(gemm_out, cudaFuncAttributeMaxDynamicSharedMemorySize,
                         GEMM_SMEM_BYTES);
    cudaFuncSetAttribute(attn_mma, cudaFuncAttributeMaxDynamicSharedMemorySize,
                         ATTN_SMEM_BYTES);

    const size_t WSZ = (size_t)1024 * 1024;

    // Preps
    conv_f16<<<(Mtot * KDIM / 4 + 255) / 256, 256>>>(embed, e, Mtot * KDIM / 4);
    dim3 tb(32, 8), tg4(32, 32, 4);
    trans4<<<tg4, tb>>>(Wq, Wk, Wv, Wz, wt);
    pack_mask<<<(Bb * Tt * Tt) / 256, 256>>>(mask, mbits);

    // Fused Q/K/V projections
    gemm_qkv<<<dim3(16, 32, 3), 256, GEMM_SMEM_BYTES>>>(
        e, wt, bq, bk, bv, q, k, vt);

    // Attention
    attn_mma<<<dim3(16, 32), 256, ATTN_SMEM_BYTES>>>();

    // Output projection -> d_out (fp32)
    gemm_out<<<dim3(16, 32), 256, GEMM_SMEM_BYTES>>>(
        z, wt + 3 * WSZ, bz, out);
}

// round 11
// speedup vs baseline: 5.8471x; 1.0645x over previous
#include <cuda_runtime.h>
#include <cuda_fp16.h>
#include <cstdint>
#include <math.h>

#define Bb 2
#define Tt 2048
#define Hh 16
#define Mtot 4096
#define KDIM 1024

// ===========================================================================
// Helpers
// ===========================================================================
__device__ __forceinline__ uint32_t smem_u32(const void* p) {
    uint32_t a;
    asm("{ .reg .u64 t; cvta.to.shared.u64 t, %1; cvt.u32.u64 %0, t; }"
        : "=r"(a) : "l"(p));
    return a;
}
__device__ __forceinline__ void cp16(uint32_t dst, const void* src) {
    asm volatile("cp.async.cg.shared.global [%0], [%1], 16;" :: "r"(dst), "l"(src));
}
#define CP_COMMIT() asm volatile("cp.async.commit_group;" ::: "memory")
#define CP_WAIT0()  asm volatile("cp.async.wait_group 0;" ::: "memory")

__device__ __forceinline__ void ldm4(uint32_t* r, uint32_t a) {
    asm volatile("ldmatrix.sync.aligned.m8n8.x4.shared.b16 {%0,%1,%2,%3}, [%4];"
        : "=r"(r[0]), "=r"(r[1]), "=r"(r[2]), "=r"(r[3]) : "r"(a));
}
__device__ __forceinline__ void mma16816(float* d, const uint32_t* a,
                                         uint32_t b0, uint32_t b1) {
    asm volatile("mma.sync.aligned.m16n8k16.row.col.f32.f16.f16.f32 "
        "{%0,%1,%2,%3}, {%4,%5,%6,%7}, {%8,%9}, {%0,%1,%2,%3};"
        : "+f"(d[0]), "+f"(d[1]), "+f"(d[2]), "+f"(d[3])
        : "r"(a[0]), "r"(a[1]), "r"(a[2]), "r"(a[3]), "r"(b0), "r"(b1));
}

__device__ __forceinline__ uint32_t packhf(float a, float b) {
    __half2 t; t.x = __float2half(a); t.y = __float2half(b);
    return *(uint32_t*)&t;
}

// ===========================================================================
// Scratch (device globals) — everything single fp16
// ===========================================================================
__device__ __half g_e[(size_t)Mtot * KDIM];                 // embed
__device__ __half g_w[(size_t)4 * 1024 * 1024];             // W^T x4
__device__ __half g_q[(size_t)Mtot * KDIM];                 // Q
__device__ __half g_k[(size_t)Mtot * KDIM];                 // K
__device__ __half g_vt[(size_t)Mtot * KDIM];                // V^T [b][n][t]
__device__ __half g_z[(size_t)Mtot * KDIM];                 // Z
__device__ uint32_t g_mbits[(size_t)Bb * Tt * (Tt / 32)];

// ===========================================================================
// Prep kernels
// ===========================================================================
__global__ void conv_f16(const float* __restrict__ x, __half* __restrict__ o, int n4) {
    int i = blockIdx.x * blockDim.x + threadIdx.x;
    if (i >= n4) return;
    float4 v = ((const float4*)x)[i];
    ((uint32_t*)o)[2 * i]     = packhf(v.x, v.y);
    ((uint32_t*)o)[2 * i + 1] = packhf(v.z, v.w);
}

__global__ void trans4(const float* __restrict__ W0, const float* __restrict__ W1,
                       const float* __restrict__ W2, const float* __restrict__ W3,
                       __half* __restrict__ T) {
    __shared__ float t[32][33];
    const float* W = (blockIdx.z == 0) ? W0 : (blockIdx.z == 1) ? W1
                   : (blockIdx.z == 2) ? W2 : W3;
    size_t dbase = (size_t)blockIdx.z * 1024 * 1024;
    int tx = threadIdx.x, ty = threadIdx.y;
    int x0 = blockIdx.x * 32, y0 = blockIdx.y * 32;
    #pragma unroll
    for (int i = 0; i < 32; i += 8)
        t[ty + i][tx] = W[(size_t)(y0 + ty + i) * 1024 + x0 + tx];
    __syncthreads();
    #pragma unroll
    for (int i = 0; i < 32; i += 8) {
        float v = t[tx][ty + i];
        T[dbase + (size_t)(x0 + ty + i) * 1024 + y0 + tx] = __float2half(v);
    }
}

__global__ void pack_mask(const int* __restrict__ m, uint32_t* __restrict__ bits) {
    int i = blockIdx.x * blockDim.x + threadIdx.x;
    uint32_t bal = __ballot_sync(0xffffffffu, m[i] != 0);
    if ((threadIdx.x & 31) == 0) bits[i >> 5] = bal;
}

// ===========================================================================
// GEMM core: 128x128 CTA tile, 8 warps (4m x 2n), warp tile 32x64.
// KC=64, 2-stage, 1 barrier/chunk. 16 mmas per 6 ldmatrix per k-step.
// ===========================================================================
#define GSTR2 72                         // smem row stride (halfs): 64 + 8 pad
#define GAEL (128 * GSTR2)               // 9216 el per operand tile
#define GSTAGE (2 * GAEL)                // 18432 el per stage
#define GEMM_SMEM_BYTES (2 * GSTAGE * 2) // 73728 B

__device__ __forceinline__ void gemm_core(
    uint32_t sb, int tid, int lane, int wm, int wn,
    const __half* __restrict__ A, const __half* __restrict__ B,
    int m0, int n0, float acc[2][8][4])
{
    const __half* srcA = A + (size_t)m0 * KDIM;
    const __half* srcB = B + (size_t)n0 * KDIM;

    auto issue = [&](int ch, int buf) {
        uint32_t dbase = sb + (uint32_t)buf * (GSTAGE * 2);
        #pragma unroll
        for (int i = 0; i < 8; i++) {
            int idx = tid + i * 256;            // 0..2047
            int t = idx >> 10;                  // 0:A 1:B
            int r = (idx >> 3) & 127, c = idx & 7;
            const __half* src = (t ? srcB : srcA) + (size_t)r * KDIM + ch * 64 + c * 8;
            cp16(dbase + t * (GAEL * 2) + r * (GSTR2 * 2) + c * 16, src);
        }
        CP_COMMIT();
    };

    issue(0, 0);
    const int NC = KDIM / 64;   // 16
    for (int ch = 0; ch < NC; ch++) {
        CP_WAIT0();
        __syncthreads();
        if (ch + 1 < NC) issue(ch + 1, (ch + 1) & 1);

        uint32_t bb = sb + (uint32_t)(ch & 1) * (GSTAGE * 2);
        uint32_t tA = bb, tB = bb + GAEL * 2;
        #pragma unroll
        for (int ks = 0; ks < 4; ks++) {
            uint32_t ao = (uint32_t)(wm * 32 + (lane & 15)) * (GSTR2 * 2)
                        + ks * 32 + (lane >> 4) * 16;
            uint32_t a0[4], a1[4];
            ldm4(a0, tA + ao);
            ldm4(a1, tA + ao + 16 * (GSTR2 * 2));
            #pragma unroll
            for (int p = 0; p < 4; p++) {
                uint32_t bo = (uint32_t)(wn * 64 + p * 16 + (lane & 15)) * (GSTR2 * 2)
                            + ks * 32 + (lane >> 4) * 16;
                uint32_t bf[4];
                ldm4(bf, tB + bo);
                mma16816(acc[0][2 * p],     a0, bf[0], bf[2]);
                mma16816(acc[0][2 * p + 1], a0, bf[1], bf[3]);
                mma16816(acc[1][2 * p],     a1, bf[0], bf[2]);
                mma16816(acc[1][2 * p + 1], a1, bf[1], bf[3]);
            }
        }
    }
}

// Fused Q/K/V projections. z=0: Q; z=1: K; z=2: V^T.
__global__ __launch_bounds__(256, 2) void gemm_qkv(
    const __half* __restrict__ A, const __half* __restrict__ Wt,
    const float* __restrict__ bq, const float* __restrict__ bk,
    const float* __restrict__ bv,
    __half* __restrict__ q, __half* __restrict__ k, __half* __restrict__ vt)
{
    extern __shared__ __half sm[];
    uint32_t sb = smem_u32(sm);
    int tid = threadIdx.x, lane = tid & 31, w = tid >> 5;
    int wm = w & 3, wn = w >> 2;
    int m0 = blockIdx.y * 128, n0 = blockIdx.x * 128;
    int z = blockIdx.z;
    const size_t WSZ = (size_t)1024 * 1024;
    const __half* B = Wt + (size_t)z * WSZ;
    const float* bias = (z == 0) ? bq : (z == 1) ? bk : bv;

    float acc[2][8][4];
    #pragma unroll
    for (int mf = 0; mf < 2; mf++)
        #pragma unroll
        for (int na = 0; na < 8; na++)
            #pragma unroll
            for (int j = 0; j < 4; j++) acc[mf][na][j] = 0.0f;

    gemm_core(sb, tid, lane, wm, wn, A, B, m0, n0, acc);

    #pragma unroll
    for (int mf = 0; mf < 2; mf++)
    #pragma unroll
    for (int na = 0; na < 8; na++) {
        int col = n0 + wn * 64 + na * 8 + (lane & 3) * 2;
        int rbase = m0 + wm * 32 + mf * 16 + (lane >> 2);
        float v0 = acc[mf][na][0] + bias[col], v1 = acc[mf][na][1] + bias[col + 1];
        float v2 = acc[mf][na][2] + bias[col], v3 = acc[mf][na][3] + bias[col + 1];
        if (z == 0 || z == 1) {
            __half* O = (z == 0) ? q : k;
            *(uint32_t*)(O + (size_t)rbase * 1024 + col)       = packhf(v0, v1);
            *(uint32_t*)(O + (size_t)(rbase + 8) * 1024 + col) = packhf(v2, v3);
        } else {
            int bi = rbase >> 11, t = rbase & 2047;
            vt[((size_t)bi * 1024 + col) * 2048 + t]     = __float2half(v0);
            vt[((size_t)bi * 1024 + col + 1) * 2048 + t] = __float2half(v1);
            int r1 = rbase + 8, t1 = r1 & 2047; bi = r1 >> 11;
            vt[((size_t)bi * 1024 + col) * 2048 + t1]     = __float2half(v2);
            vt[((size_t)bi * 1024 + col + 1) * 2048 + t1] = __float2half(v3);
        }
    }
}

// Output projection: fp32 straight to d_out.
__global__ __launch_bounds__(256, 2) void gemm_out(
    const __half* __restrict__ A, const __half* __restrict__ B,
    const float* __restrict__ bias, float* __restrict__ outF)
{
    extern __shared__ __half sm[];
    uint32_t sb = smem_u32(sm);
    int tid = threadIdx.x, lane = tid & 31, w = tid >> 5;
    int wm = w & 3, wn = w >> 2;
    int m0 = blockIdx.y * 128, n0 = blockIdx.x * 128;

    float acc[2][8][4];
    #pragma unroll
    for (int mf = 0; mf < 2; mf++)
        #pragma unroll
        for (int na = 0; na < 8; na++)
            #pragma unroll
            for (int j = 0; j < 4; j++) acc[mf][na][j] = 0.0f;

    gemm_core(sb, tid, lane, wm, wn, A, B, m0, n0, acc);

    #pragma unroll
    for (int mf = 0; mf < 2; mf++)
    #pragma unroll
    for (int na = 0; na < 8; na++) {
        int col = n0 + wn * 64 + na * 8 + (lane & 3) * 2;
        int rbase = m0 + wm * 32 + mf * 16 + (lane >> 2);
        float b0 = bias[col], b1 = bias[col + 1];
        *(float2*)(outF + (size_t)rbase * 1024 + col) =
            make_float2(acc[mf][na][0] + b0, acc[mf][na][1] + b1);
        *(float2*)(outF + (size_t)(rbase + 8) * 1024 + col) =
            make_float2(acc[mf][na][2] + b0, acc[mf][na][3] + b1);
    }
}

// ===========================================================================
// Attention — FA-2, all operands single fp16 (unchanged from R10)
// ===========================================================================
#define ASTR 72
#define AQ   (128 * ASTR)
#define AKV  (64 * ASTR)
#define ATTN_SMEM_BYTES ((AQ + 4 * AKV) * 2)   // 55296 B

__global__ __launch_bounds__(256, 2) void attn_mma() {
    extern __shared__ __half sm[];
    uint32_t sb = smem_u32(sm);
    int tid = threadIdx.x, lane = tid & 31, w = tid >> 5;
    int q0 = blockIdx.x * 128;
    int b = blockIdx.y >> 4, hd = blockIdx.y & 15;

    uint32_t tQ = sb;
    const uint32_t kvb0 = sb + 2 * AQ;

    #pragma unroll
    for (int i = 0; i < 4; i++) {
        int idx = tid + i * 256;
        int row = idx >> 3, c = idx & 7;
        cp16(tQ + row * (ASTR * 2) + c * 16,
             g_q + (size_t)(b * Tt + q0 + row) * 1024 + hd * 64 + c * 8);
    }

    auto issueKV = [&](int kt, int buf) {
        uint32_t dbase = kvb0 + (uint32_t)buf * (2 * AKV * 2);
        int kv0 = kt * 64;
        #pragma unroll
        for (int i = 0; i < 4; i++) {
            int idx = tid + i * 256;
            int t = idx >> 9;
            int r = (idx >> 3) & 63, c = idx & 7;
            const __half* src = (t == 0)
                ? g_k  + (size_t)(b * Tt + kv0 + r) * 1024 + hd * 64 + c * 8
                : g_vt + (size_t)(b * 1024 + hd * 64 + r) * Tt + kv0 + c * 8;
            cp16(dbase + t * (AKV * 2) + r * (ASTR * 2) + c * 16, src);
        }
        CP_COMMIT();
    };

    float o[8][4];
    #pragma unroll
    for (int t = 0; t < 8; t++)
        #pragma unroll
        for (int j = 0; j < 4; j++) o[t][j] = 0.0f;
    float lacc0 = 0.0f, lacc1 = 0.0f;

    int rowg = b * Tt + q0 + w * 16 + (lane >> 2);

    issueKV(0, 0);

    for (int kt = 0; kt < 32; kt++) {
        CP_WAIT0();
        __syncthreads();
        if (kt + 1 < 32) issueKV(kt + 1, (kt + 1) & 1);

        uint32_t kb = kvb0 + (uint32_t)(kt & 1) * (2 * AKV * 2);
        uint32_t tK = kb, tV = kb + AKV * 2;

        float s[8][4];
        #pragma unroll
        for (int t = 0; t < 8; t++)
            #pragma unroll
            for (int j = 0; j < 4; j++) s[t][j] = 0.0f;
        #pragma unroll
        for (int ks = 0; ks < 4; ks++) {
            uint32_t ao = (uint32_t)(w * 16 + (lane & 15)) * (ASTR * 2)
                        + ks * 32 + (lane >> 4) * 16;
            uint32_t q[4];
            ldm4(q, tQ + ao);
            #pragma unroll
            for (int pp = 0; pp < 2; pp++) {
                uint32_t bo0 = (uint32_t)((2 * pp) * 16 + (lane & 15)) * (ASTR * 2)
                             + ks * 32 + (lane >> 4) * 16;
                uint32_t bo1 = bo0 + 16 * (ASTR * 2);
                uint32_t k0[4], k1[4];
                ldm4(k0, tK + bo0); ldm4(k1, tK + bo1);
                mma16816(s[4 * pp + 0], q, k0[0], k0[2]);
                mma16816(s[4 * pp + 1], q, k0[1], k0[3]);
                mma16816(s[4 * pp + 2], q, k1[0], k1[2]);
                mma16816(s[4 * pp + 3], q, k1[1], k1[3]);
            }
        }

        uint32_t mw0 = g_mbits[(size_t)rowg * 64 + kt * 2];
        uint32_t mw1 = g_mbits[(size_t)rowg * 64 + kt * 2 + 1];
        uint32_t mw2 = g_mbits[(size_t)(rowg + 8) * 64 + kt * 2];
        uint32_t mw3 = g_mbits[(size_t)(rowg + 8) * 64 + kt * 2 + 1];

        uint32_t af[4][4];
        #pragma unroll
        for (int t = 0; t < 8; t++) {
            int cb = 8 * t + 2 * (lane & 3);
            uint32_t wa = (t < 4) ? mw0 : mw1;
            uint32_t wb = (t < 4) ? mw2 : mw3;
            int bit = cb & 31;
            float p0 = ((wa >> bit) & 1u)       ? __expf(s[t][0] * 0.125f) : 0.0f;
            float p1 = ((wa >> (bit + 1)) & 1u) ? __expf(s[t][1] * 0.125f) : 0.0f;
            float p2 = ((wb >> bit) & 1u)       ? __expf(s[t][2] * 0.125f) : 0.0f;
            float p3 = ((wb >> (bit + 1)) & 1u) ? __expf(s[t][3] * 0.125f) : 0.0f;
            lacc0 += p0 + p1;
            lacc1 += p2 + p3;
            int u = t >> 1, k = (t & 1) * 2;
            af[u][k]     = packhf(p0, p1);
            af[u][k + 1] = packhf(p2, p3);
        }

        #pragma unroll
        for (int u = 0; u < 4; u++) {
            #pragma unroll
            for (int pp = 0; pp < 2; pp++) {
                uint32_t bo0 = (uint32_t)((2 * pp) * 16 + (lane & 15)) * (ASTR * 2)
                             + u * 32 + (lane >> 4) * 16;
                uint32_t bo1 = bo0 + 16 * (ASTR * 2);
                uint32_t v0[4], v1[4];
                ldm4(v0, tV + bo0); ldm4(v1, tV + bo1);
                mma16816(o[4 * pp + 0], af[u], v0[0], v0[2]);
                mma16816(o[4 * pp + 1], af[u], v0[1], v0[3]);
                mma16816(o[4 * pp + 2], af[u], v1[0], v1[2]);
                mma16816(o[4 * pp + 3], af[u], v1[1], v1[3]);
            }
        }
    }

    lacc0 += __shfl_xor_sync(0xffffffffu, lacc0, 1);
    lacc0 += __shfl_xor_sync(0xffffffffu, lacc0, 2);
    lacc1 += __shfl_xor_sync(0xffffffffu, lacc1, 1);
    lacc1 += __shfl_xor_sync(0xffffffffu, lacc1, 2);
    float inv0 = 1.0f / lacc0, inv1 = 1.0f / lacc1;

    int row = q0 + w * 16 + (lane >> 2);
    #pragma unroll
    for (int t = 0; t < 8; t++) {
        int col = hd * 64 + 8 * t + 2 * (lane & 3);
        size_t o0 = (size_t)(b * Tt + row) * 1024 + col;
        size_t o1 = (size_t)(b * Tt + row + 8) * 1024 + col;
        *(uint32_t*)(g_z + o0) = packhf(o[t][0] * inv0, o[t][1] * inv0);
        *(uint32_t*)(g_z + o1) = packhf(o[t][2] * inv1, o[t][3] * inv1);
    }
}

// ===========================================================================
extern "C" void kernel_launch(void* const* d_in, const int* in_sizes, int n_in,
                              void* d_out, int out_size)
{
    const float* embed = (const float*)d_in[0];
    const int*   mask  = (const int*)d_in[1];
    const float* Wq = (const float*)d_in[2];
    const float* bq = (const float*)d_in[3];
    const float* Wk = (const float*)d_in[4];
    const float* bk = (const float*)d_in[5];
    const float* Wv = (const float*)d_in[6];
    const float* bv = (const float*)d_in[7];
    const float* Wz = (const float*)d_in[8];
    const float* bz = (const float*)d_in[9];
    float* out = (float*)d_out;

    __half *e, *wt, *q, *k, *vt, *z;
    uint32_t* mbits;
    cudaGetSymbolAddress((void**)&e, g_e);
    cudaGetSymbolAddress((void**)&wt, g_w);
    cudaGetSymbolAddress((void**)&q, g_q);
    cudaGetSymbolAddress((void**)&k, g_k);
    cudaGetSymbolAddress((void**)&vt, g_vt);
    cudaGetSymbolAddress((void**)&z, g_z);
    cudaGetSymbolAddress((void**)&mbits, g_mbits);

    cudaFuncSetAttribute(gemm_qkv, cudaFuncAttributeMaxDynamicSharedMemorySize,
                         GEMM_SMEM_BYTES);
    cudaFuncSetAttribute(gemm_out, cudaFuncAttributeMaxDynamicSharedMemorySize,
                         GEMM_SMEM_BYTES);
    cudaFuncSetAttribute(attn_mma, cudaFuncAttributeMaxDynamicSharedMemorySize,
                         ATTN_SMEM_BYTES);

    const size_t WSZ = (size_t)1024 * 1024;

    // Preps
    conv_f16<<<(Mtot * KDIM / 4 + 255) / 256, 256>>>(embed, e, Mtot * KDIM / 4);
    dim3 tb(32, 8), tg4(32, 32, 4);
    trans4<<<tg4, tb>>>(Wq, Wk, Wv, Wz, wt);
    pack_mask<<<(Bb * Tt * Tt) / 256, 256>>>(mask, mbits);

    // Fused Q/K/V projections (128x128 tiles)
    gemm_qkv<<<dim3(8, 32, 3), 256, GEMM_SMEM_BYTES>>>(
        e, wt, bq, bk, bv, q, k, vt);

    // Attention
    attn_mma<<<dim3(16, 32), 256, ATTN_SMEM_BYTES>>>();

    // Output projection -> d_out (fp32)
    gemm_out<<<dim3(8, 32), 256, GEMM_SMEM_BYTES>>>(
        z, wt + 3 * WSZ, bz, out);
}

// round 13
// speedup vs baseline: 5.8738x; 1.0046x over previous
#include <cuda_runtime.h>
#include <cuda_fp16.h>
#include <cstdint>
#include <math.h>

#define Bb 2
#define Tt 2048
#define Hh 16
#define Mtot 4096
#define KDIM 1024

// ===========================================================================
// Helpers
// ===========================================================================
__device__ __forceinline__ uint32_t smem_u32(const void* p) {
    uint32_t a;
    asm("{ .reg .u64 t; cvta.to.shared.u64 t, %1; cvt.u32.u64 %0, t; }"
        : "=r"(a) : "l"(p));
    return a;
}
__device__ __forceinline__ void cp16(uint32_t dst, const void* src) {
    asm volatile("cp.async.cg.shared.global [%0], [%1], 16;" :: "r"(dst), "l"(src));
}
#define CP_COMMIT() asm volatile("cp.async.commit_group;" ::: "memory")
#define CP_WAIT0()  asm volatile("cp.async.wait_group 0;" ::: "memory")

__device__ __forceinline__ void ldm4(uint32_t* r, uint32_t a) {
    asm volatile("ldmatrix.sync.aligned.m8n8.x4.shared.b16 {%0,%1,%2,%3}, [%4];"
        : "=r"(r[0]), "=r"(r[1]), "=r"(r[2]), "=r"(r[3]) : "r"(a));
}
__device__ __forceinline__ void mma16816(float* d, const uint32_t* a,
                                         uint32_t b0, uint32_t b1) {
    asm volatile("mma.sync.aligned.m16n8k16.row.col.f32.f16.f16.f32 "
        "{%0,%1,%2,%3}, {%4,%5,%6,%7}, {%8,%9}, {%0,%1,%2,%3};"
        : "+f"(d[0]), "+f"(d[1]), "+f"(d[2]), "+f"(d[3])
        : "r"(a[0]), "r"(a[1]), "r"(a[2]), "r"(a[3]), "r"(b0), "r"(b1));
}

__device__ __forceinline__ uint32_t packhf(float a, float b) {
    __half2 t; t.x = __float2half(a); t.y = __float2half(b);
    return *(uint32_t*)&t;
}

// ===========================================================================
// Scratch (device globals) — everything single fp16
// ===========================================================================
__device__ __half g_e[(size_t)Mtot * KDIM];                 // embed
__device__ __half g_w[(size_t)4 * 1024 * 1024];             // W^T x4
__device__ __half g_q[(size_t)Mtot * KDIM];                 // Q
__device__ __half g_k[(size_t)Mtot * KDIM];                 // K
__device__ __half g_vt[(size_t)Mtot * KDIM];                // V^T [b][n][t]
__device__ __half g_z[(size_t)Mtot * KDIM];                 // Z
__device__ uint32_t g_mbits[(size_t)Bb * Tt * (Tt / 32)];

// ===========================================================================
// Prep kernels
// ===========================================================================
__global__ void conv_f16(const float* __restrict__ x, __half* __restrict__ o, int n4) {
    int i = blockIdx.x * blockDim.x + threadIdx.x;
    if (i >= n4) return;
    float4 v = ((const float4*)x)[i];
    ((uint32_t*)o)[2 * i]     = packhf(v.x, v.y);
    ((uint32_t*)o)[2 * i + 1] = packhf(v.z, v.w);
}

__global__ void trans4(const float* __restrict__ W0, const float* __restrict__ W1,
                       const float* __restrict__ W2, const float* __restrict__ W3,
                       __half* __restrict__ T) {
    __shared__ float t[32][33];
    const float* W = (blockIdx.z == 0) ? W0 : (blockIdx.z == 1) ? W1
                   : (blockIdx.z == 2) ? W2 : W3;
    size_t dbase = (size_t)blockIdx.z * 1024 * 1024;
    int tx = threadIdx.x, ty = threadIdx.y;
    int x0 = blockIdx.x * 32, y0 = blockIdx.y * 32;
    #pragma unroll
    for (int i = 0; i < 32; i += 8)
        t[ty + i][tx] = W[(size_t)(y0 + ty + i) * 1024 + x0 + tx];
    __syncthreads();
    #pragma unroll
    for (int i = 0; i < 32; i += 8) {
        float v = t[tx][ty + i];
        T[dbase + (size_t)(x0 + ty + i) * 1024 + y0 + tx] = __float2half(v);
    }
}

__global__ void pack_mask(const int* __restrict__ m, uint32_t* __restrict__ bits) {
    int i = blockIdx.x * blockDim.x + threadIdx.x;
    uint32_t bal = __ballot_sync(0xffffffffu, m[i] != 0);
    if ((threadIdx.x & 31) == 0) bits[i >> 5] = bal;
}

// ===========================================================================
// GEMM core: 128x128 CTA tile, 8 warps (4m x 2n), warp tile 32x64.
// KC=64, 2-stage, 1 barrier/chunk. (unchanged from R11)
// ===========================================================================
#define GSTR2 72
#define GAEL (128 * GSTR2)
#define GSTAGE (2 * GAEL)
#define GEMM_SMEM_BYTES (2 * GSTAGE * 2) // 73728 B

__device__ __forceinline__ void gemm_core(
    uint32_t sb, int tid, int lane, int wm, int wn,
    const __half* __restrict__ A, const __half* __restrict__ B,
    int m0, int n0, float acc[2][8][4])
{
    const __half* srcA = A + (size_t)m0 * KDIM;
    const __half* srcB = B + (size_t)n0 * KDIM;

    auto issue = [&](int ch, int buf) {
        uint32_t dbase = sb + (uint32_t)buf * (GSTAGE * 2);
        #pragma unroll
        for (int i = 0; i < 8; i++) {
            int idx = tid + i * 256;
            int t = idx >> 10;
            int r = (idx >> 3) & 127, c = idx & 7;
            const __half* src = (t ? srcB : srcA) + (size_t)r * KDIM + ch * 64 + c * 8;
            cp16(dbase + t * (GAEL * 2) + r * (GSTR2 * 2) + c * 16, src);
        }
        CP_COMMIT();
    };

    issue(0, 0);
    const int NC = KDIM / 64;   // 16
    for (int ch = 0; ch < NC; ch++) {
        CP_WAIT0();
        __syncthreads();
        if (ch + 1 < NC) issue(ch + 1, (ch + 1) & 1);

        uint32_t bb = sb + (uint32_t)(ch & 1) * (GSTAGE * 2);
        uint32_t tA = bb, tB = bb + GAEL * 2;
        #pragma unroll
        for (int ks = 0; ks < 4; ks++) {
            uint32_t ao = (uint32_t)(wm * 32 + (lane & 15)) * (GSTR2 * 2)
                        + ks * 32 + (lane >> 4) * 16;
            uint32_t a0[4], a1[4];
            ldm4(a0, tA + ao);
            ldm4(a1, tA + ao + 16 * (GSTR2 * 2));
            #pragma unroll
            for (int p = 0; p < 4; p++) {
                uint32_t bo = (uint32_t)(wn * 64 + p * 16 + (lane & 15)) * (GSTR2 * 2)
                            + ks * 32 + (lane >> 4) * 16;
                uint32_t bf[4];
                ldm4(bf, tB + bo);
                mma16816(acc[0][2 * p],     a0, bf[0], bf[2]);
                mma16816(acc[0][2 * p + 1], a0, bf[1], bf[3]);
                mma16816(acc[1][2 * p],     a1, bf[0], bf[2]);
                mma16816(acc[1][2 * p + 1], a1, bf[1], bf[3]);
            }
        }
    }
}

// Fused Q/K/V projections. z=0: Q; z=1: K; z=2: V^T.
__global__ __launch_bounds__(256, 2) void gemm_qkv(
    const __half* __restrict__ A, const __half* __restrict__ Wt,
    const float* __restrict__ bq, const float* __restrict__ bk,
    const float* __restrict__ bv,
    __half* __restrict__ q, __half* __restrict__ k, __half* __restrict__ vt)
{
    extern __shared__ __half sm[];
    uint32_t sb = smem_u32(sm);
    int tid = threadIdx.x, lane = tid & 31, w = tid >> 5;
    int wm = w & 3, wn = w >> 2;
    int m0 = blockIdx.y * 128, n0 = blockIdx.x * 128;
    int z = blockIdx.z;
    const size_t WSZ = (size_t)1024 * 1024;
    const __half* B = Wt + (size_t)z * WSZ;
    const float* bias = (z == 0) ? bq : (z == 1) ? bk : bv;

    float acc[2][8][4];
    #pragma unroll
    for (int mf = 0; mf < 2; mf++)
        #pragma unroll
        for (int na = 0; na < 8; na++)
            #pragma unroll
            for (int j = 0; j < 4; j++) acc[mf][na][j] = 0.0f;

    gemm_core(sb, tid, lane, wm, wn, A, B, m0, n0, acc);

    #pragma unroll
    for (int mf = 0; mf < 2; mf++)
    #pragma unroll
    for (int na = 0; na < 8; na++) {
        int col = n0 + wn * 64 + na * 8 + (lane & 3) * 2;
        int rbase = m0 + wm * 32 + mf * 16 + (lane >> 2);
        float v0 = acc[mf][na][0] + bias[col], v1 = acc[mf][na][1] + bias[col + 1];
        float v2 = acc[mf][na][2] + bias[col], v3 = acc[mf][na][3] + bias[col + 1];
        if (z == 0 || z == 1) {
            __half* O = (z == 0) ? q : k;
            *(uint32_t*)(O + (size_t)rbase * 1024 + col)       = packhf(v0, v1);
            *(uint32_t*)(O + (size_t)(rbase + 8) * 1024 + col) = packhf(v2, v3);
        } else {
            int bi = rbase >> 11, t = rbase & 2047;
            vt[((size_t)bi * 1024 + col) * 2048 + t]     = __float2half(v0);
            vt[((size_t)bi * 1024 + col + 1) * 2048 + t] = __float2half(v1);
            int r1 = rbase + 8, t1 = r1 & 2047; bi = r1 >> 11;
            vt[((size_t)bi * 1024 + col) * 2048 + t1]     = __float2half(v2);
            vt[((size_t)bi * 1024 + col + 1) * 2048 + t1] = __float2half(v3);
        }
    }
}

// Output projection: fp32 straight to d_out.
__global__ __launch_bounds__(256, 2) void gemm_out(
    const __half* __restrict__ A, const __half* __restrict__ B,
    const float* __restrict__ bias, float* __restrict__ outF)
{
    extern __shared__ __half sm[];
    uint32_t sb = smem_u32(sm);
    int tid = threadIdx.x, lane = tid & 31, w = tid >> 5;
    int wm = w & 3, wn = w >> 2;
    int m0 = blockIdx.y * 128, n0 = blockIdx.x * 128;

    float acc[2][8][4];
    #pragma unroll
    for (int mf = 0; mf < 2; mf++)
        #pragma unroll
        for (int na = 0; na < 8; na++)
            #pragma unroll
            for (int j = 0; j < 4; j++) acc[mf][na][j] = 0.0f;

    gemm_core(sb, tid, lane, wm, wn, A, B, m0, n0, acc);

    #pragma unroll
    for (int mf = 0; mf < 2; mf++)
    #pragma unroll
    for (int na = 0; na < 8; na++) {
        int col = n0 + wn * 64 + na * 8 + (lane & 3) * 2;
        int rbase = m0 + wm * 32 + mf * 16 + (lane >> 2);
        float b0 = bias[col], b1 = bias[col + 1];
        *(float2*)(outF + (size_t)rbase * 1024 + col) =
            make_float2(acc[mf][na][0] + b0, acc[mf][na][1] + b1);
        *(float2*)(outF + (size_t)(rbase + 8) * 1024 + col) =
            make_float2(acc[mf][na][2] + b0, acc[mf][na][3] + b1);
    }
}

// ===========================================================================
// Attention — FA-2, single fp16; KV tile 128 (two 64-halves per barrier),
// Q fragments hoisted into registers.
// ===========================================================================
#define ASTR 72                          // Q/K tile row stride (halfs)
#define VSTR 136                         // V^T tile row stride (halfs)
#define AQ   (128 * ASTR)                // 9216 el
#define AK   (128 * ASTR)                // 9216 el (K: 128 kv rows x 64 d)
#define AV   (64 * VSTR)                 // 8704 el (V^T: 64 d rows x 128 kv)
#define ASTAGE (AK + AV)                 // 17920 el
#define ATTN_SMEM_BYTES ((AQ + 2 * ASTAGE) * 2)   // 90112 B

__global__ __launch_bounds__(256, 2) void attn_mma() {
    extern __shared__ __half sm[];
    uint32_t sb = smem_u32(sm);
    int tid = threadIdx.x, lane = tid & 31, w = tid >> 5;
    int q0 = blockIdx.x * 128;
    int b = blockIdx.y >> 4, hd = blockIdx.y & 15;

    uint32_t tQ = sb;
    const uint32_t kvb0 = sb + 2 * AQ;

    // Q tile -> smem (joins cp group 0)
    #pragma unroll
    for (int i = 0; i < 4; i++) {
        int idx = tid + i * 256;
        int row = idx >> 3, c = idx & 7;
        cp16(tQ + row * (ASTR * 2) + c * 16,
             g_q + (size_t)(b * Tt + q0 + row) * 1024 + hd * 64 + c * 8);
    }

    auto issueKV = [&](int kt, int buf) {
        uint32_t dbase = kvb0 + (uint32_t)buf * (ASTAGE * 2);
        int kv0 = kt * 128;
        #pragma unroll
        for (int i = 0; i < 8; i++) {
            int idx = tid + i * 256;        // 0..2047
            if (idx < 1024) {               // K: 128 rows x 8 cp16
                int r = idx >> 3, c = idx & 7;
                cp16(dbase + r * (ASTR * 2) + c * 16,
                     g_k + (size_t)(b * Tt + kv0 + r) * 1024 + hd * 64 + c * 8);
            } else {                        // V^T: 64 rows x 16 cp16
                int j = idx - 1024;
                int r = j >> 4, c = j & 15;
                cp16(dbase + AK * 2 + r * (VSTR * 2) + c * 16,
                     g_vt + (size_t)(b * 1024 + hd * 64 + r) * Tt + kv0 + c * 8);
            }
        }
        CP_COMMIT();
    };

    float o[8][4];
    #pragma unroll
    for (int t = 0; t < 8; t++)
        #pragma unroll
        for (int j = 0; j < 4; j++) o[t][j] = 0.0f;
    float lacc0 = 0.0f, lacc1 = 0.0f;
    uint32_t qf[4][4];   // hoisted Q fragments (one per ks)

    int rowg = b * Tt + q0 + w * 16 + (lane >> 2);

    issueKV(0, 0);

    for (int kt = 0; kt < 16; kt++) {
        CP_WAIT0();
        __syncthreads();
        if (kt + 1 < 16) issueKV(kt + 1, (kt + 1) & 1);
        if (kt == 0) {
            #pragma unroll
            for (int ks = 0; ks < 4; ks++) {
                uint32_t ao = (uint32_t)(w * 16 + (lane & 15)) * (ASTR * 2)
                            + ks * 32 + (lane >> 4) * 16;
                ldm4(qf[ks], tQ + ao);
            }
        }

        uint32_t kb = kvb0 + (uint32_t)(kt & 1) * (ASTAGE * 2);
        uint32_t tK = kb, tV = kb + AK * 2;

        #pragma unroll
        for (int half = 0; half < 2; half++) {
            // ---- S = Q @ K^T over this 64-kv half ----
            float s[8][4];
            #pragma unroll
            for (int t = 0; t < 8; t++)
                #pragma unroll
                for (int j = 0; j < 4; j++) s[t][j] = 0.0f;
            #pragma unroll
            for (int ks = 0; ks < 4; ks++) {
                #pragma unroll
                for (int pp = 0; pp < 2; pp++) {
                    uint32_t bo0 = (uint32_t)(half * 64 + 2 * pp * 16 + (lane & 15))
                                   * (ASTR * 2) + ks * 32 + (lane >> 4) * 16;
                    uint32_t bo1 = bo0 + 16 * (ASTR * 2);
                    uint32_t k0[4], k1[4];
                    ldm4(k0, tK + bo0); ldm4(k1, tK + bo1);
                    mma16816(s[4 * pp + 0], qf[ks], k0[0], k0[2]);
                    mma16816(s[4 * pp + 1], qf[ks], k0[1], k0[3]);
                    mma16816(s[4 * pp + 2], qf[ks], k1[0], k1[2]);
                    mma16816(s[4 * pp + 3], qf[ks], k1[1], k1[3]);
                }
            }

            // ---- softmax in registers, P fp16 fragments ----
            uint32_t mw0 = g_mbits[(size_t)rowg * 64 + kt * 4 + 2 * half];
            uint32_t mw1 = g_mbits[(size_t)rowg * 64 + kt * 4 + 2 * half + 1];
            uint32_t mw2 = g_mbits[(size_t)(rowg + 8) * 64 + kt * 4 + 2 * half];
            uint32_t mw3 = g_mbits[(size_t)(rowg + 8) * 64 + kt * 4 + 2 * half + 1];

            uint32_t af[4][4];
            #pragma unroll
            for (int t = 0; t < 8; t++) {
                int cb = 8 * t + 2 * (lane & 3);
                uint32_t wa = (t < 4) ? mw0 : mw1;
                uint32_t wb = (t < 4) ? mw2 : mw3;
                int bit = cb & 31;
                float p0 = ((wa >> bit) & 1u)       ? __expf(s[t][0] * 0.125f) : 0.0f;
                float p1 = ((wa >> (bit + 1)) & 1u) ? __expf(s[t][1] * 0.125f) : 0.0f;
                float p2 = ((wb >> bit) & 1u)       ? __expf(s[t][2] * 0.125f) : 0.0f;
                float p3 = ((wb >> (bit + 1)) & 1u) ? __expf(s[t][3] * 0.125f) : 0.0f;
                lacc0 += p0 + p1;
                lacc1 += p2 + p3;
                int u = t >> 1, k = (t & 1) * 2;
                af[u][k]     = packhf(p0, p1);
                af[u][k + 1] = packhf(p2, p3);
            }

            // ---- O += P @ V over this half ----
            #pragma unroll
            for (int u = 0; u < 4; u++) {
                #pragma unroll
                for (int pp = 0; pp < 2; pp++) {
                    uint32_t bo0 = (uint32_t)(2 * pp * 16 + (lane & 15)) * (VSTR * 2)
                                 + half * 128 + u * 32 + (lane >> 4) * 16;
                    uint32_t bo1 = bo0 + 16 * (VSTR * 2);
                    uint32_t v0[4], v1[4];
                    ldm4(v0, tV + bo0); ldm4(v1, tV + bo1);
                    mma16816(o[4 * pp + 0], af[u], v0[0], v0[2]);
                    mma16816(o[4 * pp + 1], af[u], v0[1], v0[3]);
                    mma16816(o[4 * pp + 2], af[u], v1[0], v1[2]);
                    mma16816(o[4 * pp + 3], af[u], v1[1], v1[3]);
                }
            }
        }
    }

    lacc0 += __shfl_xor_sync(0xffffffffu, lacc0, 1);
    lacc0 += __shfl_xor_sync(0xffffffffu, lacc0, 2);
    lacc1 += __shfl_xor_sync(0xffffffffu, lacc1, 1);
    lacc1 += __shfl_xor_sync(0xffffffffu, lacc1, 2);
    float inv0 = 1.0f / lacc0, inv1 = 1.0f / lacc1;

    int row = q0 + w * 16 + (lane >> 2);
    #pragma unroll
    for (int t = 0; t < 8; t++) {
        int col = hd * 64 + 8 * t + 2 * (lane & 3);
        size_t o0 = (size_t)(b * Tt + row) * 1024 + col;
        size_t o1 = (size_t)(b * Tt + row + 8) * 1024 + col;
        *(uint32_t*)(g_z + o0) = packhf(o[t][0] * inv0, o[t][1] * inv0);
        *(uint32_t*)(g_z + o1) = packhf(o[t][2] * inv1, o[t][3] * inv1);
    }
}

// ===========================================================================
extern "C" void kernel_launch(void* const* d_in, const int* in_sizes, int n_in,
                              void* d_out, int out_size)
{
    const float* embed = (const float*)d_in[0];
    const int*   mask  = (const int*)d_in[1];
    const float* Wq = (const float*)d_in[2];
    const float* bq = (const float*)d_in[3];
    const float* Wk = (const float*)d_in[4];
    const float* bk = (const float*)d_in[5];
    const float* Wv = (const float*)d_in[6];
    const float* bv = (const float*)d_in[7];
    const float* Wz = (const float*)d_in[8];
    const float* bz = (const float*)d_in[9];
    float* out = (float*)d_out;

    __half *e, *wt, *q, *k, *vt, *z;
    uint32_t* mbits;
    cudaGetSymbolAddress((void**)&e, g_e);
    cudaGetSymbolAddress((void**)&wt, g_w);
    cudaGetSymbolAddress((void**)&q, g_q);
    cudaGetSymbolAddress((void**)&k, g_k);
    cudaGetSymbolAddress((void**)&vt, g_vt);
    cudaGetSymbolAddress((void**)&z, g_z);
    cudaGetSymbolAddress((void**)&mbits, g_mbits);

    cudaFuncSetAttribute(gemm_qkv, cudaFuncAttributeMaxDynamicSharedMemorySize,
                         GEMM_SMEM_BYTES);
    cudaFuncSetAttribute(gemm_out, cudaFuncAttributeMaxDynamicSharedMemorySize,
                         GEMM_SMEM_BYTES);
    cudaFuncSetAttribute(attn_mma, cudaFuncAttributeMaxDynamicSharedMemorySize,
                         ATTN_SMEM_BYTES);

    const size_t WSZ = (size_t)1024 * 1024;

    // Preps
    conv_f16<<<(Mtot * KDIM / 4 + 255) / 256, 256>>>(embed, e, Mtot * KDIM / 4);
    dim3 tb(32, 8), tg4(32, 32, 4);
    trans4<<<tg4, tb>>>(Wq, Wk, Wv, Wz, wt);
    pack_mask<<<(Bb * Tt * Tt) / 256, 256>>>(mask, mbits);

    // Fused Q/K/V projections (128x128 tiles)
    gemm_qkv<<<dim3(8, 32, 3), 256, GEMM_SMEM_BYTES>>>(
        e, wt, bq, bk, bv, q, k, vt);

    // Attention
    attn_mma<<<dim3(16, 32), 256, ATTN_SMEM_BYTES>>>();

    // Output projection -> d_out (fp32)
    gemm_out<<<dim3(8, 32), 256, GEMM_SMEM_BYTES>>>(
        z, wt + 3 * WSZ, bz, out);
}

// round 14
// speedup vs baseline: 5.8828x; 1.0015x over previous
#include <cuda_runtime.h>
#include <cuda_fp16.h>
#include <cstdint>
#include <math.h>

#define Bb 2
#define Tt 2048
#define Hh 16
#define Mtot 4096
#define KDIM 1024

// ===========================================================================
// Helpers
// ===========================================================================
__device__ __forceinline__ uint32_t smem_u32(const void* p) {
    uint32_t a;
    asm("{ .reg .u64 t; cvta.to.shared.u64 t, %1; cvt.u32.u64 %0, t; }"
        : "=r"(a) : "l"(p));
    return a;
}
__device__ __forceinline__ void cp16(uint32_t dst, const void* src) {
    asm volatile("cp.async.cg.shared.global [%0], [%1], 16;" :: "r"(dst), "l"(src));
}
#define CP_COMMIT() asm volatile("cp.async.commit_group;" ::: "memory")
#define CP_WAIT0()  asm volatile("cp.async.wait_group 0;" ::: "memory")

__device__ __forceinline__ void ldm4(uint32_t* r, uint32_t a) {
    asm volatile("ldmatrix.sync.aligned.m8n8.x4.shared.b16 {%0,%1,%2,%3}, [%4];"
        : "=r"(r[0]), "=r"(r[1]), "=r"(r[2]), "=r"(r[3]) : "r"(a));
}
__device__ __forceinline__ void mma16816(float* d, const uint32_t* a,
                                         uint32_t b0, uint32_t b1) {
    asm volatile("mma.sync.aligned.m16n8k16.row.col.f32.f16.f16.f32 "
        "{%0,%1,%2,%3}, {%4,%5,%6,%7}, {%8,%9}, {%0,%1,%2,%3};"
        : "+f"(d[0]), "+f"(d[1]), "+f"(d[2]), "+f"(d[3])
        : "r"(a[0]), "r"(a[1]), "r"(a[2]), "r"(a[3]), "r"(b0), "r"(b1));
}

__device__ __forceinline__ uint32_t packhf(float a, float b) {
    __half2 t; t.x = __float2half(a); t.y = __float2half(b);
    return *(uint32_t*)&t;
}

// ===========================================================================
// Scratch (device globals) — everything single fp16
// ===========================================================================
__device__ __half g_e[(size_t)Mtot * KDIM];                 // embed
__device__ __half g_w[(size_t)4 * 1024 * 1024];             // W^T x4
__device__ __half g_q[(size_t)Mtot * KDIM];                 // Q
__device__ __half g_k[(size_t)Mtot * KDIM];                 // K
__device__ __half g_vt[(size_t)Mtot * KDIM];                // V^T [b][n][t]
__device__ __half g_z[(size_t)Mtot * KDIM];                 // Z
__device__ uint32_t g_mbits[(size_t)Bb * Tt * (Tt / 32)];

// ===========================================================================
// Prep kernels
// ===========================================================================
__global__ void conv_f16(const float* __restrict__ x, __half* __restrict__ o, int n4) {
    int i = blockIdx.x * blockDim.x + threadIdx.x;
    if (i >= n4) return;
    float4 v = ((const float4*)x)[i];
    ((uint32_t*)o)[2 * i]     = packhf(v.x, v.y);
    ((uint32_t*)o)[2 * i + 1] = packhf(v.z, v.w);
}

__global__ void trans4(const float* __restrict__ W0, const float* __restrict__ W1,
                       const float* __restrict__ W2, const float* __restrict__ W3,
                       __half* __restrict__ T) {
    __shared__ float t[32][33];
    const float* W = (blockIdx.z == 0) ? W0 : (blockIdx.z == 1) ? W1
                   : (blockIdx.z == 2) ? W2 : W3;
    size_t dbase = (size_t)blockIdx.z * 1024 * 1024;
    int tx = threadIdx.x, ty = threadIdx.y;
    int x0 = blockIdx.x * 32, y0 = blockIdx.y * 32;
    #pragma unroll
    for (int i = 0; i < 32; i += 8)
        t[ty + i][tx] = W[(size_t)(y0 + ty + i) * 1024 + x0 + tx];
    __syncthreads();
    #pragma unroll
    for (int i = 0; i < 32; i += 8) {
        float v = t[tx][ty + i];
        T[dbase + (size_t)(x0 + ty + i) * 1024 + y0 + tx] = __float2half(v);
    }
}

__global__ void pack_mask(const int* __restrict__ m, uint32_t* __restrict__ bits) {
    int i = blockIdx.x * blockDim.x + threadIdx.x;
    uint32_t bal = __ballot_sync(0xffffffffu, m[i] != 0);
    if ((threadIdx.x & 31) == 0) bits[i >> 5] = bal;
}

// ===========================================================================
// GEMM core: 128x128 CTA tile, 8 warps (4m x 2n), warp tile 32x64.
// KC=64, 2-stage, 1 barrier/chunk. (unchanged from R11)
// ===========================================================================
#define GSTR2 72
#define GAEL (128 * GSTR2)
#define GSTAGE (2 * GAEL)
#define GEMM_SMEM_BYTES (2 * GSTAGE * 2) // 73728 B

__device__ __forceinline__ void gemm_core(
    uint32_t sb, int tid, int lane, int wm, int wn,
    const __half* __restrict__ A, const __half* __restrict__ B,
    int m0, int n0, float acc[2][8][4])
{
    const __half* srcA = A + (size_t)m0 * KDIM;
    const __half* srcB = B + (size_t)n0 * KDIM;

    auto issue = [&](int ch, int buf) {
        uint32_t dbase = sb + (uint32_t)buf * (GSTAGE * 2);
        #pragma unroll
        for (int i = 0; i < 8; i++) {
            int idx = tid + i * 256;
            int t = idx >> 10;
            int r = (idx >> 3) & 127, c = idx & 7;
            const __half* src = (t ? srcB : srcA) + (size_t)r * KDIM + ch * 64 + c * 8;
            cp16(dbase + t * (GAEL * 2) + r * (GSTR2 * 2) + c * 16, src);
        }
        CP_COMMIT();
    };

    issue(0, 0);
    const int NC = KDIM / 64;   // 16
    for (int ch = 0; ch < NC; ch++) {
        CP_WAIT0();
        __syncthreads();
        if (ch + 1 < NC) issue(ch + 1, (ch + 1) & 1);

        uint32_t bb = sb + (uint32_t)(ch & 1) * (GSTAGE * 2);
        uint32_t tA = bb, tB = bb + GAEL * 2;
        #pragma unroll
        for (int ks = 0; ks < 4; ks++) {
            uint32_t ao = (uint32_t)(wm * 32 + (lane & 15)) * (GSTR2 * 2)
                        + ks * 32 + (lane >> 4) * 16;
            uint32_t a0[4], a1[4];
            ldm4(a0, tA + ao);
            ldm4(a1, tA + ao + 16 * (GSTR2 * 2));
            #pragma unroll
            for (int p = 0; p < 4; p++) {
                uint32_t bo = (uint32_t)(wn * 64 + p * 16 + (lane & 15)) * (GSTR2 * 2)
                            + ks * 32 + (lane >> 4) * 16;
                uint32_t bf[4];
                ldm4(bf, tB + bo);
                mma16816(acc[0][2 * p],     a0, bf[0], bf[2]);
                mma16816(acc[0][2 * p + 1], a0, bf[1], bf[3]);
                mma16816(acc[1][2 * p],     a1, bf[0], bf[2]);
                mma16816(acc[1][2 * p + 1], a1, bf[1], bf[3]);
            }
        }
    }
}

// Fused Q/K/V projections. z=0: Q; z=1: K; z=2: V^T.
__global__ __launch_bounds__(256, 2) void gemm_qkv(
    const __half* __restrict__ A, const __half* __restrict__ Wt,
    const float* __restrict__ bq, const float* __restrict__ bk,
    const float* __restrict__ bv,
    __half* __restrict__ q, __half* __restrict__ k, __half* __restrict__ vt)
{
    extern __shared__ __half sm[];
    uint32_t sb = smem_u32(sm);
    int tid = threadIdx.x, lane = tid & 31, w = tid >> 5;
    int wm = w & 3, wn = w >> 2;
    int m0 = blockIdx.y * 128, n0 = blockIdx.x * 128;
    int z = blockIdx.z;
    const size_t WSZ = (size_t)1024 * 1024;
    const __half* B = Wt + (size_t)z * WSZ;
    const float* bias = (z == 0) ? bq : (z == 1) ? bk : bv;

    float acc[2][8][4];
    #pragma unroll
    for (int mf = 0; mf < 2; mf++)
        #pragma unroll
        for (int na = 0; na < 8; na++)
            #pragma unroll
            for (int j = 0; j < 4; j++) acc[mf][na][j] = 0.0f;

    gemm_core(sb, tid, lane, wm, wn, A, B, m0, n0, acc);

    #pragma unroll
    for (int mf = 0; mf < 2; mf++)
    #pragma unroll
    for (int na = 0; na < 8; na++) {
        int col = n0 + wn * 64 + na * 8 + (lane & 3) * 2;
        int rbase = m0 + wm * 32 + mf * 16 + (lane >> 2);
        float v0 = acc[mf][na][0] + bias[col], v1 = acc[mf][na][1] + bias[col + 1];
        float v2 = acc[mf][na][2] + bias[col], v3 = acc[mf][na][3] + bias[col + 1];
        if (z == 0 || z == 1) {
            __half* O = (z == 0) ? q : k;
            *(uint32_t*)(O + (size_t)rbase * 1024 + col)       = packhf(v0, v1);
            *(uint32_t*)(O + (size_t)(rbase + 8) * 1024 + col) = packhf(v2, v3);
        } else {
            int bi = rbase >> 11, t = rbase & 2047;
            vt[((size_t)bi * 1024 + col) * 2048 + t]     = __float2half(v0);
            vt[((size_t)bi * 1024 + col + 1) * 2048 + t] = __float2half(v1);
            int r1 = rbase + 8, t1 = r1 & 2047; bi = r1 >> 11;
            vt[((size_t)bi * 1024 + col) * 2048 + t1]     = __float2half(v2);
            vt[((size_t)bi * 1024 + col + 1) * 2048 + t1] = __float2half(v3);
        }
    }
}

// Output projection: fp32 straight to d_out.
__global__ __launch_bounds__(256, 2) void gemm_out(
    const __half* __restrict__ A, const __half* __restrict__ B,
    const float* __restrict__ bias, float* __restrict__ outF)
{
    extern __shared__ __half sm[];
    uint32_t sb = smem_u32(sm);
    int tid = threadIdx.x, lane = tid & 31, w = tid >> 5;
    int wm = w & 3, wn = w >> 2;
    int m0 = blockIdx.y * 128, n0 = blockIdx.x * 128;

    float acc[2][8][4];
    #pragma unroll
    for (int mf = 0; mf < 2; mf++)
        #pragma unroll
        for (int na = 0; na < 8; na++)
            #pragma unroll
            for (int j = 0; j < 4; j++) acc[mf][na][j] = 0.0f;

    gemm_core(sb, tid, lane, wm, wn, A, B, m0, n0, acc);

    #pragma unroll
    for (int mf = 0; mf < 2; mf++)
    #pragma unroll
    for (int na = 0; na < 8; na++) {
        int col = n0 + wn * 64 + na * 8 + (lane & 3) * 2;
        int rbase = m0 + wm * 32 + mf * 16 + (lane >> 2);
        float b0 = bias[col], b1 = bias[col + 1];
        *(float2*)(outF + (size_t)rbase * 1024 + col) =
            make_float2(acc[mf][na][0] + b0, acc[mf][na][1] + b1);
        *(float2*)(outF + (size_t)(rbase + 8) * 1024 + col) =
            make_float2(acc[mf][na][2] + b0, acc[mf][na][3] + b1);
    }
}

// ===========================================================================
// Attention — FA-2, single fp16; KV tile 128 (two 64-halves per barrier),
// Q fragments hoisted into registers.
// ===========================================================================
#define ASTR 72                          // Q/K tile row stride (halfs)
#define VSTR 136                         // V^T tile row stride (halfs)
#define AQ   (128 * ASTR)                // 9216 el
#define AK   (128 * ASTR)                // 9216 el (K: 128 kv rows x 64 d)
#define AV   (64 * VSTR)                 // 8704 el (V^T: 64 d rows x 128 kv)
#define ASTAGE (AK + AV)                 // 17920 el
#define ATTN_SMEM_BYTES ((AQ + 2 * ASTAGE) * 2)   // 90112 B

__global__ __launch_bounds__(256, 2) void attn_mma() {
    extern __shared__ __half sm[];
    uint32_t sb = smem_u32(sm);
    int tid = threadIdx.x, lane = tid & 31, w = tid >> 5;
    int q0 = blockIdx.x * 128;
    int b = blockIdx.y >> 4, hd = blockIdx.y & 15;

    uint32_t tQ = sb;
    const uint32_t kvb0 = sb + 2 * AQ;

    // Q tile -> smem (joins cp group 0)
    #pragma unroll
    for (int i = 0; i < 4; i++) {
        int idx = tid + i * 256;
        int row = idx >> 3, c = idx & 7;
        cp16(tQ + row * (ASTR * 2) + c * 16,
             g_q + (size_t)(b * Tt + q0 + row) * 1024 + hd * 64 + c * 8);
    }

    auto issueKV = [&](int kt, int buf) {
        uint32_t dbase = kvb0 + (uint32_t)buf * (ASTAGE * 2);
        int kv0 = kt * 128;
        #pragma unroll
        for (int i = 0; i < 8; i++) {
            int idx = tid + i * 256;        // 0..2047
            if (idx < 1024) {               // K: 128 rows x 8 cp16
                int r = idx >> 3, c = idx & 7;
                cp16(dbase + r * (ASTR * 2) + c * 16,
                     g_k + (size_t)(b * Tt + kv0 + r) * 1024 + hd * 64 + c * 8);
            } else {                        // V^T: 64 rows x 16 cp16
                int j = idx - 1024;
                int r = j >> 4, c = j & 15;
                cp16(dbase + AK * 2 + r * (VSTR * 2) + c * 16,
                     g_vt + (size_t)(b * 1024 + hd * 64 + r) * Tt + kv0 + c * 8);
            }
        }
        CP_COMMIT();
    };

    float o[8][4];
    #pragma unroll
    for (int t = 0; t < 8; t++)
        #pragma unroll
        for (int j = 0; j < 4; j++) o[t][j] = 0.0f;
    float lacc0 = 0.0f, lacc1 = 0.0f;
    uint32_t qf[4][4];   // hoisted Q fragments (one per ks)

    int rowg = b * Tt + q0 + w * 16 + (lane >> 2);

    issueKV(0, 0);

    for (int kt = 0; kt < 16; kt++) {
        CP_WAIT0();
        __syncthreads();
        if (kt + 1 < 16) issueKV(kt + 1, (kt + 1) & 1);
        if (kt == 0) {
            #pragma unroll
            for (int ks = 0; ks < 4; ks++) {
                uint32_t ao = (uint32_t)(w * 16 + (lane & 15)) * (ASTR * 2)
                            + ks * 32 + (lane >> 4) * 16;
                ldm4(qf[ks], tQ + ao);
            }
        }

        uint32_t kb = kvb0 + (uint32_t)(kt & 1) * (ASTAGE * 2);
        uint32_t tK = kb, tV = kb + AK * 2;

        #pragma unroll
        for (int half = 0; half < 2; half++) {
            // ---- S = Q @ K^T over this 64-kv half ----
            float s[8][4];
            #pragma unroll
            for (int t = 0; t < 8; t++)
                #pragma unroll
                for (int j = 0; j < 4; j++) s[t][j] = 0.0f;
            #pragma unroll
            for (int ks = 0; ks < 4; ks++) {
                #pragma unroll
                for (int pp = 0; pp < 2; pp++) {
                    uint32_t bo0 = (uint32_t)(half * 64 + 2 * pp * 16 + (lane & 15))
                                   * (ASTR * 2) + ks * 32 + (lane >> 4) * 16;
                    uint32_t bo1 = bo0 + 16 * (ASTR * 2);
                    uint32_t k0[4], k1[4];
                    ldm4(k0, tK + bo0); ldm4(k1, tK + bo1);
                    mma16816(s[4 * pp + 0], qf[ks], k0[0], k0[2]);
                    mma16816(s[4 * pp + 1], qf[ks], k0[1], k0[3]);
                    mma16816(s[4 * pp + 2], qf[ks], k1[0], k1[2]);
                    mma16816(s[4 * pp + 3], qf[ks], k1[1], k1[3]);
                }
            }

            // ---- softmax in registers, P fp16 fragments ----
            uint32_t mw0 = g_mbits[(size_t)rowg * 64 + kt * 4 + 2 * half];
            uint32_t mw1 = g_mbits[(size_t)rowg * 64 + kt * 4 + 2 * half + 1];
            uint32_t mw2 = g_mbits[(size_t)(rowg + 8) * 64 + kt * 4 + 2 * half];
            uint32_t mw3 = g_mbits[(size_t)(rowg + 8) * 64 + kt * 4 + 2 * half + 1];

            uint32_t af[4][4];
            #pragma unroll
            for (int t = 0; t < 8; t++) {
                int cb = 8 * t + 2 * (lane & 3);
                uint32_t wa = (t < 4) ? mw0 : mw1;
                uint32_t wb = (t < 4) ? mw2 : mw3;
                int bit = cb & 31;
                float p0 = ((wa >> bit) & 1u)       ? __expf(s[t][0] * 0.125f) : 0.0f;
                float p1 = ((wa >> (bit + 1)) & 1u) ? __expf(s[t][1] * 0.125f) : 0.0f;
                float p2 = ((wb >> bit) & 1u)       ? __expf(s[t][2] * 0.125f) : 0.0f;
                float p3 = ((wb >> (bit + 1)) & 1u) ? __expf(s[t][3] * 0.125f) : 0.0f;
                lacc0 += p0 + p1;
                lacc1 += p2 + p3;
                int u = t >> 1, k = (t & 1) * 2;
                af[u][k]     = packhf(p0, p1);
                af[u][k + 1] = packhf(p2, p3);
            }

            // ---- O += P @ V over this half ----
            #pragma unroll
            for (int u = 0; u < 4; u++) {
                #pragma unroll
                for (int pp = 0; pp < 2; pp++) {
                    uint32_t bo0 = (uint32_t)(2 * pp * 16 + (lane & 15)) * (VSTR * 2)
                                 + half * 128 + u * 32 + (lane >> 4) * 16;
                    uint32_t bo1 = bo0 + 16 * (VSTR * 2);
                    uint32_t v0[4], v1[4];
                    ldm4(v0, tV + bo0); ldm4(v1, tV + bo1);
                    mma16816(o[4 * pp + 0], af[u], v0[0], v0[2]);
                    mma16816(o[4 * pp + 1], af[u], v0[1], v0[3]);
                    mma16816(o[4 * pp + 2], af[u], v1[0], v1[2]);
                    mma16816(o[4 * pp + 3], af[u], v1[1], v1[3]);
                }
            }
        }
    }

    lacc0 += __shfl_xor_sync(0xffffffffu, lacc0, 1);
    lacc0 += __shfl_xor_sync(0xffffffffu, lacc0, 2);
    lacc1 += __shfl_xor_sync(0xffffffffu, lacc1, 1);
    lacc1 += __shfl_xor_sync(0xffffffffu, lacc1, 2);
    float inv0 = 1.0f / lacc0, inv1 = 1.0f / lacc1;

    int row = q0 + w * 16 + (lane >> 2);
    #pragma unroll
    for (int t = 0; t < 8; t++) {
        int col = hd * 64 + 8 * t + 2 * (lane & 3);
        size_t o0 = (size_t)(b * Tt + row) * 1024 + col;
        size_t o1 = (size_t)(b * Tt + row + 8) * 1024 + col;
        *(uint32_t*)(g_z + o0) = packhf(o[t][0] * inv0, o[t][1] * inv0);
        *(uint32_t*)(g_z + o1) = packhf(o[t][2] * inv1, o[t][3] * inv1);
    }
}

// ===========================================================================
extern "C" void kernel_launch(void* const* d_in, const int* in_sizes, int n_in,
                              void* d_out, int out_size)
{
    const float* embed = (const float*)d_in[0];
    const int*   mask  = (const int*)d_in[1];
    const float* Wq = (const float*)d_in[2];
    const float* bq = (const float*)d_in[3];
    const float* Wk = (const float*)d_in[4];
    const float* bk = (const float*)d_in[5];
    const float* Wv = (const float*)d_in[6];
    const float* bv = (const float*)d_in[7];
    const float* Wz = (const float*)d_in[8];
    const float* bz = (const float*)d_in[9];
    float* out = (float*)d_out;

    __half *e, *wt, *q, *k, *vt, *z;
    uint32_t* mbits;
    cudaGetSymbolAddress((void**)&e, g_e);
    cudaGetSymbolAddress((void**)&wt, g_w);
    cudaGetSymbolAddress((void**)&q, g_q);
    cudaGetSymbolAddress((void**)&k, g_k);
    cudaGetSymbolAddress((void**)&vt, g_vt);
    cudaGetSymbolAddress((void**)&z, g_z);
    cudaGetSymbolAddress((void**)&mbits, g_mbits);

    cudaFuncSetAttribute(gemm_qkv, cudaFuncAttributeMaxDynamicSharedMemorySize,
                         GEMM_SMEM_BYTES);
    cudaFuncSetAttribute(gemm_out, cudaFuncAttributeMaxDynamicSharedMemorySize,
                         GEMM_SMEM_BYTES);
    cudaFuncSetAttribute(attn_mma, cudaFuncAttributeMaxDynamicSharedMemorySize,
                         ATTN_SMEM_BYTES);

    const size_t WSZ = (size_t)1024 * 1024;

    // Preps
    conv_f16<<<(Mtot * KDIM / 4 + 255) / 256, 256>>>(embed, e, Mtot * KDIM / 4);
    dim3 tb(32, 8), tg4(32, 32, 4);
    trans4<<<tg4, tb>>>(Wq, Wk, Wv, Wz, wt);
    pack_mask<<<(Bb * Tt * Tt) / 256, 256>>>(mask, mbits);

    // Fused Q/K/V projections (128x128 tiles)
    gemm_qkv<<<dim3(8, 32, 3), 256, GEMM_SMEM_BYTES>>>(
        e, wt, bq, bk, bv, q, k, vt);

    // Attention
    attn_mma<<<dim3(16, 32), 256, ATTN_SMEM_BYTES>>>();

    // Output projection -> d_out (fp32)
    gemm_out<<<dim3(8, 32), 256, GEMM_SMEM_BYTES>>>(
        z, wt + 3 * WSZ, bz, out);
}

// round 15
// speedup vs baseline: 6.0304x; 1.0251x over previous
#include <cuda_runtime.h>
#include <cuda_fp16.h>
#include <cstdint>
#include <math.h>

#define Bb 2
#define Tt 2048
#define Hh 16
#define Mtot 4096
#define KDIM 1024

// ===========================================================================
// Helpers
// ===========================================================================
__device__ __forceinline__ uint32_t smem_u32(const void* p) {
    uint32_t a;
    asm("{ .reg .u64 t; cvta.to.shared.u64 t, %1; cvt.u32.u64 %0, t; }"
        : "=r"(a) : "l"(p));
    return a;
}
__device__ __forceinline__ void cp16(uint32_t dst, const void* src) {
    asm volatile("cp.async.cg.shared.global [%0], [%1], 16;" :: "r"(dst), "l"(src));
}
#define CP_COMMIT() asm volatile("cp.async.commit_group;" ::: "memory")
#define CP_WAIT0()  asm volatile("cp.async.wait_group 0;" ::: "memory")

__device__ __forceinline__ void ldm4(uint32_t* r, uint32_t a) {
    asm volatile("ldmatrix.sync.aligned.m8n8.x4.shared.b16 {%0,%1,%2,%3}, [%4];"
        : "=r"(r[0]), "=r"(r[1]), "=r"(r[2]), "=r"(r[3]) : "r"(a));
}
__device__ __forceinline__ void mma16816(float* d, const uint32_t* a,
                                         uint32_t b0, uint32_t b1) {
    asm volatile("mma.sync.aligned.m16n8k16.row.col.f32.f16.f16.f32 "
        "{%0,%1,%2,%3}, {%4,%5,%6,%7}, {%8,%9}, {%0,%1,%2,%3};"
        : "+f"(d[0]), "+f"(d[1]), "+f"(d[2]), "+f"(d[3])
        : "r"(a[0]), "r"(a[1]), "r"(a[2]), "r"(a[3]), "r"(b0), "r"(b1));
}

__device__ __forceinline__ uint32_t packhf(float a, float b) {
    __half2 t; t.x = __float2half(a); t.y = __float2half(b);
    return *(uint32_t*)&t;
}

// ===========================================================================
// Scratch (device globals) — everything single fp16
// ===========================================================================
__device__ __half g_e[(size_t)Mtot * KDIM];                 // embed
__device__ __half g_w[(size_t)4 * 1024 * 1024];             // W^T x4
__device__ __half g_q[(size_t)Mtot * KDIM];                 // Q (pre-scaled by 1/8)
__device__ __half g_k[(size_t)Mtot * KDIM];                 // K
__device__ __half g_vt[(size_t)Mtot * KDIM];                // V^T [b][n][t]
__device__ __half g_z[(size_t)Mtot * KDIM];                 // Z
__device__ uint32_t g_mbits[(size_t)Bb * Tt * (Tt / 32)];

// ===========================================================================
// Fused prep kernel: conv_f16 (blocks [0,4096)), trans4 ([4096,8192)),
// pack_mask ([8192,40960)). All 256-thread blocks.
// ===========================================================================
__global__ void fused_prep(const float* __restrict__ embed,
                           const float* __restrict__ W0, const float* __restrict__ W1,
                           const float* __restrict__ W2, const float* __restrict__ W3,
                           const int* __restrict__ m,
                           __half* __restrict__ e, __half* __restrict__ T,
                           uint32_t* __restrict__ bits)
{
    int blk = blockIdx.x;
    int tid = threadIdx.x;
    if (blk < 4096) {
        // conv_f16: n4 = Mtot*KDIM/4 = 1048576 elements of float4
        int i = blk * 256 + tid;
        float4 v = ((const float4*)embed)[i];
        ((uint32_t*)e)[2 * i]     = packhf(v.x, v.y);
        ((uint32_t*)e)[2 * i + 1] = packhf(v.z, v.w);
    } else if (blk < 8192) {
        // trans4: 1024 blocks per matrix (32x32 grid of 32x32 tiles)
        __shared__ float t[32][33];
        int b = blk - 4096;
        int z = b >> 10, rem = b & 1023;
        int bx = rem & 31, by = rem >> 5;
        const float* W = (z == 0) ? W0 : (z == 1) ? W1 : (z == 2) ? W2 : W3;
        size_t dbase = (size_t)z * 1024 * 1024;
        int tx = tid & 31, ty = tid >> 5;   // (32, 8)
        int x0 = bx * 32, y0 = by * 32;
        #pragma unroll
        for (int i = 0; i < 32; i += 8)
            t[ty + i][tx] = W[(size_t)(y0 + ty + i) * 1024 + x0 + tx];
        __syncthreads();
        #pragma unroll
        for (int i = 0; i < 32; i += 8) {
            float v = t[tx][ty + i];
            T[dbase + (size_t)(x0 + ty + i) * 1024 + y0 + tx] = __float2half(v);
        }
    } else {
        // pack_mask: (Bb*Tt*Tt)/256 = 32768 blocks
        int i = (blk - 8192) * 256 + tid;
        uint32_t bal = __ballot_sync(0xffffffffu, m[i] != 0);
        if ((tid & 31) == 0) bits[i >> 5] = bal;
    }
}

// ===========================================================================
// GEMM core: 128x128 CTA tile, 8 warps (4m x 2n), warp tile 32x64.
// KC=64, 2-stage, 1 barrier/chunk. (unchanged)
// ===========================================================================
#define GSTR2 72
#define GAEL (128 * GSTR2)
#define GSTAGE (2 * GAEL)
#define GEMM_SMEM_BYTES (2 * GSTAGE * 2) // 73728 B

__device__ __forceinline__ void gemm_core(
    uint32_t sb, int tid, int lane, int wm, int wn,
    const __half* __restrict__ A, const __half* __restrict__ B,
    int m0, int n0, float acc[2][8][4])
{
    const __half* srcA = A + (size_t)m0 * KDIM;
    const __half* srcB = B + (size_t)n0 * KDIM;

    auto issue = [&](int ch, int buf) {
        uint32_t dbase = sb + (uint32_t)buf * (GSTAGE * 2);
        #pragma unroll
        for (int i = 0; i < 8; i++) {
            int idx = tid + i * 256;
            int t = idx >> 10;
            int r = (idx >> 3) & 127, c = idx & 7;
            const __half* src = (t ? srcB : srcA) + (size_t)r * KDIM + ch * 64 + c * 8;
            cp16(dbase + t * (GAEL * 2) + r * (GSTR2 * 2) + c * 16, src);
        }
        CP_COMMIT();
    };

    issue(0, 0);
    const int NC = KDIM / 64;   // 16
    for (int ch = 0; ch < NC; ch++) {
        CP_WAIT0();
        __syncthreads();
        if (ch + 1 < NC) issue(ch + 1, (ch + 1) & 1);

        uint32_t bb = sb + (uint32_t)(ch & 1) * (GSTAGE * 2);
        uint32_t tA = bb, tB = bb + GAEL * 2;
        #pragma unroll
        for (int ks = 0; ks < 4; ks++) {
            uint32_t ao = (uint32_t)(wm * 32 + (lane & 15)) * (GSTR2 * 2)
                        + ks * 32 + (lane >> 4) * 16;
            uint32_t a0[4], a1[4];
            ldm4(a0, tA + ao);
            ldm4(a1, tA + ao + 16 * (GSTR2 * 2));
            #pragma unroll
            for (int p = 0; p < 4; p++) {
                uint32_t bo = (uint32_t)(wn * 64 + p * 16 + (lane & 15)) * (GSTR2 * 2)
                            + ks * 32 + (lane >> 4) * 16;
                uint32_t bf[4];
                ldm4(bf, tB + bo);
                mma16816(acc[0][2 * p],     a0, bf[0], bf[2]);
                mma16816(acc[0][2 * p + 1], a0, bf[1], bf[3]);
                mma16816(acc[1][2 * p],     a1, bf[0], bf[2]);
                mma16816(acc[1][2 * p + 1], a1, bf[1], bf[3]);
            }
        }
    }
}

// Fused Q/K/V projections. z=0: Q (pre-scaled 1/8); z=1: K; z=2: V^T via smem
// transpose for coalesced stores.
#define VT_STR 136   // transpose buffer row stride (halfs)

__global__ __launch_bounds__(256, 2) void gemm_qkv(
    const __half* __restrict__ A, const __half* __restrict__ Wt,
    const float* __restrict__ bq, const float* __restrict__ bk,
    const float* __restrict__ bv,
    __half* __restrict__ q, __half* __restrict__ k, __half* __restrict__ vt)
{
    extern __shared__ __half sm[];
    uint32_t sb = smem_u32(sm);
    int tid = threadIdx.x, lane = tid & 31, w = tid >> 5;
    int wm = w & 3, wn = w >> 2;
    int m0 = blockIdx.y * 128, n0 = blockIdx.x * 128;
    int z = blockIdx.z;
    const size_t WSZ = (size_t)1024 * 1024;
    const __half* B = Wt + (size_t)z * WSZ;
    const float* bias = (z == 0) ? bq : (z == 1) ? bk : bv;

    float acc[2][8][4];
    #pragma unroll
    for (int mf = 0; mf < 2; mf++)
        #pragma unroll
        for (int na = 0; na < 8; na++)
            #pragma unroll
            for (int j = 0; j < 4; j++) acc[mf][na][j] = 0.0f;

    gemm_core(sb, tid, lane, wm, wn, A, B, m0, n0, acc);

    if (z == 0 || z == 1) {
        float scale = (z == 0) ? 0.125f : 1.0f;
        __half* O = (z == 0) ? q : k;
        #pragma unroll
        for (int mf = 0; mf < 2; mf++)
        #pragma unroll
        for (int na = 0; na < 8; na++) {
            int col = n0 + wn * 64 + na * 8 + (lane & 3) * 2;
            int rbase = m0 + wm * 32 + mf * 16 + (lane >> 2);
            float v0 = (acc[mf][na][0] + bias[col]) * scale;
            float v1 = (acc[mf][na][1] + bias[col + 1]) * scale;
            float v2 = (acc[mf][na][2] + bias[col]) * scale;
            float v3 = (acc[mf][na][3] + bias[col + 1]) * scale;
            *(uint32_t*)(O + (size_t)rbase * 1024 + col)       = packhf(v0, v1);
            *(uint32_t*)(O + (size_t)(rbase + 8) * 1024 + col) = packhf(v2, v3);
        }
    } else {
        // V: transpose through smem (pipeline buffers are dead now), then
        // write V^T [n][m] with coalesced 16B stores.
        __syncthreads();   // all warps done reading pipeline smem
        __half* tb = sm;   // [128 n][VT_STR m-halfs] = 34.8 KB
        #pragma unroll
        for (int mf = 0; mf < 2; mf++)
        #pragma unroll
        for (int na = 0; na < 8; na++) {
            int nloc = wn * 64 + na * 8 + (lane & 3) * 2;
            int mloc = wm * 32 + mf * 16 + (lane >> 2);
            float v0 = acc[mf][na][0] + bias[n0 + nloc];
            float v1 = acc[mf][na][1] + bias[n0 + nloc + 1];
            float v2 = acc[mf][na][2] + bias[n0 + nloc];
            float v3 = acc[mf][na][3] + bias[n0 + nloc + 1];
            tb[nloc * VT_STR + mloc]           = __float2half(v0);
            tb[(nloc + 1) * VT_STR + mloc]     = __float2half(v1);
            tb[nloc * VT_STR + mloc + 8]       = __float2half(v2);
            tb[(nloc + 1) * VT_STR + mloc + 8] = __float2half(v3);
        }
        __syncthreads();
        // write: 128 n-rows x 128 m halfs = 128 x 16 uint4 -> 2048 uint4
        int bi = m0 >> 11, tbase = m0 & 2047;
        #pragma unroll
        for (int i = 0; i < 8; i++) {
            int idx = tid + i * 256;       // 0..2047
            int n = idx >> 4, c = idx & 15;
            uint4 v = *(const uint4*)(tb + n * VT_STR + c * 8);
            *(uint4*)(vt + ((size_t)bi * 1024 + n0 + n) * 2048 + tbase + c * 8) = v;
        }
    }
}

// Output projection: fp32 straight to d_out.
__global__ __launch_bounds__(256, 2) void gemm_out(
    const __half* __restrict__ A, const __half* __restrict__ B,
    const float* __restrict__ bias, float* __restrict__ outF)
{
    extern __shared__ __half sm[];
    uint32_t sb = smem_u32(sm);
    int tid = threadIdx.x, lane = tid & 31, w = tid >> 5;
    int wm = w & 3, wn = w >> 2;
    int m0 = blockIdx.y * 128, n0 = blockIdx.x * 128;

    float acc[2][8][4];
    #pragma unroll
    for (int mf = 0; mf < 2; mf++)
        #pragma unroll
        for (int na = 0; na < 8; na++)
            #pragma unroll
            for (int j = 0; j < 4; j++) acc[mf][na][j] = 0.0f;

    gemm_core(sb, tid, lane, wm, wn, A, B, m0, n0, acc);

    #pragma unroll
    for (int mf = 0; mf < 2; mf++)
    #pragma unroll
    for (int na = 0; na < 8; na++) {
        int col = n0 + wn * 64 + na * 8 + (lane & 3) * 2;
        int rbase = m0 + wm * 32 + mf * 16 + (lane >> 2);
        float b0 = bias[col], b1 = bias[col + 1];
        *(float2*)(outF + (size_t)rbase * 1024 + col) =
            make_float2(acc[mf][na][0] + b0, acc[mf][na][1] + b1);
        *(float2*)(outF + (size_t)(rbase + 8) * 1024 + col) =
            make_float2(acc[mf][na][2] + b0, acc[mf][na][3] + b1);
    }
}

// ===========================================================================
// Attention — FA-2, single fp16; KV tile 128, hoisted Q fragments.
// Q is pre-scaled by 1/8 -> no scale in softmax chain.
// ===========================================================================
#define ASTR 72
#define VSTR 136
#define AQ   (128 * ASTR)
#define AK   (128 * ASTR)
#define AV   (64 * VSTR)
#define ASTAGE (AK + AV)
#define ATTN_SMEM_BYTES ((AQ + 2 * ASTAGE) * 2)   // 90112 B

__global__ __launch_bounds__(256, 2) void attn_mma() {
    extern __shared__ __half sm[];
    uint32_t sb = smem_u32(sm);
    int tid = threadIdx.x, lane = tid & 31, w = tid >> 5;
    int q0 = blockIdx.x * 128;
    int b = blockIdx.y >> 4, hd = blockIdx.y & 15;

    uint32_t tQ = sb;
    const uint32_t kvb0 = sb + 2 * AQ;

    #pragma unroll
    for (int i = 0; i < 4; i++) {
        int idx = tid + i * 256;
        int row = idx >> 3, c = idx & 7;
        cp16(tQ + row * (ASTR * 2) + c * 16,
             g_q + (size_t)(b * Tt + q0 + row) * 1024 + hd * 64 + c * 8);
    }

    auto issueKV = [&](int kt, int buf) {
        uint32_t dbase = kvb0 + (uint32_t)buf * (ASTAGE * 2);
        int kv0 = kt * 128;
        #pragma unroll
        for (int i = 0; i < 8; i++) {
            int idx = tid + i * 256;
            if (idx < 1024) {
                int r = idx >> 3, c = idx & 7;
                cp16(dbase + r * (ASTR * 2) + c * 16,
                     g_k + (size_t)(b * Tt + kv0 + r) * 1024 + hd * 64 + c * 8);
            } else {
                int j = idx - 1024;
                int r = j >> 4, c = j & 15;
                cp16(dbase + AK * 2 + r * (VSTR * 2) + c * 16,
                     g_vt + (size_t)(b * 1024 + hd * 64 + r) * Tt + kv0 + c * 8);
            }
        }
        CP_COMMIT();
    };

    float o[8][4];
    #pragma unroll
    for (int t = 0; t < 8; t++)
        #pragma unroll
        for (int j = 0; j < 4; j++) o[t][j] = 0.0f;
    float lacc0 = 0.0f, lacc1 = 0.0f;
    uint32_t qf[4][4];

    int rowg = b * Tt + q0 + w * 16 + (lane >> 2);

    issueKV(0, 0);

    for (int kt = 0; kt < 16; kt++) {
        CP_WAIT0();
        __syncthreads();
        if (kt + 1 < 16) issueKV(kt + 1, (kt + 1) & 1);
        if (kt == 0) {
            #pragma unroll
            for (int ks = 0; ks < 4; ks++) {
                uint32_t ao = (uint32_t)(w * 16 + (lane & 15)) * (ASTR * 2)
                            + ks * 32 + (lane >> 4) * 16;
                ldm4(qf[ks], tQ + ao);
            }
        }

        uint32_t kb = kvb0 + (uint32_t)(kt & 1) * (ASTAGE * 2);
        uint32_t tK = kb, tV = kb + AK * 2;

        #pragma unroll
        for (int half = 0; half < 2; half++) {
            float s[8][4];
            #pragma unroll
            for (int t = 0; t < 8; t++)
                #pragma unroll
                for (int j = 0; j < 4; j++) s[t][j] = 0.0f;
            #pragma unroll
            for (int ks = 0; ks < 4; ks++) {
                #pragma unroll
                for (int pp = 0; pp < 2; pp++) {
                    uint32_t bo0 = (uint32_t)(half * 64 + 2 * pp * 16 + (lane & 15))
                                   * (ASTR * 2) + ks * 32 + (lane >> 4) * 16;
                    uint32_t bo1 = bo0 + 16 * (ASTR * 2);
                    uint32_t k0[4], k1[4];
                    ldm4(k0, tK + bo0); ldm4(k1, tK + bo1);
                    mma16816(s[4 * pp + 0], qf[ks], k0[0], k0[2]);
                    mma16816(s[4 * pp + 1], qf[ks], k0[1], k0[3]);
                    mma16816(s[4 * pp + 2], qf[ks], k1[0], k1[2]);
                    mma16816(s[4 * pp + 3], qf[ks], k1[1], k1[3]);
                }
            }

            uint32_t mw0 = g_mbits[(size_t)rowg * 64 + kt * 4 + 2 * half];
            uint32_t mw1 = g_mbits[(size_t)rowg * 64 + kt * 4 + 2 * half + 1];
            uint32_t mw2 = g_mbits[(size_t)(rowg + 8) * 64 + kt * 4 + 2 * half];
            uint32_t mw3 = g_mbits[(size_t)(rowg + 8) * 64 + kt * 4 + 2 * half + 1];

            uint32_t af[4][4];
            #pragma unroll
            for (int t = 0; t < 8; t++) {
                int cb = 8 * t + 2 * (lane & 3);
                uint32_t wa = (t < 4) ? mw0 : mw1;
                uint32_t wb = (t < 4) ? mw2 : mw3;
                int bit = cb & 31;
                float p0 = ((wa >> bit) & 1u)       ? __expf(s[t][0]) : 0.0f;
                float p1 = ((wa >> (bit + 1)) & 1u) ? __expf(s[t][1]) : 0.0f;
                float p2 = ((wb >> bit) & 1u)       ? __expf(s[t][2]) : 0.0f;
                float p3 = ((wb >> (bit + 1)) & 1u) ? __expf(s[t][3]) : 0.0f;
                lacc0 += p0 + p1;
                lacc1 += p2 + p3;
                int u = t >> 1, k = (t & 1) * 2;
                af[u][k]     = packhf(p0, p1);
                af[u][k + 1] = packhf(p2, p3);
            }

            #pragma unroll
            for (int u = 0; u < 4; u++) {
                #pragma unroll
                for (int pp = 0; pp < 2; pp++) {
                    uint32_t bo0 = (uint32_t)(2 * pp * 16 + (lane & 15)) * (VSTR * 2)
                                 + half * 128 + u * 32 + (lane >> 4) * 16;
                    uint32_t bo1 = bo0 + 16 * (VSTR * 2);
                    uint32_t v0[4], v1[4];
                    ldm4(v0, tV + bo0); ldm4(v1, tV + bo1);
                    mma16816(o[4 * pp + 0], af[u], v0[0], v0[2]);
                    mma16816(o[4 * pp + 1], af[u], v0[1], v0[3]);
                    mma16816(o[4 * pp + 2], af[u], v1[0], v1[2]);
                    mma16816(o[4 * pp + 3], af[u], v1[1], v1[3]);
                }
            }
        }
    }

    lacc0 += __shfl_xor_sync(0xffffffffu, lacc0, 1);
    lacc0 += __shfl_xor_sync(0xffffffffu, lacc0, 2);
    lacc1 += __shfl_xor_sync(0xffffffffu, lacc1, 1);
    lacc1 += __shfl_xor_sync(0xffffffffu, lacc1, 2);
    float inv0 = 1.0f / lacc0, inv1 = 1.0f / lacc1;

    int row = q0 + w * 16 + (lane >> 2);
    #pragma unroll
    for (int t = 0; t < 8; t++) {
        int col = hd * 64 + 8 * t + 2 * (lane & 3);
        size_t o0 = (size_t)(b * Tt + row) * 1024 + col;
        size_t o1 = (size_t)(b * Tt + row + 8) * 1024 + col;
        *(uint32_t*)(g_z + o0) = packhf(o[t][0] * inv0, o[t][1] * inv0);
        *(uint32_t*)(g_z + o1) = packhf(o[t][2] * inv1, o[t][3] * inv1);
    }
}

// ===========================================================================
extern "C" void kernel_launch(void* const* d_in, const int* in_sizes, int n_in,
                              void* d_out, int out_size)
{
    const float* embed = (const float*)d_in[0];
    const int*   mask  = (const int*)d_in[1];
    const float* Wq = (const float*)d_in[2];
    const float* bq = (const float*)d_in[3];
    const float* Wk = (const float*)d_in[4];
    const float* bk = (const float*)d_in[5];
    const float* Wv = (const float*)d_in[6];
    const float* bv = (const float*)d_in[7];
    const float* Wz = (const float*)d_in[8];
    const float* bz = (const float*)d_in[9];
    float* out = (float*)d_out;

    __half *e, *wt, *q, *k, *vt, *z;
    uint32_t* mbits;
    cudaGetSymbolAddress((void**)&e, g_e);
    cudaGetSymbolAddress((void**)&wt, g_w);
    cudaGetSymbolAddress((void**)&q, g_q);
    cudaGetSymbolAddress((void**)&k, g_k);
    cudaGetSymbolAddress((void**)&vt, g_vt);
    cudaGetSymbolAddress((void**)&z, g_z);
    cudaGetSymbolAddress((void**)&mbits, g_mbits);

    cudaFuncSetAttribute(gemm_qkv, cudaFuncAttributeMaxDynamicSharedMemorySize,
                         GEMM_SMEM_BYTES);
    cudaFuncSetAttribute(gemm_out, cudaFuncAttributeMaxDynamicSharedMemorySize,
                         GEMM_SMEM_BYTES);
    cudaFuncSetAttribute(attn_mma, cudaFuncAttributeMaxDynamicSharedMemorySize,
                         ATTN_SMEM_BYTES);

    const size_t WSZ = (size_t)1024 * 1024;

    // Single fused prep launch: conv (4096) + trans4 (4096) + pack (32768)
    fused_prep<<<40960, 256>>>(embed, Wq, Wk, Wv, Wz, mask, e, wt, mbits);

    // Fused Q/K/V projections (128x128 tiles)
    gemm_qkv<<<dim3(8, 32, 3), 256, GEMM_SMEM_BYTES>>>(
        e, wt, bq, bk, bv, q, k, vt);

    // Attention
    attn_mma<<<dim3(16, 32), 256, ATTN_SMEM_BYTES>>>();

    // Output projection -> d_out (fp32)
    gemm_out<<<dim3(8, 32), 256, GEMM_SMEM_BYTES>>>(
        z, wt + 3 * WSZ, bz, out);
}

// round 16
// speedup vs baseline: 6.0611x; 1.0051x over previous
#include <cuda_runtime.h>
#include <cuda_fp16.h>
#include <cstdint>
#include <math.h>

#define Bb 2
#define Tt 2048
#define Hh 16
#define Mtot 4096
#define KDIM 1024

// ===========================================================================
// Helpers
// ===========================================================================
__device__ __forceinline__ uint32_t smem_u32(const void* p) {
    uint32_t a;
    asm("{ .reg .u64 t; cvta.to.shared.u64 t, %1; cvt.u32.u64 %0, t; }"
        : "=r"(a) : "l"(p));
    return a;
}
__device__ __forceinline__ void cp16(uint32_t dst, const void* src) {
    asm volatile("cp.async.cg.shared.global [%0], [%1], 16;" :: "r"(dst), "l"(src));
}
#define CP_COMMIT() asm volatile("cp.async.commit_group;" ::: "memory")
#define CP_WAIT0()  asm volatile("cp.async.wait_group 0;" ::: "memory")

__device__ __forceinline__ void ldm4(uint32_t* r, uint32_t a) {
    asm volatile("ldmatrix.sync.aligned.m8n8.x4.shared.b16 {%0,%1,%2,%3}, [%4];"
        : "=r"(r[0]), "=r"(r[1]), "=r"(r[2]), "=r"(r[3]) : "r"(a));
}
__device__ __forceinline__ void mma16816(float* d, const uint32_t* a,
                                         uint32_t b0, uint32_t b1) {
    asm volatile("mma.sync.aligned.m16n8k16.row.col.f32.f16.f16.f32 "
        "{%0,%1,%2,%3}, {%4,%5,%6,%7}, {%8,%9}, {%0,%1,%2,%3};"
        : "+f"(d[0]), "+f"(d[1]), "+f"(d[2]), "+f"(d[3])
        : "r"(a[0]), "r"(a[1]), "r"(a[2]), "r"(a[3]), "r"(b0), "r"(b1));
}

__device__ __forceinline__ uint32_t packhf(float a, float b) {
    __half2 t; t.x = __float2half(a); t.y = __float2half(b);
    return *(uint32_t*)&t;
}

// ===========================================================================
// Scratch (device globals) — everything single fp16
// ===========================================================================
__device__ __half g_e[(size_t)Mtot * KDIM];                 // embed
__device__ __half g_w[(size_t)4 * 1024 * 1024];             // W^T x4
__device__ __half g_q[(size_t)Mtot * KDIM];                 // Q (pre-scaled 0.125*log2e)
__device__ __half g_k[(size_t)Mtot * KDIM];                 // K
__device__ __half g_vt[(size_t)Mtot * KDIM];                // V^T [b][n][t]
__device__ __half g_z[(size_t)Mtot * KDIM];                 // Z
__device__ uint32_t g_mbits[(size_t)Bb * Tt * (Tt / 32)];

// ===========================================================================
// Fused prep kernel (unchanged from R15)
// ===========================================================================
__global__ void fused_prep(const float* __restrict__ embed,
                           const float* __restrict__ W0, const float* __restrict__ W1,
                           const float* __restrict__ W2, const float* __restrict__ W3,
                           const int* __restrict__ m,
                           __half* __restrict__ e, __half* __restrict__ T,
                           uint32_t* __restrict__ bits)
{
    int blk = blockIdx.x;
    int tid = threadIdx.x;
    if (blk < 4096) {
        int i = blk * 256 + tid;
        float4 v = ((const float4*)embed)[i];
        ((uint32_t*)e)[2 * i]     = packhf(v.x, v.y);
        ((uint32_t*)e)[2 * i + 1] = packhf(v.z, v.w);
    } else if (blk < 8192) {
        __shared__ float t[32][33];
        int b = blk - 4096;
        int z = b >> 10, rem = b & 1023;
        int bx = rem & 31, by = rem >> 5;
        const float* W = (z == 0) ? W0 : (z == 1) ? W1 : (z == 2) ? W2 : W3;
        size_t dbase = (size_t)z * 1024 * 1024;
        int tx = tid & 31, ty = tid >> 5;
        int x0 = bx * 32, y0 = by * 32;
        #pragma unroll
        for (int i = 0; i < 32; i += 8)
            t[ty + i][tx] = W[(size_t)(y0 + ty + i) * 1024 + x0 + tx];
        __syncthreads();
        #pragma unroll
        for (int i = 0; i < 32; i += 8) {
            float v = t[tx][ty + i];
            T[dbase + (size_t)(x0 + ty + i) * 1024 + y0 + tx] = __float2half(v);
        }
    } else {
        int i = (blk - 8192) * 256 + tid;
        uint32_t bal = __ballot_sync(0xffffffffu, m[i] != 0);
        if ((tid & 31) == 0) bits[i >> 5] = bal;
    }
}

// ===========================================================================
// GEMM core: 128x128 CTA tile, KC=64, 2-stage (unchanged)
// ===========================================================================
#define GSTR2 72
#define GAEL (128 * GSTR2)
#define GSTAGE (2 * GAEL)
#define GEMM_SMEM_BYTES (2 * GSTAGE * 2) // 73728 B

__device__ __forceinline__ void gemm_core(
    uint32_t sb, int tid, int lane, int wm, int wn,
    const __half* __restrict__ A, const __half* __restrict__ B,
    int m0, int n0, float acc[2][8][4])
{
    const __half* srcA = A + (size_t)m0 * KDIM;
    const __half* srcB = B + (size_t)n0 * KDIM;

    auto issue = [&](int ch, int buf) {
        uint32_t dbase = sb + (uint32_t)buf * (GSTAGE * 2);
        #pragma unroll
        for (int i = 0; i < 8; i++) {
            int idx = tid + i * 256;
            int t = idx >> 10;
            int r = (idx >> 3) & 127, c = idx & 7;
            const __half* src = (t ? srcB : srcA) + (size_t)r * KDIM + ch * 64 + c * 8;
            cp16(dbase + t * (GAEL * 2) + r * (GSTR2 * 2) + c * 16, src);
        }
        CP_COMMIT();
    };

    issue(0, 0);
    const int NC = KDIM / 64;
    for (int ch = 0; ch < NC; ch++) {
        CP_WAIT0();
        __syncthreads();
        if (ch + 1 < NC) issue(ch + 1, (ch + 1) & 1);

        uint32_t bb = sb + (uint32_t)(ch & 1) * (GSTAGE * 2);
        uint32_t tA = bb, tB = bb + GAEL * 2;
        #pragma unroll
        for (int ks = 0; ks < 4; ks++) {
            uint32_t ao = (uint32_t)(wm * 32 + (lane & 15)) * (GSTR2 * 2)
                        + ks * 32 + (lane >> 4) * 16;
            uint32_t a0[4], a1[4];
            ldm4(a0, tA + ao);
            ldm4(a1, tA + ao + 16 * (GSTR2 * 2));
            #pragma unroll
            for (int p = 0; p < 4; p++) {
                uint32_t bo = (uint32_t)(wn * 64 + p * 16 + (lane & 15)) * (GSTR2 * 2)
                            + ks * 32 + (lane >> 4) * 16;
                uint32_t bf[4];
                ldm4(bf, tB + bo);
                mma16816(acc[0][2 * p],     a0, bf[0], bf[2]);
                mma16816(acc[0][2 * p + 1], a0, bf[1], bf[3]);
                mma16816(acc[1][2 * p],     a1, bf[0], bf[2]);
                mma16816(acc[1][2 * p + 1], a1, bf[1], bf[3]);
            }
        }
    }
}

// Fused Q/K/V projections. z=0: Q (scaled 0.125*log2e); z=1: K; z=2: V^T.
#define VT_STR 136

__global__ __launch_bounds__(256, 2) void gemm_qkv(
    const __half* __restrict__ A, const __half* __restrict__ Wt,
    const float* __restrict__ bq, const float* __restrict__ bk,
    const float* __restrict__ bv,
    __half* __restrict__ q, __half* __restrict__ k, __half* __restrict__ vt)
{
    extern __shared__ __half sm[];
    uint32_t sb = smem_u32(sm);
    int tid = threadIdx.x, lane = tid & 31, w = tid >> 5;
    int wm = w & 3, wn = w >> 2;
    int m0 = blockIdx.y * 128, n0 = blockIdx.x * 128;
    int z = blockIdx.z;
    const size_t WSZ = (size_t)1024 * 1024;
    const __half* B = Wt + (size_t)z * WSZ;
    const float* bias = (z == 0) ? bq : (z == 1) ? bk : bv;

    float acc[2][8][4];
    #pragma unroll
    for (int mf = 0; mf < 2; mf++)
        #pragma unroll
        for (int na = 0; na < 8; na++)
            #pragma unroll
            for (int j = 0; j < 4; j++) acc[mf][na][j] = 0.0f;

    gemm_core(sb, tid, lane, wm, wn, A, B, m0, n0, acc);

    if (z == 0 || z == 1) {
        // Q scale folds softmax 1/8 AND log2(e) so attention uses bare ex2.
        float scale = (z == 0) ? 0.125f * 1.44269504f : 1.0f;
        __half* O = (z == 0) ? q : k;
        #pragma unroll
        for (int mf = 0; mf < 2; mf++)
        #pragma unroll
        for (int na = 0; na < 8; na++) {
            int col = n0 + wn * 64 + na * 8 + (lane & 3) * 2;
            int rbase = m0 + wm * 32 + mf * 16 + (lane >> 2);
            float v0 = (acc[mf][na][0] + bias[col]) * scale;
            float v1 = (acc[mf][na][1] + bias[col + 1]) * scale;
            float v2 = (acc[mf][na][2] + bias[col]) * scale;
            float v3 = (acc[mf][na][3] + bias[col + 1]) * scale;
            *(uint32_t*)(O + (size_t)rbase * 1024 + col)       = packhf(v0, v1);
            *(uint32_t*)(O + (size_t)(rbase + 8) * 1024 + col) = packhf(v2, v3);
        }
    } else {
        __syncthreads();
        __half* tb = sm;
        #pragma unroll
        for (int mf = 0; mf < 2; mf++)
        #pragma unroll
        for (int na = 0; na < 8; na++) {
            int nloc = wn * 64 + na * 8 + (lane & 3) * 2;
            int mloc = wm * 32 + mf * 16 + (lane >> 2);
            float v0 = acc[mf][na][0] + bias[n0 + nloc];
            float v1 = acc[mf][na][1] + bias[n0 + nloc + 1];
            float v2 = acc[mf][na][2] + bias[n0 + nloc];
            float v3 = acc[mf][na][3] + bias[n0 + nloc + 1];
            tb[nloc * VT_STR + mloc]           = __float2half(v0);
            tb[(nloc + 1) * VT_STR + mloc]     = __float2half(v1);
            tb[nloc * VT_STR + mloc + 8]       = __float2half(v2);
            tb[(nloc + 1) * VT_STR + mloc + 8] = __float2half(v3);
        }
        __syncthreads();
        int bi = m0 >> 11, tbase = m0 & 2047;
        #pragma unroll
        for (int i = 0; i < 8; i++) {
            int idx = tid + i * 256;
            int n = idx >> 4, c = idx & 15;
            uint4 v = *(const uint4*)(tb + n * VT_STR + c * 8);
            *(uint4*)(vt + ((size_t)bi * 1024 + n0 + n) * 2048 + tbase + c * 8) = v;
        }
    }
}

// Output projection: fp32 straight to d_out.
__global__ __launch_bounds__(256, 2) void gemm_out(
    const __half* __restrict__ A, const __half* __restrict__ B,
    const float* __restrict__ bias, float* __restrict__ outF)
{
    extern __shared__ __half sm[];
    uint32_t sb = smem_u32(sm);
    int tid = threadIdx.x, lane = tid & 31, w = tid >> 5;
    int wm = w & 3, wn = w >> 2;
    int m0 = blockIdx.y * 128, n0 = blockIdx.x * 128;

    float acc[2][8][4];
    #pragma unroll
    for (int mf = 0; mf < 2; mf++)
        #pragma unroll
        for (int na = 0; na < 8; na++)
            #pragma unroll
            for (int j = 0; j < 4; j++) acc[mf][na][j] = 0.0f;

    gemm_core(sb, tid, lane, wm, wn, A, B, m0, n0, acc);

    #pragma unroll
    for (int mf = 0; mf < 2; mf++)
    #pragma unroll
    for (int na = 0; na < 8; na++) {
        int col = n0 + wn * 64 + na * 8 + (lane & 3) * 2;
        int rbase = m0 + wm * 32 + mf * 16 + (lane >> 2);
        float b0 = bias[col], b1 = bias[col + 1];
        *(float2*)(outF + (size_t)rbase * 1024 + col) =
            make_float2(acc[mf][na][0] + b0, acc[mf][na][1] + b1);
        *(float2*)(outF + (size_t)(rbase + 8) * 1024 + col) =
            make_float2(acc[mf][na][2] + b0, acc[mf][na][3] + b1);
    }
}

// ===========================================================================
// Attention — FA-2, single fp16; KV tile 128; halves software-pipelined:
// S(h0) -> sm(h0) -> S(h1) -> PV(h0) -> sm(h1) -> PV(h1). exp2f (ex2) softmax.
// ===========================================================================
#define ASTR 72
#define VSTR 136
#define AQ   (128 * ASTR)
#define AK   (128 * ASTR)
#define AV   (64 * VSTR)
#define ASTAGE (AK + AV)
#define ATTN_SMEM_BYTES ((AQ + 2 * ASTAGE) * 2)   // 90112 B

__global__ __launch_bounds__(256, 2) void attn_mma() {
    extern __shared__ __half sm[];
    uint32_t sb = smem_u32(sm);
    int tid = threadIdx.x, lane = tid & 31, w = tid >> 5;
    int q0 = blockIdx.x * 128;
    int b = blockIdx.y >> 4, hd = blockIdx.y & 15;

    uint32_t tQ = sb;
    const uint32_t kvb0 = sb + 2 * AQ;

    #pragma unroll
    for (int i = 0; i < 4; i++) {
        int idx = tid + i * 256;
        int row = idx >> 3, c = idx & 7;
        cp16(tQ + row * (ASTR * 2) + c * 16,
             g_q + (size_t)(b * Tt + q0 + row) * 1024 + hd * 64 + c * 8);
    }

    auto issueKV = [&](int kt, int buf) {
        uint32_t dbase = kvb0 + (uint32_t)buf * (ASTAGE * 2);
        int kv0 = kt * 128;
        #pragma unroll
        for (int i = 0; i < 8; i++) {
            int idx = tid + i * 256;
            if (idx < 1024) {
                int r = idx >> 3, c = idx & 7;
                cp16(dbase + r * (ASTR * 2) + c * 16,
                     g_k + (size_t)(b * Tt + kv0 + r) * 1024 + hd * 64 + c * 8);
            } else {
                int j = idx - 1024;
                int r = j >> 4, c = j & 15;
                cp16(dbase + AK * 2 + r * (VSTR * 2) + c * 16,
                     g_vt + (size_t)(b * 1024 + hd * 64 + r) * Tt + kv0 + c * 8);
            }
        }
        CP_COMMIT();
    };

    float o[8][4];
    #pragma unroll
    for (int t = 0; t < 8; t++)
        #pragma unroll
        for (int j = 0; j < 4; j++) o[t][j] = 0.0f;
    float lacc0 = 0.0f, lacc1 = 0.0f;
    uint32_t qf[4][4];

    int rowg = b * Tt + q0 + w * 16 + (lane >> 2);

    issueKV(0, 0);

    float s[8][4];
    uint32_t af[4][4];

    for (int kt = 0; kt < 16; kt++) {
        CP_WAIT0();
        __syncthreads();
        if (kt + 1 < 16) issueKV(kt + 1, (kt + 1) & 1);
        if (kt == 0) {
            #pragma unroll
            for (int ks = 0; ks < 4; ks++) {
                uint32_t ao = (uint32_t)(w * 16 + (lane & 15)) * (ASTR * 2)
                            + ks * 32 + (lane >> 4) * 16;
                ldm4(qf[ks], tQ + ao);
            }
        }

        uint32_t kb = kvb0 + (uint32_t)(kt & 1) * (ASTAGE * 2);
        uint32_t tK = kb, tV = kb + AK * 2;

        auto computeS = [&](int half) {
            #pragma unroll
            for (int t = 0; t < 8; t++)
                #pragma unroll
                for (int j = 0; j < 4; j++) s[t][j] = 0.0f;
            #pragma unroll
            for (int ks = 0; ks < 4; ks++) {
                #pragma unroll
                for (int pp = 0; pp < 2; pp++) {
                    uint32_t bo0 = (uint32_t)(half * 64 + 2 * pp * 16 + (lane & 15))
                                   * (ASTR * 2) + ks * 32 + (lane >> 4) * 16;
                    uint32_t bo1 = bo0 + 16 * (ASTR * 2);
                    uint32_t k0[4], k1[4];
                    ldm4(k0, tK + bo0); ldm4(k1, tK + bo1);
                    mma16816(s[4 * pp + 0], qf[ks], k0[0], k0[2]);
                    mma16816(s[4 * pp + 1], qf[ks], k0[1], k0[3]);
                    mma16816(s[4 * pp + 2], qf[ks], k1[0], k1[2]);
                    mma16816(s[4 * pp + 3], qf[ks], k1[1], k1[3]);
                }
            }
        };

        auto softmax = [&](int half) {
            uint32_t mw0 = g_mbits[(size_t)rowg * 64 + kt * 4 + 2 * half];
            uint32_t mw1 = g_mbits[(size_t)rowg * 64 + kt * 4 + 2 * half + 1];
            uint32_t mw2 = g_mbits[(size_t)(rowg + 8) * 64 + kt * 4 + 2 * half];
            uint32_t mw3 = g_mbits[(size_t)(rowg + 8) * 64 + kt * 4 + 2 * half + 1];
            #pragma unroll
            for (int t = 0; t < 8; t++) {
                int cb = 8 * t + 2 * (lane & 3);
                uint32_t wa = (t < 4) ? mw0 : mw1;
                uint32_t wb = (t < 4) ? mw2 : mw3;
                int bit = cb & 31;
                float p0 = ((wa >> bit) & 1u)       ? exp2f(s[t][0]) : 0.0f;
                float p1 = ((wa >> (bit + 1)) & 1u) ? exp2f(s[t][1]) : 0.0f;
                float p2 = ((wb >> bit) & 1u)       ? exp2f(s[t][2]) : 0.0f;
                float p3 = ((wb >> (bit + 1)) & 1u) ? exp2f(s[t][3]) : 0.0f;
                lacc0 += p0 + p1;
                lacc1 += p2 + p3;
                int u = t >> 1, k = (t & 1) * 2;
                af[u][k]     = packhf(p0, p1);
                af[u][k + 1] = packhf(p2, p3);
            }
        };

        auto doPV = [&](int half) {
            #pragma unroll
            for (int u = 0; u < 4; u++) {
                #pragma unroll
                for (int pp = 0; pp < 2; pp++) {
                    uint32_t bo0 = (uint32_t)(2 * pp * 16 + (lane & 15)) * (VSTR * 2)
                                 + half * 128 + u * 32 + (lane >> 4) * 16;
                    uint32_t bo1 = bo0 + 16 * (VSTR * 2);
                    uint32_t v0[4], v1[4];
                    ldm4(v0, tV + bo0); ldm4(v1, tV + bo1);
                    mma16816(o[4 * pp + 0], af[u], v0[0], v0[2]);
                    mma16816(o[4 * pp + 1], af[u], v0[1], v0[3]);
                    mma16816(o[4 * pp + 2], af[u], v1[0], v1[2]);
                    mma16816(o[4 * pp + 3], af[u], v1[1], v1[3]);
                }
            }
        };

        // software pipeline: PV(h0) mmas overlap softmax(h1) latency
        computeS(0);
        softmax(0);
        computeS(1);
        doPV(0);
        softmax(1);
        doPV(1);
    }

    lacc0 += __shfl_xor_sync(0xffffffffu, lacc0, 1);
    lacc0 += __shfl_xor_sync(0xffffffffu, lacc0, 2);
    lacc1 += __shfl_xor_sync(0xffffffffu, lacc1, 1);
    lacc1 += __shfl_xor_sync(0xffffffffu, lacc1, 2);
    float inv0 = 1.0f / lacc0, inv1 = 1.0f / lacc1;

    int row = q0 + w * 16 + (lane >> 2);
    #pragma unroll
    for (int t = 0; t < 8; t++) {
        int col = hd * 64 + 8 * t + 2 * (lane & 3);
        size_t o0 = (size_t)(b * Tt + row) * 1024 + col;
        size_t o1 = (size_t)(b * Tt + row + 8) * 1024 + col;
        *(uint32_t*)(g_z + o0) = packhf(o[t][0] * inv0, o[t][1] * inv0);
        *(uint32_t*)(g_z + o1) = packhf(o[t][2] * inv1, o[t][3] * inv1);
    }
}

// ===========================================================================
extern "C" void kernel_launch(void* const* d_in, const int* in_sizes, int n_in,
                              void* d_out, int out_size)
{
    const float* embed = (const float*)d_in[0];
    const int*   mask  = (const int*)d_in[1];
    const float* Wq = (const float*)d_in[2];
    const float* bq = (const float*)d_in[3];
    const float* Wk = (const float*)d_in[4];
    const float* bk = (const float*)d_in[5];
    const float* Wv = (const float*)d_in[6];
    const float* bv = (const float*)d_in[7];
    const float* Wz = (const float*)d_in[8];
    const float* bz = (const float*)d_in[9];
    float* out = (float*)d_out;

    __half *e, *wt, *q, *k, *vt, *z;
    uint32_t* mbits;
    cudaGetSymbolAddress((void**)&e, g_e);
    cudaGetSymbolAddress((void**)&wt, g_w);
    cudaGetSymbolAddress((void**)&q, g_q);
    cudaGetSymbolAddress((void**)&k, g_k);
    cudaGetSymbolAddress((void**)&vt, g_vt);
    cudaGetSymbolAddress((void**)&z, g_z);
    cudaGetSymbolAddress((void**)&mbits, g_mbits);

    cudaFuncSetAttribute(gemm_qkv, cudaFuncAttributeMaxDynamicSharedMemorySize,
                         GEMM_SMEM_BYTES);
    cudaFuncSetAttribute(gemm_out, cudaFuncAttributeMaxDynamicSharedMemorySize,
                         GEMM_SMEM_BYTES);
    cudaFuncSetAttribute(attn_mma, cudaFuncAttributeMaxDynamicSharedMemorySize,
                         ATTN_SMEM_BYTES);

    const size_t WSZ = (size_t)1024 * 1024;

    // Single fused prep launch
    fused_prep<<<40960, 256>>>(embed, Wq, Wk, Wv, Wz, mask, e, wt, mbits);

    // Fused Q/K/V projections (128x128 tiles)
    gemm_qkv<<<dim3(8, 32, 3), 256, GEMM_SMEM_BYTES>>>(
        e, wt, bq, bk, bv, q, k, vt);

    // Attention
    attn_mma<<<dim3(16, 32), 256, ATTN_SMEM_BYTES>>>();

    // Output projection -> d_out (fp32)
    gemm_out<<<dim3(8, 32), 256, GEMM_SMEM_BYTES>>>(
        z, wt + 3 * WSZ, bz, out);
}